// round 5
// baseline (speedup 1.0000x reference)
#include <cuda_runtime.h>
#include <cuda_bf16.h>
#include <math.h>
#include <float.h>
#include <stdint.h>

#define B_   8
#define V_   4
#define N_   16384
#define CP_  256
#define BV_  (B_*V_)            // 32
#define TM_  128                // points per CTA tile
#define NT2_ (N_*BV_/TM_)       // 4096 tiles
#define A_STR 528               // A row stride bytes (256 bf16 + 16B pad)
#define B_STR 144               // B row stride bytes (64 bf16 + 16B pad)
#define D_STR 264               // D row stride floats (256 + 8 pad)
#define OFF_AL 67584            // 128*528
#define OFF_BH 135168           // 2*128*528
#define OFF_BL 172032           // OFF_BH + 256*144
#define DYN_SMEM 208896         // OFF_BL + 256*144

// ---------------- device scratch (static; no allocations) -------------------
__device__ float d_center[BV_*3];
__device__ float d_invdiam[BV_];
__device__ __align__(16) float d_gmax[BV_*CP_];
__device__ __align__(16) float d_gpart[BV_*CP_];
__device__ float d_mw[BV_*N_];
__device__ float d_denom[BV_];
// local_xyz bf16 hi/lo: [tile][plane][m 128][k 256] => words [tile][plane][m][k/2]
__device__ __align__(16) uint32_t d_localw[(size_t)NT2_*2*128*128];   // 512MB
// weights pre-split to bf16 hi/lo, [n][k] row-major (B^T), no padding
__device__ __align__(16) unsigned char d_W2h[CP_*CP_*2];
__device__ __align__(16) unsigned char d_W2l[CP_*CP_*2];
__device__ __align__(16) unsigned char d_W3h[CP_*CP_*2];
__device__ __align__(16) unsigned char d_W3l[CP_*CP_*2];

// ---------------- helpers ---------------------------------------------------
__device__ __forceinline__ uint32_t sm2u(const void* p) {
    uint32_t a;
    asm("{ .reg .u64 t; cvta.to.shared.u64 t, %1; cvt.u32.u64 %0, t; }"
        : "=r"(a) : "l"(p));
    return a;
}
#define LDSM4(r, addr) \
    asm volatile("ldmatrix.sync.aligned.m8n8.x4.shared.b16 {%0,%1,%2,%3}, [%4];" \
        : "=r"((r)[0]), "=r"((r)[1]), "=r"((r)[2]), "=r"((r)[3]) : "r"(addr))
#define MMAOP(d, a, b0, b1) \
    asm volatile("mma.sync.aligned.m16n8k16.row.col.f32.bf16.bf16.f32 " \
        "{%0,%1,%2,%3}, {%4,%5,%6,%7}, {%8,%9}, {%0,%1,%2,%3};" \
        : "+f"((d)[0]), "+f"((d)[1]), "+f"((d)[2]), "+f"((d)[3]) \
        : "r"((a)[0]), "r"((a)[1]), "r"((a)[2]), "r"((a)[3]), "r"(b0), "r"(b1))

static __device__ __forceinline__ uint32_t pack2(float v0, float v1, uint32_t* lo) {
    __nv_bfloat16 h0 = __float2bfloat16_rn(v0);
    __nv_bfloat16 h1 = __float2bfloat16_rn(v1);
    __nv_bfloat16 l0 = __float2bfloat16_rn(v0 - __bfloat162float(h0));
    __nv_bfloat16 l1 = __float2bfloat16_rn(v1 - __bfloat162float(h1));
    *lo = (uint32_t)__bfloat16_as_ushort(l0) | ((uint32_t)__bfloat16_as_ushort(l1) << 16);
    return (uint32_t)__bfloat16_as_ushort(h0) | ((uint32_t)__bfloat16_as_ushort(h1) << 16);
}
__device__ __forceinline__ void atomicMaxFloat(float* addr, float val) {
    if (__float_as_int(val) >= 0) atomicMax((int*)addr, __float_as_int(val));
    else atomicMin((unsigned int*)addr, __float_as_uint(val));
}

// ---------------- kP: split weights to bf16 hi/lo [n][k] --------------------
__global__ void __launch_bounds__(256) kP(const float* __restrict__ W2,
                                          const float* __restrict__ W3) {
    int k = blockIdx.x;   // W row (GEMM K)
    int n = threadIdx.x;  // W col (GEMM N)
    size_t pos = ((size_t)n*CP_ + k)*2;

    float v = W2[k*CP_ + n];
    __nv_bfloat16 h = __float2bfloat16_rn(v);
    __nv_bfloat16 l = __float2bfloat16_rn(v - __bfloat162float(h));
    *(unsigned short*)(d_W2h + pos) = __bfloat16_as_ushort(h);
    *(unsigned short*)(d_W2l + pos) = __bfloat16_as_ushort(l);

    v = W3[k*CP_ + n];    // top 256 rows of W3
    h = __float2bfloat16_rn(v);
    l = __float2bfloat16_rn(v - __bfloat162float(h));
    *(unsigned short*)(d_W3h + pos) = __bfloat16_as_ushort(h);
    *(unsigned short*)(d_W3l + pos) = __bfloat16_as_ushort(l);
}

// ---------------- kA: per-(b,v) stats + init --------------------------------
__global__ void __launch_bounds__(256) kA(const float* __restrict__ xyz,
                                          const float* __restrict__ masks) {
    int bv = blockIdx.x;
    int b  = bv >> 2;
    int tid = threadIdx.x;

    float s0=0.f, s1=0.f, s2=0.f, cnt=0.f;
    float mx0=-FLT_MAX, mx1=-FLT_MAX, mx2=-FLT_MAX;
    float mn0= FLT_MAX, mn1= FLT_MAX, mn2= FLT_MAX;

    const float* mrow = masks + (size_t)bv*N_;
    const float* x0r  = xyz + (size_t)(b*3+0)*N_;
    const float* x1r  = xyz + (size_t)(b*3+1)*N_;
    const float* x2r  = xyz + (size_t)(b*3+2)*N_;

    for (int n = tid; n < N_; n += 256) {
        float m = mrow[n];
        float a = x0r[n]*m, c = x1r[n]*m, e = x2r[n]*m;
        s0 += a; s1 += c; s2 += e; cnt += m;
        mx0 = fmaxf(mx0,a); mx1 = fmaxf(mx1,c); mx2 = fmaxf(mx2,e);
        mn0 = fminf(mn0,a); mn1 = fminf(mn1,c); mn2 = fminf(mn2,e);
    }
    __shared__ float rs[4][256];
    __shared__ float rx[3][256];
    __shared__ float rn[3][256];
    rs[0][tid]=s0; rs[1][tid]=s1; rs[2][tid]=s2; rs[3][tid]=cnt;
    rx[0][tid]=mx0; rx[1][tid]=mx1; rx[2][tid]=mx2;
    rn[0][tid]=mn0; rn[1][tid]=mn1; rn[2][tid]=mn2;
    __syncthreads();
    for (int s = 128; s > 0; s >>= 1) {
        if (tid < s) {
            #pragma unroll
            for (int q = 0; q < 4; q++) rs[q][tid] += rs[q][tid+s];
            #pragma unroll
            for (int q = 0; q < 3; q++) {
                rx[q][tid] = fmaxf(rx[q][tid], rx[q][tid+s]);
                rn[q][tid] = fminf(rn[q][tid], rn[q][tid+s]);
            }
        }
        __syncthreads();
    }
    if (tid == 0) {
        float valid = fmaxf(rs[3][0], 1.f);
        d_center[bv*3+0] = rs[0][0]/valid;
        d_center[bv*3+1] = rs[1][0]/valid;
        d_center[bv*3+2] = rs[2][0]/valid;
        float diam = fmaxf(fmaxf(rx[0][0]-rn[0][0], rx[1][0]-rn[1][0]),
                           rx[2][0]-rn[2][0]);
        if (diam == 0.f) diam = 1.f;
        d_invdiam[bv] = 1.f/diam;
        d_denom[bv]   = 0.f;
    }
    d_gmax[bv*CP_ + tid] = -FLT_MAX;
}

// ---------------- MMA core (shared by kB/kD): dA/dB accumulate --------------
// Warp wid: m-strips mt0=(wid>>2)*16 and mt0+64; n-strip nb=(wid&3)*64.
// A in smem at [0](hi) / [OFF_AL](lo); B chunk at [OFF_BH]/[OFF_BL].

// ---------------- kB: stage1+LN1+ReLU -> HMMA(W2) -> LN2 -> local + gmax ----
__global__ void __launch_bounds__(512) kB(const float* __restrict__ xyz,
    const float* __restrict__ W1, const float* __restrict__ b1,
    const float* __restrict__ g1, const float* __restrict__ be1,
    const float* __restrict__ b2, const float* __restrict__ g2,
    const float* __restrict__ be2)
{
    extern __shared__ unsigned char ds[];
    __shared__ float w1s[3*CP_];
    __shared__ float b1s[CP_], g1s[CP_], e1s[CP_], b2s[CP_], g2s[CP_], e2s[CP_];
    __shared__ float srS[TM_][4], srQ[TM_][4];
    __shared__ float cmax[CP_];

    int tile = blockIdx.x;
    int bv = tile >> 7;
    int b  = bv >> 2;
    int n0g = (tile & 127) * TM_;
    int tid = threadIdx.x, lane = tid & 31, wid = tid >> 5;
    uint32_t su = sm2u(ds);

    for (int i = tid; i < 3*CP_; i += 512) w1s[i] = W1[i];
    if (tid < 256) {
        b1s[tid]=b1[tid]; g1s[tid]=g1[tid]; e1s[tid]=be1[tid];
        b2s[tid]=b2[tid]; g2s[tid]=g2[tid]; e2s[tid]=be2[tid];
        cmax[tid] = -FLT_MAX;
    }

    int p = tid >> 2, sub = tid & 3, c0 = sub*64;
    int n = n0g + p;
    float idm = d_invdiam[bv];
    float x0 = (xyz[(size_t)(b*3+0)*N_ + n] - d_center[bv*3+0]) * idm;
    float x1 = (xyz[(size_t)(b*3+1)*N_ + n] - d_center[bv*3+1]) * idm;
    float x2 = (xyz[(size_t)(b*3+2)*N_ + n] - d_center[bv*3+2]) * idm;
    __syncthreads();

    // LN1 stats over this thread's 64 channels
    float sum = 0.f, sq = 0.f;
    #pragma unroll 4
    for (int c = c0; c < c0+64; c++) {
        float y = b1s[c] + x0*w1s[c] + x1*w1s[CP_+c] + x2*w1s[2*CP_+c];
        sum += y; sq += y*y;
    }
    srS[p][sub] = sum; srQ[p][sub] = sq;
    __syncthreads();
    float mean = (srS[p][0]+srS[p][1]+srS[p][2]+srS[p][3]) * (1.f/CP_);
    float var  = (srQ[p][0]+srQ[p][1]+srQ[p][2]+srQ[p][3]) * (1.f/CP_) - mean*mean;
    float rstd = rsqrtf(var + 1e-5f);

    // recompute, LN+ReLU, split hi/lo, write A rows to smem
    #pragma unroll 8
    for (int i = 0; i < 32; i++) {
        int c = c0 + 2*i;
        float y0 = b1s[c]   + x0*w1s[c]   + x1*w1s[CP_+c]   + x2*w1s[2*CP_+c];
        float y1 = b1s[c+1] + x0*w1s[c+1] + x1*w1s[CP_+c+1] + x2*w1s[2*CP_+c+1];
        y0 = fmaxf((y0-mean)*rstd*g1s[c]   + e1s[c],   0.f);
        y1 = fmaxf((y1-mean)*rstd*g1s[c+1] + e1s[c+1], 0.f);
        uint32_t wl, wh = pack2(y0, y1, &wl);
        *(uint32_t*)(ds + (size_t)p*A_STR + c*2) = wh;
        *(uint32_t*)(ds + OFF_AL + (size_t)p*A_STR + c*2) = wl;
    }

    // ---- HMMA mainloop ----
    int mt0 = (wid >> 2) * 16;
    int nb  = (wid & 3) * 64;
    uint32_t aoff0 = (uint32_t)(mt0 + (lane&7) + ((lane>>3)&1)*8)*A_STR + (lane>>4)*16;
    uint32_t aoff1 = aoff0 + 64u*A_STR;
    uint32_t boff  = (uint32_t)(nb + (lane&7) + (lane>>4)*8)*B_STR + ((lane>>3)&1)*16;

    float dA[8][4] = {}, dB[8][4] = {};
    for (int ch = 0; ch < 4; ch++) {
        __syncthreads();
        for (int i = tid; i < 2048; i += 512) {
            int r = i >> 3, q = i & 7;
            uint4 vh = *(const uint4*)(d_W2h + (size_t)r*512 + ch*128 + q*16);
            uint4 vl = *(const uint4*)(d_W2l + (size_t)r*512 + ch*128 + q*16);
            *(uint4*)(ds + OFF_BH + (size_t)r*B_STR + q*16) = vh;
            *(uint4*)(ds + OFF_BL + (size_t)r*B_STR + q*16) = vl;
        }
        __syncthreads();
        #pragma unroll
        for (int kb = 0; kb < 4; kb++) {
            uint32_t kA = (uint32_t)(ch*128 + kb*32);
            uint32_t ah[4], al[4], ah2[4], al2[4];
            LDSM4(ah,  su + aoff0 + kA);
            LDSM4(al,  su + OFF_AL + aoff0 + kA);
            LDSM4(ah2, su + aoff1 + kA);
            LDSM4(al2, su + OFF_AL + aoff1 + kA);
            #pragma unroll
            for (int nt = 0; nt < 4; nt++) {
                uint32_t bh[4], bl[4];
                uint32_t ba = su + OFF_BH + boff + (uint32_t)(nt*16*B_STR + kb*32);
                LDSM4(bh, ba);
                LDSM4(bl, ba + (OFF_BL - OFF_BH));
                MMAOP(dA[2*nt],   ah,  bh[0], bh[1]);
                MMAOP(dA[2*nt+1], ah,  bh[2], bh[3]);
                MMAOP(dA[2*nt],   al,  bh[0], bh[1]);
                MMAOP(dA[2*nt+1], al,  bh[2], bh[3]);
                MMAOP(dA[2*nt],   ah,  bl[0], bl[1]);
                MMAOP(dA[2*nt+1], ah,  bl[2], bl[3]);
                MMAOP(dB[2*nt],   ah2, bh[0], bh[1]);
                MMAOP(dB[2*nt+1], ah2, bh[2], bh[3]);
                MMAOP(dB[2*nt],   al2, bh[0], bh[1]);
                MMAOP(dB[2*nt+1], al2, bh[2], bh[3]);
                MMAOP(dB[2*nt],   ah2, bl[0], bl[1]);
                MMAOP(dB[2*nt+1], ah2, bl[2], bl[3]);
            }
        }
    }
    __syncthreads();

    // store D frags to smem (reuse A area), fp32 [128][264]
    {
        float* Db = (float*)ds;
        int r = lane >> 2, q = (lane & 3)*2;
        #pragma unroll
        for (int nt = 0; nt < 8; nt++) {
            int col = nb + nt*8 + q;
            Db[(mt0+r)*D_STR + col]      = dA[nt][0];
            Db[(mt0+r)*D_STR + col + 1]  = dA[nt][1];
            Db[(mt0+r+8)*D_STR + col]    = dA[nt][2];
            Db[(mt0+r+8)*D_STR + col +1] = dA[nt][3];
            Db[(mt0+64+r)*D_STR + col]      = dB[nt][0];
            Db[(mt0+64+r)*D_STR + col + 1]  = dB[nt][1];
            Db[(mt0+64+r+8)*D_STR + col]    = dB[nt][2];
            Db[(mt0+64+r+8)*D_STR + col +1] = dB[nt][3];
        }
    }
    __syncthreads();

    // LN2 over D
    const float* Db = (const float*)ds;
    sum = 0.f; sq = 0.f;
    #pragma unroll 4
    for (int c = c0; c < c0+64; c++) {
        float v = Db[p*D_STR + c] + b2s[c];
        sum += v; sq += v*v;
    }
    srS[p][sub] = sum; srQ[p][sub] = sq;
    __syncthreads();
    mean = (srS[p][0]+srS[p][1]+srS[p][2]+srS[p][3]) * (1.f/CP_);
    var  = (srQ[p][0]+srQ[p][1]+srQ[p][2]+srQ[p][3]) * (1.f/CP_) - mean*mean;
    rstd = rsqrtf(var + 1e-5f);

    size_t lw = (size_t)tile * 2 * 16384;
    #pragma unroll 8
    for (int i = 0; i < 32; i++) {
        int c = c0 + 2*i;
        float v0 = Db[p*D_STR + c]   + b2s[c];
        float v1 = Db[p*D_STR + c+1] + b2s[c+1];
        float lv0 = (v0-mean)*rstd*g2s[c]   + e2s[c];
        float lv1 = (v1-mean)*rstd*g2s[c+1] + e2s[c+1];
        atomicMaxFloat(&cmax[c],   lv0);
        atomicMaxFloat(&cmax[c+1], lv1);
        uint32_t wl, wh = pack2(lv0, lv1, &wl);
        d_localw[lw + (size_t)p*128 + (c>>1)]         = wh;
        d_localw[lw + 16384 + (size_t)p*128 + (c>>1)] = wl;
    }
    __syncthreads();
    if (tid < 256) atomicMaxFloat(&d_gmax[bv*CP_ + tid], cmax[tid]);
}

// ---------------- kC: gpart = global_xyz @ W3[256:512] + b3 -----------------
__global__ void __launch_bounds__(256) kC(const float* __restrict__ W3,
                                          const float* __restrict__ b3) {
    int bv = blockIdx.x;
    int c  = threadIdx.x;
    __shared__ float sg[CP_];
    sg[c] = d_gmax[bv*CP_ + c];
    __syncthreads();
    float acc = b3[c];
    const float* w = W3 + (size_t)256*CP_ + c;
    #pragma unroll 8
    for (int k = 0; k < CP_; k++) acc += sg[k] * w[(size_t)k*CP_];
    d_gpart[bv*CP_ + c] = acc;
}

// ---------------- kD: HMMA(W3-top) + LN3 + ReLU + W4 -> weights -------------
__global__ void __launch_bounds__(512) kD(const float* __restrict__ masks,
    const float* __restrict__ g3, const float* __restrict__ be3,
    const float* __restrict__ W4)
{
    extern __shared__ unsigned char ds[];
    __shared__ float sG3[CP_], sE3[CP_], sW4[CP_], sGp[CP_];
    __shared__ float srS[TM_][4], srQ[TM_][4];
    __shared__ float sw[TM_];

    int tile = blockIdx.x;
    int bv = tile >> 7;
    int n0g = (tile & 127) * TM_;
    int tid = threadIdx.x, lane = tid & 31, wid = tid >> 5;
    uint32_t su = sm2u(ds);

    if (tid < 256) {
        sG3[tid] = g3[tid]; sE3[tid] = be3[tid]; sW4[tid] = W4[tid];
        sGp[tid] = d_gpart[bv*CP_ + tid];
    }

    // load A (local hi/lo) into padded smem rows
    {
        const uint4* src = (const uint4*)d_localw + (size_t)tile*8192;
        for (int i = tid; i < 8192; i += 512) {
            int plane = i >> 12, idx = i & 4095;
            int row = idx >> 5, q = idx & 31;
            uint4 v = src[(size_t)plane*4096 + row*32 + q];
            *(uint4*)(ds + (size_t)plane*OFF_AL + (size_t)row*A_STR + q*16) = v;
        }
    }
    __syncthreads();

    int mt0 = (wid >> 2) * 16;
    int nb  = (wid & 3) * 64;
    uint32_t aoff0 = (uint32_t)(mt0 + (lane&7) + ((lane>>3)&1)*8)*A_STR + (lane>>4)*16;
    uint32_t aoff1 = aoff0 + 64u*A_STR;
    uint32_t boff  = (uint32_t)(nb + (lane&7) + (lane>>4)*8)*B_STR + ((lane>>3)&1)*16;

    float dA[8][4] = {}, dB[8][4] = {};
    for (int ch = 0; ch < 4; ch++) {
        __syncthreads();
        for (int i = tid; i < 2048; i += 512) {
            int r = i >> 3, q = i & 7;
            uint4 vh = *(const uint4*)(d_W3h + (size_t)r*512 + ch*128 + q*16);
            uint4 vl = *(const uint4*)(d_W3l + (size_t)r*512 + ch*128 + q*16);
            *(uint4*)(ds + OFF_BH + (size_t)r*B_STR + q*16) = vh;
            *(uint4*)(ds + OFF_BL + (size_t)r*B_STR + q*16) = vl;
        }
        __syncthreads();
        #pragma unroll
        for (int kb = 0; kb < 4; kb++) {
            uint32_t kA = (uint32_t)(ch*128 + kb*32);
            uint32_t ah[4], al[4], ah2[4], al2[4];
            LDSM4(ah,  su + aoff0 + kA);
            LDSM4(al,  su + OFF_AL + aoff0 + kA);
            LDSM4(ah2, su + aoff1 + kA);
            LDSM4(al2, su + OFF_AL + aoff1 + kA);
            #pragma unroll
            for (int nt = 0; nt < 4; nt++) {
                uint32_t bh[4], bl[4];
                uint32_t ba = su + OFF_BH + boff + (uint32_t)(nt*16*B_STR + kb*32);
                LDSM4(bh, ba);
                LDSM4(bl, ba + (OFF_BL - OFF_BH));
                MMAOP(dA[2*nt],   ah,  bh[0], bh[1]);
                MMAOP(dA[2*nt+1], ah,  bh[2], bh[3]);
                MMAOP(dA[2*nt],   al,  bh[0], bh[1]);
                MMAOP(dA[2*nt+1], al,  bh[2], bh[3]);
                MMAOP(dA[2*nt],   ah,  bl[0], bl[1]);
                MMAOP(dA[2*nt+1], ah,  bl[2], bl[3]);
                MMAOP(dB[2*nt],   ah2, bh[0], bh[1]);
                MMAOP(dB[2*nt+1], ah2, bh[2], bh[3]);
                MMAOP(dB[2*nt],   al2, bh[0], bh[1]);
                MMAOP(dB[2*nt+1], al2, bh[2], bh[3]);
                MMAOP(dB[2*nt],   ah2, bl[0], bl[1]);
                MMAOP(dB[2*nt+1], ah2, bl[2], bl[3]);
            }
        }
    }
    __syncthreads();

    {
        float* Dbw = (float*)ds;
        int r = lane >> 2, q = (lane & 3)*2;
        #pragma unroll
        for (int nt = 0; nt < 8; nt++) {
            int col = nb + nt*8 + q;
            Dbw[(mt0+r)*D_STR + col]      = dA[nt][0];
            Dbw[(mt0+r)*D_STR + col + 1]  = dA[nt][1];
            Dbw[(mt0+r+8)*D_STR + col]    = dA[nt][2];
            Dbw[(mt0+r+8)*D_STR + col +1] = dA[nt][3];
            Dbw[(mt0+64+r)*D_STR + col]      = dB[nt][0];
            Dbw[(mt0+64+r)*D_STR + col + 1]  = dB[nt][1];
            Dbw[(mt0+64+r+8)*D_STR + col]    = dB[nt][2];
            Dbw[(mt0+64+r+8)*D_STR + col +1] = dB[nt][3];
        }
    }
    __syncthreads();

    const float* Db = (const float*)ds;
    int p = tid >> 2, sub = tid & 3, c0 = sub*64;
    float sum = 0.f, sq = 0.f;
    #pragma unroll 4
    for (int c = c0; c < c0+64; c++) {
        float v = Db[p*D_STR + c] + sGp[c];
        sum += v; sq += v*v;
    }
    srS[p][sub] = sum; srQ[p][sub] = sq;
    __syncthreads();
    float mean = (srS[p][0]+srS[p][1]+srS[p][2]+srS[p][3]) * (1.f/CP_);
    float var  = (srQ[p][0]+srQ[p][1]+srQ[p][2]+srQ[p][3]) * (1.f/CP_) - mean*mean;
    float rstd = rsqrtf(var + 1e-5f);

    float dot = 0.f;
    #pragma unroll 4
    for (int c = c0; c < c0+64; c++) {
        float v = Db[p*D_STR + c] + sGp[c];
        float hv = fmaxf((v-mean)*rstd*sG3[c] + sE3[c], 0.f);
        dot += hv * sW4[c];
    }
    __syncthreads();      // srS reuse
    srS[p][sub] = dot;
    __syncthreads();
    if (sub == 0) {
        float dt = srS[p][0]+srS[p][1]+srS[p][2]+srS[p][3];
        int n = n0g + p;
        float m = masks[(size_t)bv*N_ + n];
        float w = 2.f * m / (1.f + expf(-dt));
        d_mw[(size_t)bv*N_ + n] = w;
        sw[p] = w;
    }
    __syncthreads();
    if (tid == 0) {
        float s = 0.f;
        #pragma unroll 8
        for (int i = 0; i < TM_; i++) s += sw[i];
        atomicAdd(&d_denom[bv], s);
    }
}

// ---------------- kE: weighted pooling + epilogue ---------------------------
__global__ void __launch_bounds__(256) kE(const float* __restrict__ feats,
                                          float* __restrict__ out) {
    int blk = blockIdx.x;        // b*CP_ + c
    int b = blk >> 8;
    int c = blk & 255;
    int tid = threadIdx.x;

    const float* f   = feats + (size_t)(b*CP_ + c)*N_;
    const float* mw0 = d_mw + (size_t)(b*4+0)*N_;
    const float* mw1 = d_mw + (size_t)(b*4+1)*N_;
    const float* mw2 = d_mw + (size_t)(b*4+2)*N_;
    const float* mw3 = d_mw + (size_t)(b*4+3)*N_;

    float a0=0.f, a1=0.f, a2=0.f, a3=0.f;
    for (int n = tid; n < N_; n += 256) {
        float fv = f[n];
        a0 += fv*mw0[n]; a1 += fv*mw1[n]; a2 += fv*mw2[n]; a3 += fv*mw3[n];
    }
    #pragma unroll
    for (int o = 16; o > 0; o >>= 1) {
        a0 += __shfl_xor_sync(0xffffffffu, a0, o);
        a1 += __shfl_xor_sync(0xffffffffu, a1, o);
        a2 += __shfl_xor_sync(0xffffffffu, a2, o);
        a3 += __shfl_xor_sync(0xffffffffu, a3, o);
    }
    __shared__ float sr[4][8];
    int lane = tid & 31, warp = tid >> 5;
    if (lane == 0) { sr[0][warp]=a0; sr[1][warp]=a1; sr[2][warp]=a2; sr[3][warp]=a3; }
    __syncthreads();
    if (tid < 4) {
        float ps = 0.f;
        #pragma unroll
        for (int w = 0; w < 8; w++) ps += sr[tid][w];
        int bvv = b*4 + tid;
        float den = fmaxf(d_denom[bvv], 1e-8f);
        out[(size_t)bvv*CP_ + c] = ps/den + d_gmax[bvv*CP_ + c];
    }
}

// ---------------- launch ----------------------------------------------------
extern "C" void kernel_launch(void* const* d_in, const int* in_sizes, int n_in,
                              void* d_out, int out_size) {
    const float* xyz = (const float*)d_in[0];
    const float* pf  = (const float*)d_in[1];
    const float* pm  = (const float*)d_in[2];
    const float* W1  = (const float*)d_in[3];
    const float* b1  = (const float*)d_in[4];
    const float* g1  = (const float*)d_in[5];
    const float* be1 = (const float*)d_in[6];
    const float* W2  = (const float*)d_in[7];
    const float* b2  = (const float*)d_in[8];
    const float* g2  = (const float*)d_in[9];
    const float* be2 = (const float*)d_in[10];
    const float* W3  = (const float*)d_in[11];
    const float* b3  = (const float*)d_in[12];
    const float* g3  = (const float*)d_in[13];
    const float* be3 = (const float*)d_in[14];
    const float* W4  = (const float*)d_in[15];
    float* out = (float*)d_out;

    static int configured = 0;
    if (!configured) {
        cudaFuncSetAttribute(kB, cudaFuncAttributeMaxDynamicSharedMemorySize, DYN_SMEM);
        cudaFuncSetAttribute(kD, cudaFuncAttributeMaxDynamicSharedMemorySize, DYN_SMEM);
        configured = 1;
    }

    kP<<<CP_, 256>>>(W2, W3);
    kA<<<BV_, 256>>>(xyz, pm);
    kB<<<NT2_, 512, DYN_SMEM>>>(xyz, W1, b1, g1, be1, b2, g2, be2);
    kC<<<BV_, 256>>>(W3, b3);
    kD<<<NT2_, 512, DYN_SMEM>>>(pm, g3, be3, W4);
    kE<<<B_*CP_, 256>>>(pf, out);
}

// round 6
// speedup vs baseline: 1.1239x; 1.1239x over previous
#include <cuda_runtime.h>
#include <cuda_bf16.h>
#include <math.h>
#include <float.h>
#include <stdint.h>

#define B_   8
#define V_   4
#define N_   16384
#define CP_  256
#define BV_  (B_*V_)            // 32
#define TM_  128                // points per CTA tile
#define NT2_ (N_*BV_/TM_)       // 4096 tiles
#define A_STR 528               // A row stride bytes (256 bf16 + 16B pad) -> conflict-free ldmatrix
#define B_STR 80                // B row stride bytes (32 bf16 + 16B pad)  -> 5r+c, conflict-free
#define D_STR 264               // D row stride floats
#define OFF_AL   67584          // 128*528
#define OFF_B    135168         // B buffers start (2*128*528)
#define B_PLANE  20480          // 256*80 per plane
#define B_BUF    40960          // hi+lo per buffer
#define B_GCH    16384          // packed gmem chunk bytes per plane (256*64)
#define A_IMG    135168         // full A image bytes (2 planes)
#define DYN_SMEM (OFF_B + 2*B_BUF)   // 217088

// ---------------- device scratch (static; no allocations) -------------------
__device__ float d_center[BV_*3];
__device__ float d_invdiam[BV_];
__device__ __align__(16) float d_gmax[BV_*CP_];
__device__ __align__(16) float d_gpart[BV_*CP_];
__device__ float d_mw[BV_*N_];
__device__ float d_denom[BV_];
// local_xyz stored as the exact padded A-smem byte image per tile (hi|lo planes)
__device__ __align__(16) unsigned char d_localA[(size_t)NT2_*A_IMG];  // 553MB
// weights bf16 hi/lo, packed K32-chunk layout: [chunk 8][n 256][32 bf16]
__device__ __align__(16) unsigned char d_W2h[CP_*CP_*2];
__device__ __align__(16) unsigned char d_W2l[CP_*CP_*2];
__device__ __align__(16) unsigned char d_W3h[CP_*CP_*2];
__device__ __align__(16) unsigned char d_W3l[CP_*CP_*2];

// ---------------- helpers ---------------------------------------------------
__device__ __forceinline__ uint32_t sm2u(const void* p) {
    uint32_t a;
    asm("{ .reg .u64 t; cvta.to.shared.u64 t, %1; cvt.u32.u64 %0, t; }"
        : "=r"(a) : "l"(p));
    return a;
}
#define LDSM4(r, addr) \
    asm volatile("ldmatrix.sync.aligned.m8n8.x4.shared.b16 {%0,%1,%2,%3}, [%4];" \
        : "=r"((r)[0]), "=r"((r)[1]), "=r"((r)[2]), "=r"((r)[3]) : "r"(addr))
#define MMAOP(d, a, b0, b1) \
    asm volatile("mma.sync.aligned.m16n8k16.row.col.f32.bf16.bf16.f32 " \
        "{%0,%1,%2,%3}, {%4,%5,%6,%7}, {%8,%9}, {%0,%1,%2,%3};" \
        : "+f"((d)[0]), "+f"((d)[1]), "+f"((d)[2]), "+f"((d)[3]) \
        : "r"((a)[0]), "r"((a)[1]), "r"((a)[2]), "r"((a)[3]), "r"(b0), "r"(b1))
#define CPA16(dst, src) \
    asm volatile("cp.async.cg.shared.global [%0], [%1], 16;" :: "r"(dst), "l"(src))
#define CPCOMMIT() asm volatile("cp.async.commit_group;" ::: "memory")
#define CPWAIT1()  asm volatile("cp.async.wait_group 1;" ::: "memory")

static __device__ __forceinline__ uint32_t pack2(float v0, float v1, uint32_t* lo) {
    __nv_bfloat16 h0 = __float2bfloat16_rn(v0);
    __nv_bfloat16 h1 = __float2bfloat16_rn(v1);
    __nv_bfloat16 l0 = __float2bfloat16_rn(v0 - __bfloat162float(h0));
    __nv_bfloat16 l1 = __float2bfloat16_rn(v1 - __bfloat162float(h1));
    *lo = (uint32_t)__bfloat16_as_ushort(l0) | ((uint32_t)__bfloat16_as_ushort(l1) << 16);
    return (uint32_t)__bfloat16_as_ushort(h0) | ((uint32_t)__bfloat16_as_ushort(h1) << 16);
}
__device__ __forceinline__ void atomicMaxFloat(float* addr, float val) {
    if (__float_as_int(val) >= 0) atomicMax((int*)addr, __float_as_int(val));
    else atomicMin((unsigned int*)addr, __float_as_uint(val));
}

// issue cp.async for B chunk ch into buffer buf (0/1); 4 ops/thread
__device__ __forceinline__ void prefetchB(uint32_t su, int buf, int ch,
                                          const unsigned char* gh,
                                          const unsigned char* gl, int tid) {
    uint32_t base = su + OFF_B + (uint32_t)buf*B_BUF;
    #pragma unroll
    for (int i = 0; i < 4; i++) {
        int idx = tid + i*512;           // 0..2047
        int plane = idx >> 10, w = idx & 1023;
        int n = w >> 2, c16 = w & 3;
        uint32_t dst = base + (uint32_t)plane*B_PLANE + (uint32_t)n*B_STR + c16*16;
        const unsigned char* src = (plane ? gl : gh) + (size_t)ch*B_GCH + (size_t)w*16;
        CPA16(dst, src);
    }
}

// ---------------- kP: split weights to bf16 hi/lo packed chunk layout -------
__global__ void __launch_bounds__(256) kP(const float* __restrict__ W2,
                                          const float* __restrict__ W3) {
    int k = blockIdx.x;   // GEMM K
    int n = threadIdx.x;  // GEMM N
    int ch = k >> 5, kk = k & 31;
    size_t pos = (size_t)ch*B_GCH + (size_t)n*64 + (size_t)kk*2;

    float v = W2[k*CP_ + n];
    __nv_bfloat16 h = __float2bfloat16_rn(v);
    __nv_bfloat16 l = __float2bfloat16_rn(v - __bfloat162float(h));
    *(unsigned short*)(d_W2h + pos) = __bfloat16_as_ushort(h);
    *(unsigned short*)(d_W2l + pos) = __bfloat16_as_ushort(l);

    v = W3[k*CP_ + n];    // top 256 rows of W3
    h = __float2bfloat16_rn(v);
    l = __float2bfloat16_rn(v - __bfloat162float(h));
    *(unsigned short*)(d_W3h + pos) = __bfloat16_as_ushort(h);
    *(unsigned short*)(d_W3l + pos) = __bfloat16_as_ushort(l);
}

// ---------------- kA: per-(b,v) stats + init --------------------------------
__global__ void __launch_bounds__(256) kA(const float* __restrict__ xyz,
                                          const float* __restrict__ masks) {
    int bv = blockIdx.x;
    int b  = bv >> 2;
    int tid = threadIdx.x;

    float s0=0.f, s1=0.f, s2=0.f, cnt=0.f;
    float mx0=-FLT_MAX, mx1=-FLT_MAX, mx2=-FLT_MAX;
    float mn0= FLT_MAX, mn1= FLT_MAX, mn2= FLT_MAX;

    const float* mrow = masks + (size_t)bv*N_;
    const float* x0r  = xyz + (size_t)(b*3+0)*N_;
    const float* x1r  = xyz + (size_t)(b*3+1)*N_;
    const float* x2r  = xyz + (size_t)(b*3+2)*N_;

    for (int n = tid; n < N_; n += 256) {
        float m = mrow[n];
        float a = x0r[n]*m, c = x1r[n]*m, e = x2r[n]*m;
        s0 += a; s1 += c; s2 += e; cnt += m;
        mx0 = fmaxf(mx0,a); mx1 = fmaxf(mx1,c); mx2 = fmaxf(mx2,e);
        mn0 = fminf(mn0,a); mn1 = fminf(mn1,c); mn2 = fminf(mn2,e);
    }
    __shared__ float rs[4][256];
    __shared__ float rx[3][256];
    __shared__ float rn[3][256];
    rs[0][tid]=s0; rs[1][tid]=s1; rs[2][tid]=s2; rs[3][tid]=cnt;
    rx[0][tid]=mx0; rx[1][tid]=mx1; rx[2][tid]=mx2;
    rn[0][tid]=mn0; rn[1][tid]=mn1; rn[2][tid]=mn2;
    __syncthreads();
    for (int s = 128; s > 0; s >>= 1) {
        if (tid < s) {
            #pragma unroll
            for (int q = 0; q < 4; q++) rs[q][tid] += rs[q][tid+s];
            #pragma unroll
            for (int q = 0; q < 3; q++) {
                rx[q][tid] = fmaxf(rx[q][tid], rx[q][tid+s]);
                rn[q][tid] = fminf(rn[q][tid], rn[q][tid+s]);
            }
        }
        __syncthreads();
    }
    if (tid == 0) {
        float valid = fmaxf(rs[3][0], 1.f);
        d_center[bv*3+0] = rs[0][0]/valid;
        d_center[bv*3+1] = rs[1][0]/valid;
        d_center[bv*3+2] = rs[2][0]/valid;
        float diam = fmaxf(fmaxf(rx[0][0]-rn[0][0], rx[1][0]-rn[1][0]),
                           rx[2][0]-rn[2][0]);
        if (diam == 0.f) diam = 1.f;
        d_invdiam[bv] = 1.f/diam;
        d_denom[bv]   = 0.f;
    }
    d_gmax[bv*CP_ + tid] = -FLT_MAX;
}

// 12 MMAs for one (kb, nt) group, accumulator-reuse distance 4
#define MMA_GROUP(dlo, dhi, DLO2, DHI2) \
    MMAOP(dlo,  ah,  bh[0], bh[1]);  MMAOP(dhi,  ah,  bh[2], bh[3]); \
    MMAOP(DLO2, ah2, bh[0], bh[1]);  MMAOP(DHI2, ah2, bh[2], bh[3]); \
    MMAOP(dlo,  al,  bh[0], bh[1]);  MMAOP(dhi,  al,  bh[2], bh[3]); \
    MMAOP(DLO2, al2, bh[0], bh[1]);  MMAOP(DHI2, al2, bh[2], bh[3]); \
    MMAOP(dlo,  ah,  bl[0], bl[1]);  MMAOP(dhi,  ah,  bl[2], bl[3]); \
    MMAOP(DLO2, ah2, bl[0], bl[1]);  MMAOP(DHI2, ah2, bl[2], bl[3])

// ---------------- kB: stage1+LN1+ReLU -> HMMA(W2) -> LN2 -> local + gmax ----
__global__ void __launch_bounds__(512) kB(const float* __restrict__ xyz,
    const float* __restrict__ W1, const float* __restrict__ b1,
    const float* __restrict__ g1, const float* __restrict__ be1,
    const float* __restrict__ b2, const float* __restrict__ g2,
    const float* __restrict__ be2)
{
    extern __shared__ unsigned char ds[];
    __shared__ float w1s[3*CP_];
    __shared__ float b1s[CP_], g1s[CP_], e1s[CP_], b2s[CP_], g2s[CP_], e2s[CP_];
    __shared__ float srS[TM_][4], srQ[TM_][4];
    __shared__ float cmax[CP_];

    int tile = blockIdx.x;
    int bv = tile >> 7;
    int b  = bv >> 2;
    int tid = threadIdx.x, lane = tid & 31, wid = tid >> 5;
    uint32_t su = sm2u(ds);

    // B chunk 0/1 prefetch FIRST (overlaps all of stage-1)
    prefetchB(su, 0, 0, d_W2h, d_W2l, tid); CPCOMMIT();
    prefetchB(su, 1, 1, d_W2h, d_W2l, tid); CPCOMMIT();

    for (int i = tid; i < 3*CP_; i += 512) w1s[i] = W1[i];
    if (tid < 256) {
        b1s[tid]=b1[tid]; g1s[tid]=g1[tid]; e1s[tid]=be1[tid];
        b2s[tid]=b2[tid]; g2s[tid]=g2[tid]; e2s[tid]=be2[tid];
        cmax[tid] = -FLT_MAX;
    }

    int p = tid >> 2, sub = tid & 3, c0 = sub*64;
    float idm = d_invdiam[bv];
    int n = (tile & 127) * TM_ + p;
    float x0 = (xyz[(size_t)(b*3+0)*N_ + n] - d_center[bv*3+0]) * idm;
    float x1 = (xyz[(size_t)(b*3+1)*N_ + n] - d_center[bv*3+1]) * idm;
    float x2 = (xyz[(size_t)(b*3+2)*N_ + n] - d_center[bv*3+2]) * idm;
    __syncthreads();

    // LN1 stats over this thread's 64 channels
    float sum = 0.f, sq = 0.f;
    #pragma unroll 4
    for (int c = c0; c < c0+64; c++) {
        float y = b1s[c] + x0*w1s[c] + x1*w1s[CP_+c] + x2*w1s[2*CP_+c];
        sum += y; sq += y*y;
    }
    srS[p][sub] = sum; srQ[p][sub] = sq;
    __syncthreads();
    float mean = (srS[p][0]+srS[p][1]+srS[p][2]+srS[p][3]) * (1.f/CP_);
    float var  = (srQ[p][0]+srQ[p][1]+srQ[p][2]+srQ[p][3]) * (1.f/CP_) - mean*mean;
    float rstd = rsqrtf(var + 1e-5f);

    // recompute, LN+ReLU, split hi/lo, write A rows to smem
    #pragma unroll 8
    for (int i = 0; i < 32; i++) {
        int c = c0 + 2*i;
        float y0 = b1s[c]   + x0*w1s[c]   + x1*w1s[CP_+c]   + x2*w1s[2*CP_+c];
        float y1 = b1s[c+1] + x0*w1s[c+1] + x1*w1s[CP_+c+1] + x2*w1s[2*CP_+c+1];
        y0 = fmaxf((y0-mean)*rstd*g1s[c]   + e1s[c],   0.f);
        y1 = fmaxf((y1-mean)*rstd*g1s[c+1] + e1s[c+1], 0.f);
        uint32_t wl, wh = pack2(y0, y1, &wl);
        *(uint32_t*)(ds + (size_t)p*A_STR + c*2) = wh;
        *(uint32_t*)(ds + OFF_AL + (size_t)p*A_STR + c*2) = wl;
    }

    // ---- HMMA mainloop: 8 K32 chunks, double-buffered B ----
    int mt0 = (wid >> 2) * 16;
    int nb  = (wid & 3) * 64;
    uint32_t aoff0 = (uint32_t)(mt0 + (lane&7) + ((lane>>3)&1)*8)*A_STR + (lane>>4)*16;
    uint32_t aoff1 = aoff0 + 64u*A_STR;
    uint32_t boff  = (uint32_t)(nb + (lane&7) + (lane>>4)*8)*B_STR + ((lane>>3)&1)*16;

    float dA[8][4] = {}, dB[8][4] = {};
    for (int ch = 0; ch < 8; ch++) {
        CPWAIT1();
        __syncthreads();
        uint32_t bb = su + OFF_B + (uint32_t)(ch&1)*B_BUF;
        #pragma unroll
        for (int kb = 0; kb < 2; kb++) {
            uint32_t kA = (uint32_t)(ch*64 + kb*32);
            uint32_t ah[4], al[4], ah2[4], al2[4];
            LDSM4(ah,  su + aoff0 + kA);
            LDSM4(al,  su + OFF_AL + aoff0 + kA);
            LDSM4(ah2, su + aoff1 + kA);
            LDSM4(al2, su + OFF_AL + aoff1 + kA);
            #pragma unroll
            for (int nt = 0; nt < 4; nt++) {
                uint32_t bh[4], bl[4];
                uint32_t ba = bb + boff + (uint32_t)(nt*16*B_STR) + kb*32;
                LDSM4(bh, ba);
                LDSM4(bl, ba + B_PLANE);
                MMA_GROUP(dA[2*nt], dA[2*nt+1], dB[2*nt], dB[2*nt+1]);
            }
        }
        __syncthreads();
        if (ch < 6) { prefetchB(su, ch&1, ch+2, d_W2h, d_W2l, tid); }
        CPCOMMIT();   // empty group when ch>=6 keeps wait-count invariant
    }

    // store D frags to smem (reuse A region), fp32 [128][264]
    {
        float* Db = (float*)ds;
        int r = lane >> 2, q = (lane & 3)*2;
        #pragma unroll
        for (int nt = 0; nt < 8; nt++) {
            int col = nb + nt*8 + q;
            Db[(mt0+r)*D_STR + col]      = dA[nt][0];
            Db[(mt0+r)*D_STR + col + 1]  = dA[nt][1];
            Db[(mt0+r+8)*D_STR + col]    = dA[nt][2];
            Db[(mt0+r+8)*D_STR + col +1] = dA[nt][3];
            Db[(mt0+64+r)*D_STR + col]      = dB[nt][0];
            Db[(mt0+64+r)*D_STR + col + 1]  = dB[nt][1];
            Db[(mt0+64+r+8)*D_STR + col]    = dB[nt][2];
            Db[(mt0+64+r+8)*D_STR + col +1] = dB[nt][3];
        }
    }
    __syncthreads();

    // LN2 over D
    const float* Db = (const float*)ds;
    sum = 0.f; sq = 0.f;
    #pragma unroll 4
    for (int c = c0; c < c0+64; c++) {
        float v = Db[p*D_STR + c] + b2s[c];
        sum += v; sq += v*v;
    }
    srS[p][sub] = sum; srQ[p][sub] = sq;
    __syncthreads();
    mean = (srS[p][0]+srS[p][1]+srS[p][2]+srS[p][3]) * (1.f/CP_);
    var  = (srQ[p][0]+srQ[p][1]+srQ[p][2]+srQ[p][3]) * (1.f/CP_) - mean*mean;
    rstd = rsqrtf(var + 1e-5f);

    unsigned char* lw = d_localA + (size_t)tile*A_IMG;
    #pragma unroll 8
    for (int i = 0; i < 32; i++) {
        int c = c0 + 2*i;
        float v0 = Db[p*D_STR + c]   + b2s[c];
        float v1 = Db[p*D_STR + c+1] + b2s[c+1];
        float lv0 = (v0-mean)*rstd*g2s[c]   + e2s[c];
        float lv1 = (v1-mean)*rstd*g2s[c+1] + e2s[c+1];
        atomicMaxFloat(&cmax[c],   lv0);
        atomicMaxFloat(&cmax[c+1], lv1);
        uint32_t wl, wh = pack2(lv0, lv1, &wl);
        *(uint32_t*)(lw + (size_t)p*A_STR + c*2) = wh;
        *(uint32_t*)(lw + OFF_AL + (size_t)p*A_STR + c*2) = wl;
    }
    __syncthreads();
    if (tid < 256) atomicMaxFloat(&d_gmax[bv*CP_ + tid], cmax[tid]);
}

// ---------------- kC: gpart = global_xyz @ W3[256:512] + b3 -----------------
__global__ void __launch_bounds__(256) kC(const float* __restrict__ W3,
                                          const float* __restrict__ b3) {
    int bv = blockIdx.x;
    int c  = threadIdx.x;
    __shared__ float sg[CP_];
    sg[c] = d_gmax[bv*CP_ + c];
    __syncthreads();
    float acc = b3[c];
    const float* w = W3 + (size_t)256*CP_ + c;
    #pragma unroll 8
    for (int k = 0; k < CP_; k++) acc += sg[k] * w[(size_t)k*CP_];
    d_gpart[bv*CP_ + c] = acc;
}

// ---------------- kD: HMMA(W3-top) + LN3 + ReLU + W4 -> weights -------------
__global__ void __launch_bounds__(512) kD(const float* __restrict__ masks,
    const float* __restrict__ g3, const float* __restrict__ be3,
    const float* __restrict__ W4)
{
    extern __shared__ unsigned char ds[];
    __shared__ float sG3[CP_], sE3[CP_], sW4[CP_], sGp[CP_];
    __shared__ float srS[TM_][4], srQ[TM_][4];
    __shared__ float sw[TM_];

    int tile = blockIdx.x;
    int bv = tile >> 7;
    int n0g = (tile & 127) * TM_;
    int tid = threadIdx.x, lane = tid & 31, wid = tid >> 5;
    uint32_t su = sm2u(ds);

    // group 0: entire A image + B chunk 0 ; group 1: B chunk 1
    {
        const unsigned char* src = d_localA + (size_t)tile*A_IMG;
        for (int i = tid; i < A_IMG/16; i += 512)
            CPA16(su + (uint32_t)i*16, src + (size_t)i*16);
    }
    prefetchB(su, 0, 0, d_W3h, d_W3l, tid); CPCOMMIT();
    prefetchB(su, 1, 1, d_W3h, d_W3l, tid); CPCOMMIT();

    if (tid < 256) {
        sG3[tid] = g3[tid]; sE3[tid] = be3[tid]; sW4[tid] = W4[tid];
        sGp[tid] = d_gpart[bv*CP_ + tid];
    }

    int mt0 = (wid >> 2) * 16;
    int nb  = (wid & 3) * 64;
    uint32_t aoff0 = (uint32_t)(mt0 + (lane&7) + ((lane>>3)&1)*8)*A_STR + (lane>>4)*16;
    uint32_t aoff1 = aoff0 + 64u*A_STR;
    uint32_t boff  = (uint32_t)(nb + (lane&7) + (lane>>4)*8)*B_STR + ((lane>>3)&1)*16;

    float dA[8][4] = {}, dB[8][4] = {};
    for (int ch = 0; ch < 8; ch++) {
        CPWAIT1();
        __syncthreads();
        uint32_t bb = su + OFF_B + (uint32_t)(ch&1)*B_BUF;
        #pragma unroll
        for (int kb = 0; kb < 2; kb++) {
            uint32_t kA = (uint32_t)(ch*64 + kb*32);
            uint32_t ah[4], al[4], ah2[4], al2[4];
            LDSM4(ah,  su + aoff0 + kA);
            LDSM4(al,  su + OFF_AL + aoff0 + kA);
            LDSM4(ah2, su + aoff1 + kA);
            LDSM4(al2, su + OFF_AL + aoff1 + kA);
            #pragma unroll
            for (int nt = 0; nt < 4; nt++) {
                uint32_t bh[4], bl[4];
                uint32_t ba = bb + boff + (uint32_t)(nt*16*B_STR) + kb*32;
                LDSM4(bh, ba);
                LDSM4(bl, ba + B_PLANE);
                MMA_GROUP(dA[2*nt], dA[2*nt+1], dB[2*nt], dB[2*nt+1]);
            }
        }
        __syncthreads();
        if (ch < 6) { prefetchB(su, ch&1, ch+2, d_W3h, d_W3l, tid); }
        CPCOMMIT();
    }

    {
        float* Dbw = (float*)ds;
        int r = lane >> 2, q = (lane & 3)*2;
        #pragma unroll
        for (int nt = 0; nt < 8; nt++) {
            int col = nb + nt*8 + q;
            Dbw[(mt0+r)*D_STR + col]      = dA[nt][0];
            Dbw[(mt0+r)*D_STR + col + 1]  = dA[nt][1];
            Dbw[(mt0+r+8)*D_STR + col]    = dA[nt][2];
            Dbw[(mt0+r+8)*D_STR + col +1] = dA[nt][3];
            Dbw[(mt0+64+r)*D_STR + col]      = dB[nt][0];
            Dbw[(mt0+64+r)*D_STR + col + 1]  = dB[nt][1];
            Dbw[(mt0+64+r+8)*D_STR + col]    = dB[nt][2];
            Dbw[(mt0+64+r+8)*D_STR + col +1] = dB[nt][3];
        }
    }
    __syncthreads();

    const float* Db = (const float*)ds;
    int p = tid >> 2, sub = tid & 3, c0 = sub*64;
    float sum = 0.f, sq = 0.f;
    #pragma unroll 4
    for (int c = c0; c < c0+64; c++) {
        float v = Db[p*D_STR + c] + sGp[c];
        sum += v; sq += v*v;
    }
    srS[p][sub] = sum; srQ[p][sub] = sq;
    __syncthreads();
    float mean = (srS[p][0]+srS[p][1]+srS[p][2]+srS[p][3]) * (1.f/CP_);
    float var  = (srQ[p][0]+srQ[p][1]+srQ[p][2]+srQ[p][3]) * (1.f/CP_) - mean*mean;
    float rstd = rsqrtf(var + 1e-5f);

    float dot = 0.f;
    #pragma unroll 4
    for (int c = c0; c < c0+64; c++) {
        float v = Db[p*D_STR + c] + sGp[c];
        float hv = fmaxf((v-mean)*rstd*sG3[c] + sE3[c], 0.f);
        dot += hv * sW4[c];
    }
    __syncthreads();
    srS[p][sub] = dot;
    __syncthreads();
    if (sub == 0) {
        float dt = srS[p][0]+srS[p][1]+srS[p][2]+srS[p][3];
        int n = n0g + p;
        float m = masks[(size_t)bv*N_ + n];
        float w = 2.f * m / (1.f + expf(-dt));
        d_mw[(size_t)bv*N_ + n] = w;
        sw[p] = w;
    }
    __syncthreads();
    if (tid == 0) {
        float s = 0.f;
        #pragma unroll 8
        for (int i = 0; i < TM_; i++) s += sw[i];
        atomicAdd(&d_denom[bv], s);
    }
}

// ---------------- kE: weighted pooling + epilogue ---------------------------
__global__ void __launch_bounds__(256) kE(const float* __restrict__ feats,
                                          float* __restrict__ out) {
    int blk = blockIdx.x;        // b*CP_ + c
    int b = blk >> 8;
    int c = blk & 255;
    int tid = threadIdx.x;

    const float* f   = feats + (size_t)(b*CP_ + c)*N_;
    const float* mw0 = d_mw + (size_t)(b*4+0)*N_;
    const float* mw1 = d_mw + (size_t)(b*4+1)*N_;
    const float* mw2 = d_mw + (size_t)(b*4+2)*N_;
    const float* mw3 = d_mw + (size_t)(b*4+3)*N_;

    float a0=0.f, a1=0.f, a2=0.f, a3=0.f;
    for (int n = tid; n < N_; n += 256) {
        float fv = f[n];
        a0 += fv*mw0[n]; a1 += fv*mw1[n]; a2 += fv*mw2[n]; a3 += fv*mw3[n];
    }
    #pragma unroll
    for (int o = 16; o > 0; o >>= 1) {
        a0 += __shfl_xor_sync(0xffffffffu, a0, o);
        a1 += __shfl_xor_sync(0xffffffffu, a1, o);
        a2 += __shfl_xor_sync(0xffffffffu, a2, o);
        a3 += __shfl_xor_sync(0xffffffffu, a3, o);
    }
    __shared__ float sr[4][8];
    int lane = tid & 31, warp = tid >> 5;
    if (lane == 0) { sr[0][warp]=a0; sr[1][warp]=a1; sr[2][warp]=a2; sr[3][warp]=a3; }
    __syncthreads();
    if (tid < 4) {
        float ps = 0.f;
        #pragma unroll
        for (int w = 0; w < 8; w++) ps += sr[tid][w];
        int bvv = b*4 + tid;
        float den = fmaxf(d_denom[bvv], 1e-8f);
        out[(size_t)bvv*CP_ + c] = ps/den + d_gmax[bvv*CP_ + c];
    }
}

// ---------------- launch ----------------------------------------------------
extern "C" void kernel_launch(void* const* d_in, const int* in_sizes, int n_in,
                              void* d_out, int out_size) {
    const float* xyz = (const float*)d_in[0];
    const float* pf  = (const float*)d_in[1];
    const float* pm  = (const float*)d_in[2];
    const float* W1  = (const float*)d_in[3];
    const float* b1  = (const float*)d_in[4];
    const float* g1  = (const float*)d_in[5];
    const float* be1 = (const float*)d_in[6];
    const float* W2  = (const float*)d_in[7];
    const float* b2  = (const float*)d_in[8];
    const float* g2  = (const float*)d_in[9];
    const float* be2 = (const float*)d_in[10];
    const float* W3  = (const float*)d_in[11];
    const float* b3  = (const float*)d_in[12];
    const float* g3  = (const float*)d_in[13];
    const float* be3 = (const float*)d_in[14];
    const float* W4  = (const float*)d_in[15];
    float* out = (float*)d_out;

    static int configured = 0;
    if (!configured) {
        cudaFuncSetAttribute(kB, cudaFuncAttributeMaxDynamicSharedMemorySize, DYN_SMEM);
        cudaFuncSetAttribute(kD, cudaFuncAttributeMaxDynamicSharedMemorySize, DYN_SMEM);
        configured = 1;
    }

    kP<<<CP_, 256>>>(W2, W3);
    kA<<<BV_, 256>>>(xyz, pm);
    kB<<<NT2_, 512, DYN_SMEM>>>(xyz, W1, b1, g1, be1, b2, g2, be2);
    kC<<<BV_, 256>>>(W3, b3);
    kD<<<NT2_, 512, DYN_SMEM>>>(pm, g3, be3, W4);
    kE<<<B_*CP_, 256>>>(pf, out);
}

// round 7
// speedup vs baseline: 1.5952x; 1.4194x over previous
#include <cuda_runtime.h>
#include <cuda_fp16.h>
#include <math.h>
#include <float.h>
#include <stdint.h>

#define B_   8
#define V_   4
#define N_   16384
#define CP_  256
#define BV_  (B_*V_)            // 32
#define TM_  128                // points per CTA tile
#define NT2_ (N_*BV_/TM_)       // 4096 tiles
#define A_STR 528               // A row stride bytes (256 fp16 = 512B + 16 pad)
#define B_STR 80                // B row stride bytes (32 fp16 = 64B + 16 pad)
#define D_STR 264               // D row stride floats
#define OFF_B    67584          // B buffers start (128*528)
#define B_BUF    20480          // one K32 chunk: 256 rows x 80B
#define B_GCH    16384          // packed gmem chunk bytes (256*64)
#define A_IMG    67584          // A image bytes (single fp16 plane)
#define DYN_SMEM 135168         // max(A+2B = 108544, D staging 128*264*4 = 135168)

// ---------------- device scratch (static; no allocations) -------------------
__device__ float d_center[BV_*3];
__device__ float d_invdiam[BV_];
__device__ __align__(16) float d_gmax[BV_*CP_];
__device__ __align__(16) float d_gpart[BV_*CP_];
__device__ float d_mw[BV_*N_];
__device__ float d_denom[BV_];
// local_xyz: exact padded A-smem byte image per tile (fp16, single plane)
__device__ __align__(16) unsigned char d_localA[(size_t)NT2_*A_IMG];  // 277MB
// weights fp16, packed K32-chunk layout: [chunk 8][n 256][32 fp16]
__device__ __align__(16) unsigned char d_W2f[CP_*CP_*2];
__device__ __align__(16) unsigned char d_W3f[CP_*CP_*2];

// ---------------- helpers ---------------------------------------------------
__device__ __forceinline__ uint32_t sm2u(const void* p) {
    uint32_t a;
    asm("{ .reg .u64 t; cvta.to.shared.u64 t, %1; cvt.u32.u64 %0, t; }"
        : "=r"(a) : "l"(p));
    return a;
}
#define LDSM4(r, addr) \
    asm volatile("ldmatrix.sync.aligned.m8n8.x4.shared.b16 {%0,%1,%2,%3}, [%4];" \
        : "=r"((r)[0]), "=r"((r)[1]), "=r"((r)[2]), "=r"((r)[3]) : "r"(addr))
#define MMAOP(d, a, b0, b1) \
    asm volatile("mma.sync.aligned.m16n8k16.row.col.f32.f16.f16.f32 " \
        "{%0,%1,%2,%3}, {%4,%5,%6,%7}, {%8,%9}, {%0,%1,%2,%3};" \
        : "+f"((d)[0]), "+f"((d)[1]), "+f"((d)[2]), "+f"((d)[3]) \
        : "r"((a)[0]), "r"((a)[1]), "r"((a)[2]), "r"((a)[3]), "r"(b0), "r"(b1))
#define CPA16(dst, src) \
    asm volatile("cp.async.cg.shared.global [%0], [%1], 16;" :: "r"(dst), "l"(src))
#define CPCOMMIT() asm volatile("cp.async.commit_group;" ::: "memory")
#define CPWAIT1()  asm volatile("cp.async.wait_group 1;" ::: "memory")

static __device__ __forceinline__ uint32_t pack2h(float v0, float v1) {
    __half h0 = __float2half_rn(v0);
    __half h1 = __float2half_rn(v1);
    return (uint32_t)__half_as_ushort(h0) | ((uint32_t)__half_as_ushort(h1) << 16);
}
__device__ __forceinline__ void atomicMaxFloat(float* addr, float val) {
    if (__float_as_int(val) >= 0) atomicMax((int*)addr, __float_as_int(val));
    else atomicMin((unsigned int*)addr, __float_as_uint(val));
}

// issue cp.async for B chunk ch into buffer buf (0/1): 16KB, 2 ops/thread
__device__ __forceinline__ void prefetchB(uint32_t su, int buf, int ch,
                                          const unsigned char* g, int tid) {
    uint32_t base = su + OFF_B + (uint32_t)buf*B_BUF;
    #pragma unroll
    for (int i = 0; i < 2; i++) {
        int w = tid + i*512;             // 0..1023
        int n = w >> 2, c16 = w & 3;
        uint32_t dst = base + (uint32_t)n*B_STR + c16*16;
        CPA16(dst, g + (size_t)ch*B_GCH + (size_t)w*16);
    }
}

// ---------------- kP: convert weights to fp16 packed chunk layout -----------
__global__ void __launch_bounds__(256) kP(const float* __restrict__ W2,
                                          const float* __restrict__ W3) {
    int k = blockIdx.x;   // GEMM K
    int n = threadIdx.x;  // GEMM N
    int ch = k >> 5, kk = k & 31;
    size_t pos = (size_t)ch*B_GCH + (size_t)n*64 + (size_t)kk*2;
    *(unsigned short*)(d_W2f + pos) = __half_as_ushort(__float2half_rn(W2[k*CP_ + n]));
    *(unsigned short*)(d_W3f + pos) = __half_as_ushort(__float2half_rn(W3[k*CP_ + n]));
}

// ---------------- kA: per-(b,v) stats + init --------------------------------
__global__ void __launch_bounds__(256) kA(const float* __restrict__ xyz,
                                          const float* __restrict__ masks) {
    int bv = blockIdx.x;
    int b  = bv >> 2;
    int tid = threadIdx.x;

    float s0=0.f, s1=0.f, s2=0.f, cnt=0.f;
    float mx0=-FLT_MAX, mx1=-FLT_MAX, mx2=-FLT_MAX;
    float mn0= FLT_MAX, mn1= FLT_MAX, mn2= FLT_MAX;

    const float* mrow = masks + (size_t)bv*N_;
    const float* x0r  = xyz + (size_t)(b*3+0)*N_;
    const float* x1r  = xyz + (size_t)(b*3+1)*N_;
    const float* x2r  = xyz + (size_t)(b*3+2)*N_;

    for (int n = tid; n < N_; n += 256) {
        float m = mrow[n];
        float a = x0r[n]*m, c = x1r[n]*m, e = x2r[n]*m;
        s0 += a; s1 += c; s2 += e; cnt += m;
        mx0 = fmaxf(mx0,a); mx1 = fmaxf(mx1,c); mx2 = fmaxf(mx2,e);
        mn0 = fminf(mn0,a); mn1 = fminf(mn1,c); mn2 = fminf(mn2,e);
    }
    __shared__ float rs[4][256];
    __shared__ float rx[3][256];
    __shared__ float rn[3][256];
    rs[0][tid]=s0; rs[1][tid]=s1; rs[2][tid]=s2; rs[3][tid]=cnt;
    rx[0][tid]=mx0; rx[1][tid]=mx1; rx[2][tid]=mx2;
    rn[0][tid]=mn0; rn[1][tid]=mn1; rn[2][tid]=mn2;
    __syncthreads();
    for (int s = 128; s > 0; s >>= 1) {
        if (tid < s) {
            #pragma unroll
            for (int q = 0; q < 4; q++) rs[q][tid] += rs[q][tid+s];
            #pragma unroll
            for (int q = 0; q < 3; q++) {
                rx[q][tid] = fmaxf(rx[q][tid], rx[q][tid+s]);
                rn[q][tid] = fminf(rn[q][tid], rn[q][tid+s]);
            }
        }
        __syncthreads();
    }
    if (tid == 0) {
        float valid = fmaxf(rs[3][0], 1.f);
        d_center[bv*3+0] = rs[0][0]/valid;
        d_center[bv*3+1] = rs[1][0]/valid;
        d_center[bv*3+2] = rs[2][0]/valid;
        float diam = fmaxf(fmaxf(rx[0][0]-rn[0][0], rx[1][0]-rn[1][0]),
                           rx[2][0]-rn[2][0]);
        if (diam == 0.f) diam = 1.f;
        d_invdiam[bv] = 1.f/diam;
        d_denom[bv]   = 0.f;
    }
    d_gmax[bv*CP_ + tid] = -FLT_MAX;
}

// ---------------- kB: stage1+LN1+ReLU -> HMMA(W2) -> LN2 -> local + gmax ----
__global__ void __launch_bounds__(512) kB(const float* __restrict__ xyz,
    const float* __restrict__ W1, const float* __restrict__ b1,
    const float* __restrict__ g1, const float* __restrict__ be1,
    const float* __restrict__ b2, const float* __restrict__ g2,
    const float* __restrict__ be2)
{
    extern __shared__ unsigned char ds[];
    __shared__ float w1s[3*CP_];
    __shared__ float b1s[CP_], g1s[CP_], e1s[CP_], b2s[CP_], g2s[CP_], e2s[CP_];
    __shared__ float srS[TM_][4], srQ[TM_][4];
    __shared__ float cmax[CP_];

    int tile = blockIdx.x;
    int bv = tile >> 7;
    int b  = bv >> 2;
    int tid = threadIdx.x, lane = tid & 31, wid = tid >> 5;
    uint32_t su = sm2u(ds);

    // B chunk 0/1 prefetch first (overlaps all of stage-1)
    prefetchB(su, 0, 0, d_W2f, tid); CPCOMMIT();
    prefetchB(su, 1, 1, d_W2f, tid); CPCOMMIT();

    for (int i = tid; i < 3*CP_; i += 512) w1s[i] = W1[i];
    if (tid < 256) {
        b1s[tid]=b1[tid]; g1s[tid]=g1[tid]; e1s[tid]=be1[tid];
        b2s[tid]=b2[tid]; g2s[tid]=g2[tid]; e2s[tid]=be2[tid];
        cmax[tid] = -FLT_MAX;
    }

    int p = tid >> 2, sub = tid & 3, c0 = sub*64;
    float idm = d_invdiam[bv];
    int n = (tile & 127) * TM_ + p;
    float x0 = (xyz[(size_t)(b*3+0)*N_ + n] - d_center[bv*3+0]) * idm;
    float x1 = (xyz[(size_t)(b*3+1)*N_ + n] - d_center[bv*3+1]) * idm;
    float x2 = (xyz[(size_t)(b*3+2)*N_ + n] - d_center[bv*3+2]) * idm;
    __syncthreads();

    // LN1 stats over this thread's 64 channels
    float sum = 0.f, sq = 0.f;
    #pragma unroll 4
    for (int c = c0; c < c0+64; c++) {
        float y = b1s[c] + x0*w1s[c] + x1*w1s[CP_+c] + x2*w1s[2*CP_+c];
        sum += y; sq += y*y;
    }
    srS[p][sub] = sum; srQ[p][sub] = sq;
    __syncthreads();
    float mean = (srS[p][0]+srS[p][1]+srS[p][2]+srS[p][3]) * (1.f/CP_);
    float var  = (srQ[p][0]+srQ[p][1]+srQ[p][2]+srQ[p][3]) * (1.f/CP_) - mean*mean;
    float rstd = rsqrtf(var + 1e-5f);

    // recompute, LN+ReLU, fp16, write A rows to smem
    #pragma unroll 8
    for (int i = 0; i < 32; i++) {
        int c = c0 + 2*i;
        float y0 = b1s[c]   + x0*w1s[c]   + x1*w1s[CP_+c]   + x2*w1s[2*CP_+c];
        float y1 = b1s[c+1] + x0*w1s[c+1] + x1*w1s[CP_+c+1] + x2*w1s[2*CP_+c+1];
        y0 = fmaxf((y0-mean)*rstd*g1s[c]   + e1s[c],   0.f);
        y1 = fmaxf((y1-mean)*rstd*g1s[c+1] + e1s[c+1], 0.f);
        *(uint32_t*)(ds + (size_t)p*A_STR + c*2) = pack2h(y0, y1);
    }

    // ---- HMMA mainloop: 8 K32 chunks, double-buffered B ----
    int mt0 = (wid >> 2) * 16;
    int nb  = (wid & 3) * 64;
    uint32_t aoff0 = (uint32_t)(mt0 + (lane&7) + ((lane>>3)&1)*8)*A_STR + (lane>>4)*16;
    uint32_t aoff1 = aoff0 + 64u*A_STR;
    uint32_t boff  = (uint32_t)(nb + (lane&7) + (lane>>4)*8)*B_STR + ((lane>>3)&1)*16;

    float dA[8][4] = {}, dB[8][4] = {};
    for (int ch = 0; ch < 8; ch++) {
        CPWAIT1();
        __syncthreads();
        uint32_t bb = su + OFF_B + (uint32_t)(ch&1)*B_BUF;
        #pragma unroll
        for (int kb = 0; kb < 2; kb++) {
            uint32_t kA = (uint32_t)(ch*64 + kb*32);
            uint32_t ah[4], ah2[4];
            LDSM4(ah,  su + aoff0 + kA);
            LDSM4(ah2, su + aoff1 + kA);
            #pragma unroll
            for (int nt = 0; nt < 4; nt++) {
                uint32_t bh[4];
                LDSM4(bh, bb + boff + (uint32_t)(nt*16*B_STR) + kb*32);
                MMAOP(dA[2*nt],   ah,  bh[0], bh[1]);
                MMAOP(dA[2*nt+1], ah,  bh[2], bh[3]);
                MMAOP(dB[2*nt],   ah2, bh[0], bh[1]);
                MMAOP(dB[2*nt+1], ah2, bh[2], bh[3]);
            }
        }
        __syncthreads();
        if (ch < 6) { prefetchB(su, ch&1, ch+2, d_W2f, tid); }
        CPCOMMIT();   // empty group when ch>=6 keeps wait-count invariant
    }

    // store D frags to smem (reuse A+B region), fp32 [128][264]
    {
        float* Db = (float*)ds;
        int r = lane >> 2, q = (lane & 3)*2;
        #pragma unroll
        for (int nt = 0; nt < 8; nt++) {
            int col = nb + nt*8 + q;
            Db[(mt0+r)*D_STR + col]      = dA[nt][0];
            Db[(mt0+r)*D_STR + col + 1]  = dA[nt][1];
            Db[(mt0+r+8)*D_STR + col]    = dA[nt][2];
            Db[(mt0+r+8)*D_STR + col +1] = dA[nt][3];
            Db[(mt0+64+r)*D_STR + col]      = dB[nt][0];
            Db[(mt0+64+r)*D_STR + col + 1]  = dB[nt][1];
            Db[(mt0+64+r+8)*D_STR + col]    = dB[nt][2];
            Db[(mt0+64+r+8)*D_STR + col +1] = dB[nt][3];
        }
    }
    __syncthreads();

    // LN2 over D
    const float* Db = (const float*)ds;
    sum = 0.f; sq = 0.f;
    #pragma unroll 4
    for (int c = c0; c < c0+64; c++) {
        float v = Db[p*D_STR + c] + b2s[c];
        sum += v; sq += v*v;
    }
    srS[p][sub] = sum; srQ[p][sub] = sq;
    __syncthreads();
    mean = (srS[p][0]+srS[p][1]+srS[p][2]+srS[p][3]) * (1.f/CP_);
    var  = (srQ[p][0]+srQ[p][1]+srQ[p][2]+srQ[p][3]) * (1.f/CP_) - mean*mean;
    rstd = rsqrtf(var + 1e-5f);

    unsigned char* lw = d_localA + (size_t)tile*A_IMG;
    #pragma unroll 8
    for (int i = 0; i < 32; i++) {
        int c = c0 + 2*i;
        float v0 = Db[p*D_STR + c]   + b2s[c];
        float v1 = Db[p*D_STR + c+1] + b2s[c+1];
        float lv0 = (v0-mean)*rstd*g2s[c]   + e2s[c];
        float lv1 = (v1-mean)*rstd*g2s[c+1] + e2s[c+1];
        atomicMaxFloat(&cmax[c],   lv0);
        atomicMaxFloat(&cmax[c+1], lv1);
        *(uint32_t*)(lw + (size_t)p*A_STR + c*2) = pack2h(lv0, lv1);
    }
    __syncthreads();
    if (tid < 256) atomicMaxFloat(&d_gmax[bv*CP_ + tid], cmax[tid]);
}

// ---------------- kC: gpart = global_xyz @ W3[256:512] + b3 -----------------
__global__ void __launch_bounds__(256) kC(const float* __restrict__ W3,
                                          const float* __restrict__ b3) {
    int bv = blockIdx.x;
    int c  = threadIdx.x;
    __shared__ float sg[CP_];
    sg[c] = d_gmax[bv*CP_ + c];
    __syncthreads();
    float acc = b3[c];
    const float* w = W3 + (size_t)256*CP_ + c;
    #pragma unroll 8
    for (int k = 0; k < CP_; k++) acc += sg[k] * w[(size_t)k*CP_];
    d_gpart[bv*CP_ + c] = acc;
}

// ---------------- kD: HMMA(W3-top) + LN3 + ReLU + W4 -> weights -------------
__global__ void __launch_bounds__(512) kD(const float* __restrict__ masks,
    const float* __restrict__ g3, const float* __restrict__ be3,
    const float* __restrict__ W4)
{
    extern __shared__ unsigned char ds[];
    __shared__ float sG3[CP_], sE3[CP_], sW4[CP_], sGp[CP_];
    __shared__ float srS[TM_][4], srQ[TM_][4];
    __shared__ float sw[TM_];

    int tile = blockIdx.x;
    int bv = tile >> 7;
    int n0g = (tile & 127) * TM_;
    int tid = threadIdx.x, lane = tid & 31, wid = tid >> 5;
    uint32_t su = sm2u(ds);

    // group 0: entire A image (66KB) + B chunk 0 ; group 1: B chunk 1
    {
        const unsigned char* src = d_localA + (size_t)tile*A_IMG;
        for (int i = tid; i < A_IMG/16; i += 512)
            CPA16(su + (uint32_t)i*16, src + (size_t)i*16);
    }
    prefetchB(su, 0, 0, d_W3f, tid); CPCOMMIT();
    prefetchB(su, 1, 1, d_W3f, tid); CPCOMMIT();

    if (tid < 256) {
        sG3[tid] = g3[tid]; sE3[tid] = be3[tid]; sW4[tid] = W4[tid];
        sGp[tid] = d_gpart[bv*CP_ + tid];
    }

    int mt0 = (wid >> 2) * 16;
    int nb  = (wid & 3) * 64;
    uint32_t aoff0 = (uint32_t)(mt0 + (lane&7) + ((lane>>3)&1)*8)*A_STR + (lane>>4)*16;
    uint32_t aoff1 = aoff0 + 64u*A_STR;
    uint32_t boff  = (uint32_t)(nb + (lane&7) + (lane>>4)*8)*B_STR + ((lane>>3)&1)*16;

    float dA[8][4] = {}, dB[8][4] = {};
    for (int ch = 0; ch < 8; ch++) {
        CPWAIT1();
        __syncthreads();
        uint32_t bb = su + OFF_B + (uint32_t)(ch&1)*B_BUF;
        #pragma unroll
        for (int kb = 0; kb < 2; kb++) {
            uint32_t kA = (uint32_t)(ch*64 + kb*32);
            uint32_t ah[4], ah2[4];
            LDSM4(ah,  su + aoff0 + kA);
            LDSM4(ah2, su + aoff1 + kA);
            #pragma unroll
            for (int nt = 0; nt < 4; nt++) {
                uint32_t bh[4];
                LDSM4(bh, bb + boff + (uint32_t)(nt*16*B_STR) + kb*32);
                MMAOP(dA[2*nt],   ah,  bh[0], bh[1]);
                MMAOP(dA[2*nt+1], ah,  bh[2], bh[3]);
                MMAOP(dB[2*nt],   ah2, bh[0], bh[1]);
                MMAOP(dB[2*nt+1], ah2, bh[2], bh[3]);
            }
        }
        __syncthreads();
        if (ch < 6) { prefetchB(su, ch&1, ch+2, d_W3f, tid); }
        CPCOMMIT();
    }

    {
        float* Dbw = (float*)ds;
        int r = lane >> 2, q = (lane & 3)*2;
        #pragma unroll
        for (int nt = 0; nt < 8; nt++) {
            int col = nb + nt*8 + q;
            Dbw[(mt0+r)*D_STR + col]      = dA[nt][0];
            Dbw[(mt0+r)*D_STR + col + 1]  = dA[nt][1];
            Dbw[(mt0+r+8)*D_STR + col]    = dA[nt][2];
            Dbw[(mt0+r+8)*D_STR + col +1] = dA[nt][3];
            Dbw[(mt0+64+r)*D_STR + col]      = dB[nt][0];
            Dbw[(mt0+64+r)*D_STR + col + 1]  = dB[nt][1];
            Dbw[(mt0+64+r+8)*D_STR + col]    = dB[nt][2];
            Dbw[(mt0+64+r+8)*D_STR + col +1] = dB[nt][3];
        }
    }
    __syncthreads();

    const float* Db = (const float*)ds;
    int p = tid >> 2, sub = tid & 3, c0 = sub*64;
    float sum = 0.f, sq = 0.f;
    #pragma unroll 4
    for (int c = c0; c < c0+64; c++) {
        float v = Db[p*D_STR + c] + sGp[c];
        sum += v; sq += v*v;
    }
    srS[p][sub] = sum; srQ[p][sub] = sq;
    __syncthreads();
    float mean = (srS[p][0]+srS[p][1]+srS[p][2]+srS[p][3]) * (1.f/CP_);
    float var  = (srQ[p][0]+srQ[p][1]+srQ[p][2]+srQ[p][3]) * (1.f/CP_) - mean*mean;
    float rstd = rsqrtf(var + 1e-5f);

    float dot = 0.f;
    #pragma unroll 4
    for (int c = c0; c < c0+64; c++) {
        float v = Db[p*D_STR + c] + sGp[c];
        float hv = fmaxf((v-mean)*rstd*sG3[c] + sE3[c], 0.f);
        dot += hv * sW4[c];
    }
    __syncthreads();
    srS[p][sub] = dot;
    __syncthreads();
    if (sub == 0) {
        float dt = srS[p][0]+srS[p][1]+srS[p][2]+srS[p][3];
        int n = n0g + p;
        float m = masks[(size_t)bv*N_ + n];
        float w = 2.f * m / (1.f + expf(-dt));
        d_mw[(size_t)bv*N_ + n] = w;
        sw[p] = w;
    }
    __syncthreads();
    if (tid == 0) {
        float s = 0.f;
        #pragma unroll 8
        for (int i = 0; i < TM_; i++) s += sw[i];
        atomicAdd(&d_denom[bv], s);
    }
}

// ---------------- kE: weighted pooling + epilogue ---------------------------
__global__ void __launch_bounds__(256) kE(const float* __restrict__ feats,
                                          float* __restrict__ out) {
    int blk = blockIdx.x;        // b*CP_ + c
    int b = blk >> 8;
    int c = blk & 255;
    int tid = threadIdx.x;

    const float* f   = feats + (size_t)(b*CP_ + c)*N_;
    const float* mw0 = d_mw + (size_t)(b*4+0)*N_;
    const float* mw1 = d_mw + (size_t)(b*4+1)*N_;
    const float* mw2 = d_mw + (size_t)(b*4+2)*N_;
    const float* mw3 = d_mw + (size_t)(b*4+3)*N_;

    float a0=0.f, a1=0.f, a2=0.f, a3=0.f;
    for (int n = tid; n < N_; n += 256) {
        float fv = f[n];
        a0 += fv*mw0[n]; a1 += fv*mw1[n]; a2 += fv*mw2[n]; a3 += fv*mw3[n];
    }
    #pragma unroll
    for (int o = 16; o > 0; o >>= 1) {
        a0 += __shfl_xor_sync(0xffffffffu, a0, o);
        a1 += __shfl_xor_sync(0xffffffffu, a1, o);
        a2 += __shfl_xor_sync(0xffffffffu, a2, o);
        a3 += __shfl_xor_sync(0xffffffffu, a3, o);
    }
    __shared__ float sr[4][8];
    int lane = tid & 31, warp = tid >> 5;
    if (lane == 0) { sr[0][warp]=a0; sr[1][warp]=a1; sr[2][warp]=a2; sr[3][warp]=a3; }
    __syncthreads();
    if (tid < 4) {
        float ps = 0.f;
        #pragma unroll
        for (int w = 0; w < 8; w++) ps += sr[tid][w];
        int bvv = b*4 + tid;
        float den = fmaxf(d_denom[bvv], 1e-8f);
        out[(size_t)bvv*CP_ + c] = ps/den + d_gmax[bvv*CP_ + c];
    }
}

// ---------------- launch ----------------------------------------------------
extern "C" void kernel_launch(void* const* d_in, const int* in_sizes, int n_in,
                              void* d_out, int out_size) {
    const float* xyz = (const float*)d_in[0];
    const float* pf  = (const float*)d_in[1];
    const float* pm  = (const float*)d_in[2];
    const float* W1  = (const float*)d_in[3];
    const float* b1  = (const float*)d_in[4];
    const float* g1  = (const float*)d_in[5];
    const float* be1 = (const float*)d_in[6];
    const float* W2  = (const float*)d_in[7];
    const float* b2  = (const float*)d_in[8];
    const float* g2  = (const float*)d_in[9];
    const float* be2 = (const float*)d_in[10];
    const float* W3  = (const float*)d_in[11];
    const float* b3  = (const float*)d_in[12];
    const float* g3  = (const float*)d_in[13];
    const float* be3 = (const float*)d_in[14];
    const float* W4  = (const float*)d_in[15];
    float* out = (float*)d_out;

    static int configured = 0;
    if (!configured) {
        cudaFuncSetAttribute(kB, cudaFuncAttributeMaxDynamicSharedMemorySize, DYN_SMEM);
        cudaFuncSetAttribute(kD, cudaFuncAttributeMaxDynamicSharedMemorySize, DYN_SMEM);
        configured = 1;
    }

    kP<<<CP_, 256>>>(W2, W3);
    kA<<<BV_, 256>>>(xyz, pm);
    kB<<<NT2_, 512, DYN_SMEM>>>(xyz, W1, b1, g1, be1, b2, g2, be2);
    kC<<<BV_, 256>>>(W3, b3);
    kD<<<NT2_, 512, DYN_SMEM>>>(pm, g3, be3, W4);
    kE<<<B_*CP_, 256>>>(pf, out);
}

// round 8
// speedup vs baseline: 1.9500x; 1.2224x over previous
#include <cuda_runtime.h>
#include <cuda_fp16.h>
#include <math.h>
#include <float.h>
#include <stdint.h>

#define B_   8
#define V_   4
#define N_   16384
#define CP_  256
#define BV_  (B_*V_)            // 32
#define TM_  64                 // points per CTA tile
#define NT2_ (N_*BV_/TM_)       // 8192 tiles
#define TPBV_ 256               // tiles per (b,v)
#define A_STR 528               // A row stride bytes (256 fp16 + 16 pad)
#define B_STR 80                // B row stride bytes (32 fp16 + 16 pad)
#define D_STR 264               // D row stride floats
#define A_IMG    33792          // 64*528
#define OFF_B    33792
#define B_BUF    20480          // one K32 chunk: 256 rows x 80B
#define B_GCH    16384          // packed gmem chunk bytes (256*64)
#define DYN_SMEM 95232          // A + 3*B_BUF ; D staging 64*264*4=67584 fits

// ---------------- device scratch (static; no allocations) -------------------
__device__ float d_center[BV_*3];
__device__ float d_invdiam[BV_];
__device__ __align__(16) float d_gmax[BV_*CP_];
__device__ __align__(16) float d_gpart[BV_*CP_];
__device__ float d_mw[BV_*N_];
__device__ float d_denom[BV_];
// local_xyz: exact padded A-smem byte image per tile (fp16)
__device__ __align__(16) unsigned char d_localA[(size_t)NT2_*A_IMG];  // 277MB
// weights fp16, packed K32-chunk layout: [chunk 8][n 256][32 fp16]
__device__ __align__(16) unsigned char d_W2f[CP_*CP_*2];
__device__ __align__(16) unsigned char d_W3f[CP_*CP_*2];

// ---------------- helpers ---------------------------------------------------
__device__ __forceinline__ uint32_t sm2u(const void* p) {
    uint32_t a;
    asm("{ .reg .u64 t; cvta.to.shared.u64 t, %1; cvt.u32.u64 %0, t; }"
        : "=r"(a) : "l"(p));
    return a;
}
#define LDSM4(r, addr) \
    asm volatile("ldmatrix.sync.aligned.m8n8.x4.shared.b16 {%0,%1,%2,%3}, [%4];" \
        : "=r"((r)[0]), "=r"((r)[1]), "=r"((r)[2]), "=r"((r)[3]) : "r"(addr))
#define MMAOP(d, a, b0, b1) \
    asm volatile("mma.sync.aligned.m16n8k16.row.col.f32.f16.f16.f32 " \
        "{%0,%1,%2,%3}, {%4,%5,%6,%7}, {%8,%9}, {%0,%1,%2,%3};" \
        : "+f"((d)[0]), "+f"((d)[1]), "+f"((d)[2]), "+f"((d)[3]) \
        : "r"((a)[0]), "r"((a)[1]), "r"((a)[2]), "r"((a)[3]), "r"(b0), "r"(b1))
#define CPA16(dst, src) \
    asm volatile("cp.async.cg.shared.global [%0], [%1], 16;" :: "r"(dst), "l"(src))
#define CPCOMMIT() asm volatile("cp.async.commit_group;" ::: "memory")
#define CPWAIT1()  asm volatile("cp.async.wait_group 1;" ::: "memory")

static __device__ __forceinline__ uint32_t pack2h(float v0, float v1) {
    __half h0 = __float2half_rn(v0);
    __half h1 = __float2half_rn(v1);
    return (uint32_t)__half_as_ushort(h0) | ((uint32_t)__half_as_ushort(h1) << 16);
}
__device__ __forceinline__ void atomicMaxFloat(float* addr, float val) {
    if (__float_as_int(val) >= 0) atomicMax((int*)addr, __float_as_int(val));
    else atomicMin((unsigned int*)addr, __float_as_uint(val));
}

// issue cp.async for B chunk ch into buffer buf (0..2): 16KB, 4 ops/thread
__device__ __forceinline__ void prefetchB(uint32_t su, int buf, int ch,
                                          const unsigned char* g, int tid) {
    uint32_t base = su + OFF_B + (uint32_t)buf*B_BUF;
    #pragma unroll
    for (int i = 0; i < 4; i++) {
        int w = tid + i*256;             // 0..1023
        int n = w >> 2, c16 = w & 3;
        uint32_t dst = base + (uint32_t)n*B_STR + c16*16;
        CPA16(dst, g + (size_t)ch*B_GCH + (size_t)w*16);
    }
}

// ---------------- kP: convert weights to fp16 packed chunk layout -----------
__global__ void __launch_bounds__(256) kP(const float* __restrict__ W2,
                                          const float* __restrict__ W3) {
    int k = blockIdx.x;   // GEMM K
    int n = threadIdx.x;  // GEMM N
    int ch = k >> 5, kk = k & 31;
    size_t pos = (size_t)ch*B_GCH + (size_t)n*64 + (size_t)kk*2;
    *(unsigned short*)(d_W2f + pos) = __half_as_ushort(__float2half_rn(W2[k*CP_ + n]));
    *(unsigned short*)(d_W3f + pos) = __half_as_ushort(__float2half_rn(W3[k*CP_ + n]));
}

// ---------------- kA: per-(b,v) stats + init --------------------------------
__global__ void __launch_bounds__(256) kA(const float* __restrict__ xyz,
                                          const float* __restrict__ masks) {
    int bv = blockIdx.x;
    int b  = bv >> 2;
    int tid = threadIdx.x;

    float s0=0.f, s1=0.f, s2=0.f, cnt=0.f;
    float mx0=-FLT_MAX, mx1=-FLT_MAX, mx2=-FLT_MAX;
    float mn0= FLT_MAX, mn1= FLT_MAX, mn2= FLT_MAX;

    const float* mrow = masks + (size_t)bv*N_;
    const float* x0r  = xyz + (size_t)(b*3+0)*N_;
    const float* x1r  = xyz + (size_t)(b*3+1)*N_;
    const float* x2r  = xyz + (size_t)(b*3+2)*N_;

    for (int n = tid; n < N_; n += 256) {
        float m = mrow[n];
        float a = x0r[n]*m, c = x1r[n]*m, e = x2r[n]*m;
        s0 += a; s1 += c; s2 += e; cnt += m;
        mx0 = fmaxf(mx0,a); mx1 = fmaxf(mx1,c); mx2 = fmaxf(mx2,e);
        mn0 = fminf(mn0,a); mn1 = fminf(mn1,c); mn2 = fminf(mn2,e);
    }
    __shared__ float rs[4][256];
    __shared__ float rx[3][256];
    __shared__ float rn[3][256];
    rs[0][tid]=s0; rs[1][tid]=s1; rs[2][tid]=s2; rs[3][tid]=cnt;
    rx[0][tid]=mx0; rx[1][tid]=mx1; rx[2][tid]=mx2;
    rn[0][tid]=mn0; rn[1][tid]=mn1; rn[2][tid]=mn2;
    __syncthreads();
    for (int s = 128; s > 0; s >>= 1) {
        if (tid < s) {
            #pragma unroll
            for (int q = 0; q < 4; q++) rs[q][tid] += rs[q][tid+s];
            #pragma unroll
            for (int q = 0; q < 3; q++) {
                rx[q][tid] = fmaxf(rx[q][tid], rx[q][tid+s]);
                rn[q][tid] = fminf(rn[q][tid], rn[q][tid+s]);
            }
        }
        __syncthreads();
    }
    if (tid == 0) {
        float valid = fmaxf(rs[3][0], 1.f);
        d_center[bv*3+0] = rs[0][0]/valid;
        d_center[bv*3+1] = rs[1][0]/valid;
        d_center[bv*3+2] = rs[2][0]/valid;
        float diam = fmaxf(fmaxf(rx[0][0]-rn[0][0], rx[1][0]-rn[1][0]),
                           rx[2][0]-rn[2][0]);
        if (diam == 0.f) diam = 1.f;
        d_invdiam[bv] = 1.f/diam;
        d_denom[bv]   = 0.f;
    }
    d_gmax[bv*CP_ + tid] = -FLT_MAX;
}

// ---------------- kB: stage1+LN1+ReLU -> HMMA(W2) -> LN2 -> local + gmax ----
__global__ void __launch_bounds__(256, 2) kB(const float* __restrict__ xyz,
    const float* __restrict__ W1, const float* __restrict__ b1,
    const float* __restrict__ g1, const float* __restrict__ be1,
    const float* __restrict__ b2, const float* __restrict__ g2,
    const float* __restrict__ be2)
{
    extern __shared__ unsigned char ds[];
    __shared__ float w1s[3*CP_];
    __shared__ float b1s[CP_], g1s[CP_], e1s[CP_], b2s[CP_], g2s[CP_], e2s[CP_];
    __shared__ float srS[TM_][4], srQ[TM_][4];
    __shared__ float sMean[TM_], sRstd[TM_];

    int tile = blockIdx.x;
    int bv = tile >> 8;
    int b  = bv >> 2;
    int tid = threadIdx.x, lane = tid & 31, wid = tid >> 5;
    uint32_t su = sm2u(ds);

    // B chunk 0/1 prefetch first (overlaps all of stage-1)
    prefetchB(su, 0, 0, d_W2f, tid); CPCOMMIT();
    prefetchB(su, 1, 1, d_W2f, tid); CPCOMMIT();

    for (int i = tid; i < 3*CP_; i += 256) w1s[i] = W1[i];
    b1s[tid]=b1[tid]; g1s[tid]=g1[tid]; e1s[tid]=be1[tid];
    b2s[tid]=b2[tid]; g2s[tid]=g2[tid]; e2s[tid]=be2[tid];

    int p = tid >> 2, sub = tid & 3, c0 = sub*64;
    float idm = d_invdiam[bv];
    int n = (tile & 255) * TM_ + p;
    float x0 = (xyz[(size_t)(b*3+0)*N_ + n] - d_center[bv*3+0]) * idm;
    float x1 = (xyz[(size_t)(b*3+1)*N_ + n] - d_center[bv*3+1]) * idm;
    float x2 = (xyz[(size_t)(b*3+2)*N_ + n] - d_center[bv*3+2]) * idm;
    __syncthreads();

    // LN1 stats over this thread's 64 channels
    float sum = 0.f, sq = 0.f;
    #pragma unroll 4
    for (int c = c0; c < c0+64; c++) {
        float y = b1s[c] + x0*w1s[c] + x1*w1s[CP_+c] + x2*w1s[2*CP_+c];
        sum += y; sq += y*y;
    }
    srS[p][sub] = sum; srQ[p][sub] = sq;
    __syncthreads();
    float mean = (srS[p][0]+srS[p][1]+srS[p][2]+srS[p][3]) * (1.f/CP_);
    float var  = (srQ[p][0]+srQ[p][1]+srQ[p][2]+srQ[p][3]) * (1.f/CP_) - mean*mean;
    float rstd = rsqrtf(var + 1e-5f);

    // recompute, LN+ReLU, fp16, write A rows to smem
    #pragma unroll 8
    for (int i = 0; i < 32; i++) {
        int c = c0 + 2*i;
        float y0 = b1s[c]   + x0*w1s[c]   + x1*w1s[CP_+c]   + x2*w1s[2*CP_+c];
        float y1 = b1s[c+1] + x0*w1s[c+1] + x1*w1s[CP_+c+1] + x2*w1s[2*CP_+c+1];
        y0 = fmaxf((y0-mean)*rstd*g1s[c]   + e1s[c],   0.f);
        y1 = fmaxf((y1-mean)*rstd*g1s[c+1] + e1s[c+1], 0.f);
        *(uint32_t*)(ds + (size_t)p*A_STR + c*2) = pack2h(y0, y1);
    }

    // ---- HMMA mainloop: 8 K32 chunks, triple-buffered B, 1 sync/iter ----
    int mt0 = (wid >> 2) * 16;
    int nb  = (wid & 3) * 64;
    uint32_t aoff0 = (uint32_t)(mt0 + (lane&7) + ((lane>>3)&1)*8)*A_STR + (lane>>4)*16;
    uint32_t aoff1 = aoff0 + 32u*A_STR;
    uint32_t boff  = (uint32_t)(nb + (lane&7) + (lane>>4)*8)*B_STR + ((lane>>3)&1)*16;

    float dA[8][4] = {}, dB[8][4] = {};
    #pragma unroll 1
    for (int ch = 0; ch < 8; ch++) {
        CPWAIT1();
        __syncthreads();
        if (ch < 6) prefetchB(su, (ch+2)%3, ch+2, d_W2f, tid);
        CPCOMMIT();
        uint32_t bb = su + OFF_B + (uint32_t)(ch%3)*B_BUF;
        #pragma unroll
        for (int kb = 0; kb < 2; kb++) {
            uint32_t kA = (uint32_t)(ch*64 + kb*32);
            uint32_t ah[4], ah2[4];
            LDSM4(ah,  su + aoff0 + kA);
            LDSM4(ah2, su + aoff1 + kA);
            #pragma unroll
            for (int nt = 0; nt < 4; nt++) {
                uint32_t bh[4];
                LDSM4(bh, bb + boff + (uint32_t)(nt*16*B_STR) + kb*32);
                MMAOP(dA[2*nt],   ah,  bh[0], bh[1]);
                MMAOP(dA[2*nt+1], ah,  bh[2], bh[3]);
                MMAOP(dB[2*nt],   ah2, bh[0], bh[1]);
                MMAOP(dB[2*nt+1], ah2, bh[2], bh[3]);
            }
        }
    }
    __syncthreads();

    // store D frags to smem (reuse A+B region), fp32 [64][264]
    {
        float* Db = (float*)ds;
        int r = lane >> 2, q = (lane & 3)*2;
        #pragma unroll
        for (int nt = 0; nt < 8; nt++) {
            int col = nb + nt*8 + q;
            Db[(mt0+r)*D_STR + col]         = dA[nt][0];
            Db[(mt0+r)*D_STR + col + 1]     = dA[nt][1];
            Db[(mt0+r+8)*D_STR + col]       = dA[nt][2];
            Db[(mt0+r+8)*D_STR + col +1]    = dA[nt][3];
            Db[(mt0+32+r)*D_STR + col]      = dB[nt][0];
            Db[(mt0+32+r)*D_STR + col + 1]  = dB[nt][1];
            Db[(mt0+32+r+8)*D_STR + col]    = dB[nt][2];
            Db[(mt0+32+r+8)*D_STR + col +1] = dB[nt][3];
        }
    }
    __syncthreads();

    // LN2 over D
    const float* Db = (const float*)ds;
    sum = 0.f; sq = 0.f;
    #pragma unroll 4
    for (int c = c0; c < c0+64; c++) {
        float v = Db[p*D_STR + c] + b2s[c];
        sum += v; sq += v*v;
    }
    srS[p][sub] = sum; srQ[p][sub] = sq;
    __syncthreads();
    mean = (srS[p][0]+srS[p][1]+srS[p][2]+srS[p][3]) * (1.f/CP_);
    var  = (srQ[p][0]+srQ[p][1]+srQ[p][2]+srQ[p][3]) * (1.f/CP_) - mean*mean;
    rstd = rsqrtf(var + 1e-5f);
    if (sub == 0) { sMean[p] = mean; sRstd[p] = rstd; }

    // normalize + pack local (no atomics)
    unsigned char* lw = d_localA + (size_t)tile*A_IMG;
    #pragma unroll 8
    for (int i = 0; i < 32; i++) {
        int c = c0 + 2*i;
        float lv0 = (Db[p*D_STR + c]   + b2s[c]  -mean)*rstd*g2s[c]   + e2s[c];
        float lv1 = (Db[p*D_STR + c+1] + b2s[c+1]-mean)*rstd*g2s[c+1] + e2s[c+1];
        *(uint32_t*)(lw + (size_t)p*A_STR + c*2) = pack2h(lv0, lv1);
    }
    __syncthreads();

    // column-max pass: thread = column, 64 rows; one global atomic
    {
        int c = tid;
        float gc = g2s[c], ec = e2s[c], bc = b2s[c];
        float mx = -FLT_MAX;
        #pragma unroll 4
        for (int pp = 0; pp < TM_; pp++) {
            float lv = (Db[pp*D_STR + c] + bc - sMean[pp])*sRstd[pp]*gc + ec;
            mx = fmaxf(mx, lv);
        }
        atomicMaxFloat(&d_gmax[bv*CP_ + c], mx);
    }
}

// ---------------- kC: gpart = global_xyz @ W3[256:512] + b3 -----------------
__global__ void __launch_bounds__(256) kC(const float* __restrict__ W3,
                                          const float* __restrict__ b3) {
    int bv = blockIdx.x;
    int c  = threadIdx.x;
    __shared__ float sg[CP_];
    sg[c] = d_gmax[bv*CP_ + c];
    __syncthreads();
    float acc = b3[c];
    const float* w = W3 + (size_t)256*CP_ + c;
    #pragma unroll 8
    for (int k = 0; k < CP_; k++) acc += sg[k] * w[(size_t)k*CP_];
    d_gpart[bv*CP_ + c] = acc;
}

// ---------------- kD: HMMA(W3-top) + LN3 + ReLU + W4 -> weights -------------
__global__ void __launch_bounds__(256, 2) kD(const float* __restrict__ masks,
    const float* __restrict__ g3, const float* __restrict__ be3,
    const float* __restrict__ W4)
{
    extern __shared__ unsigned char ds[];
    __shared__ float sG3[CP_], sE3[CP_], sW4[CP_], sGp[CP_];
    __shared__ float srS[TM_][4], srQ[TM_][4];
    __shared__ float sw[TM_];

    int tile = blockIdx.x;
    int bv = tile >> 8;
    int n0g = (tile & 255) * TM_;
    int tid = threadIdx.x, lane = tid & 31, wid = tid >> 5;
    uint32_t su = sm2u(ds);

    // group 0: A image (33KB) + B chunk 0 ; group 1: B chunk 1
    {
        const unsigned char* src = d_localA + (size_t)tile*A_IMG;
        for (int i = tid; i < A_IMG/16; i += 256)
            CPA16(su + (uint32_t)i*16, src + (size_t)i*16);
    }
    prefetchB(su, 0, 0, d_W3f, tid); CPCOMMIT();
    prefetchB(su, 1, 1, d_W3f, tid); CPCOMMIT();

    sG3[tid] = g3[tid]; sE3[tid] = be3[tid]; sW4[tid] = W4[tid];
    sGp[tid] = d_gpart[bv*CP_ + tid];

    int mt0 = (wid >> 2) * 16;
    int nb  = (wid & 3) * 64;
    uint32_t aoff0 = (uint32_t)(mt0 + (lane&7) + ((lane>>3)&1)*8)*A_STR + (lane>>4)*16;
    uint32_t aoff1 = aoff0 + 32u*A_STR;
    uint32_t boff  = (uint32_t)(nb + (lane&7) + (lane>>4)*8)*B_STR + ((lane>>3)&1)*16;

    float dA[8][4] = {}, dB[8][4] = {};
    #pragma unroll 1
    for (int ch = 0; ch < 8; ch++) {
        CPWAIT1();
        __syncthreads();
        if (ch < 6) prefetchB(su, (ch+2)%3, ch+2, d_W3f, tid);
        CPCOMMIT();
        uint32_t bb = su + OFF_B + (uint32_t)(ch%3)*B_BUF;
        #pragma unroll
        for (int kb = 0; kb < 2; kb++) {
            uint32_t kA = (uint32_t)(ch*64 + kb*32);
            uint32_t ah[4], ah2[4];
            LDSM4(ah,  su + aoff0 + kA);
            LDSM4(ah2, su + aoff1 + kA);
            #pragma unroll
            for (int nt = 0; nt < 4; nt++) {
                uint32_t bh[4];
                LDSM4(bh, bb + boff + (uint32_t)(nt*16*B_STR) + kb*32);
                MMAOP(dA[2*nt],   ah,  bh[0], bh[1]);
                MMAOP(dA[2*nt+1], ah,  bh[2], bh[3]);
                MMAOP(dB[2*nt],   ah2, bh[0], bh[1]);
                MMAOP(dB[2*nt+1], ah2, bh[2], bh[3]);
            }
        }
    }
    __syncthreads();

    {
        float* Dbw = (float*)ds;
        int r = lane >> 2, q = (lane & 3)*2;
        #pragma unroll
        for (int nt = 0; nt < 8; nt++) {
            int col = nb + nt*8 + q;
            Dbw[(mt0+r)*D_STR + col]         = dA[nt][0];
            Dbw[(mt0+r)*D_STR + col + 1]     = dA[nt][1];
            Dbw[(mt0+r+8)*D_STR + col]       = dA[nt][2];
            Dbw[(mt0+r+8)*D_STR + col +1]    = dA[nt][3];
            Dbw[(mt0+32+r)*D_STR + col]      = dB[nt][0];
            Dbw[(mt0+32+r)*D_STR + col + 1]  = dB[nt][1];
            Dbw[(mt0+32+r+8)*D_STR + col]    = dB[nt][2];
            Dbw[(mt0+32+r+8)*D_STR + col +1] = dB[nt][3];
        }
    }
    __syncthreads();

    const float* Db = (const float*)ds;
    int p = tid >> 2, sub = tid & 3, c0 = sub*64;
    float sum = 0.f, sq = 0.f;
    #pragma unroll 4
    for (int c = c0; c < c0+64; c++) {
        float v = Db[p*D_STR + c] + sGp[c];
        sum += v; sq += v*v;
    }
    srS[p][sub] = sum; srQ[p][sub] = sq;
    __syncthreads();
    float mean = (srS[p][0]+srS[p][1]+srS[p][2]+srS[p][3]) * (1.f/CP_);
    float var  = (srQ[p][0]+srQ[p][1]+srQ[p][2]+srQ[p][3]) * (1.f/CP_) - mean*mean;
    float rstd = rsqrtf(var + 1e-5f);

    float dot = 0.f;
    #pragma unroll 4
    for (int c = c0; c < c0+64; c++) {
        float v = Db[p*D_STR + c] + sGp[c];
        float hv = fmaxf((v-mean)*rstd*sG3[c] + sE3[c], 0.f);
        dot += hv * sW4[c];
    }
    __syncthreads();
    srS[p][sub] = dot;
    __syncthreads();
    if (sub == 0) {
        float dt = srS[p][0]+srS[p][1]+srS[p][2]+srS[p][3];
        int n = n0g + p;
        float m = masks[(size_t)bv*N_ + n];
        float w = 2.f * m / (1.f + expf(-dt));
        d_mw[(size_t)bv*N_ + n] = w;
        sw[p] = w;
    }
    __syncthreads();
    if (tid == 0) {
        float s = 0.f;
        #pragma unroll 8
        for (int i = 0; i < TM_; i++) s += sw[i];
        atomicAdd(&d_denom[bv], s);
    }
}

// ---------------- kE: weighted pooling + epilogue ---------------------------
__global__ void __launch_bounds__(256) kE(const float* __restrict__ feats,
                                          float* __restrict__ out) {
    int blk = blockIdx.x;        // b*CP_ + c
    int b = blk >> 8;
    int c = blk & 255;
    int tid = threadIdx.x;

    const float* f   = feats + (size_t)(b*CP_ + c)*N_;
    const float* mw0 = d_mw + (size_t)(b*4+0)*N_;
    const float* mw1 = d_mw + (size_t)(b*4+1)*N_;
    const float* mw2 = d_mw + (size_t)(b*4+2)*N_;
    const float* mw3 = d_mw + (size_t)(b*4+3)*N_;

    float a0=0.f, a1=0.f, a2=0.f, a3=0.f;
    for (int n = tid; n < N_; n += 256) {
        float fv = f[n];
        a0 += fv*mw0[n]; a1 += fv*mw1[n]; a2 += fv*mw2[n]; a3 += fv*mw3[n];
    }
    #pragma unroll
    for (int o = 16; o > 0; o >>= 1) {
        a0 += __shfl_xor_sync(0xffffffffu, a0, o);
        a1 += __shfl_xor_sync(0xffffffffu, a1, o);
        a2 += __shfl_xor_sync(0xffffffffu, a2, o);
        a3 += __shfl_xor_sync(0xffffffffu, a3, o);
    }
    __shared__ float sr[4][8];
    int lane = tid & 31, warp = tid >> 5;
    if (lane == 0) { sr[0][warp]=a0; sr[1][warp]=a1; sr[2][warp]=a2; sr[3][warp]=a3; }
    __syncthreads();
    if (tid < 4) {
        float ps = 0.f;
        #pragma unroll
        for (int w = 0; w < 8; w++) ps += sr[tid][w];
        int bvv = b*4 + tid;
        float den = fmaxf(d_denom[bvv], 1e-8f);
        out[(size_t)bvv*CP_ + c] = ps/den + d_gmax[bvv*CP_ + c];
    }
}

// ---------------- launch ----------------------------------------------------
extern "C" void kernel_launch(void* const* d_in, const int* in_sizes, int n_in,
                              void* d_out, int out_size) {
    const float* xyz = (const float*)d_in[0];
    const float* pf  = (const float*)d_in[1];
    const float* pm  = (const float*)d_in[2];
    const float* W1  = (const float*)d_in[3];
    const float* b1  = (const float*)d_in[4];
    const float* g1  = (const float*)d_in[5];
    const float* be1 = (const float*)d_in[6];
    const float* W2  = (const float*)d_in[7];
    const float* b2  = (const float*)d_in[8];
    const float* g2  = (const float*)d_in[9];
    const float* be2 = (const float*)d_in[10];
    const float* W3  = (const float*)d_in[11];
    const float* b3  = (const float*)d_in[12];
    const float* g3  = (const float*)d_in[13];
    const float* be3 = (const float*)d_in[14];
    const float* W4  = (const float*)d_in[15];
    float* out = (float*)d_out;

    static int configured = 0;
    if (!configured) {
        cudaFuncSetAttribute(kB, cudaFuncAttributeMaxDynamicSharedMemorySize, DYN_SMEM);
        cudaFuncSetAttribute(kD, cudaFuncAttributeMaxDynamicSharedMemorySize, DYN_SMEM);
        configured = 1;
    }

    kP<<<CP_, 256>>>(W2, W3);
    kA<<<BV_, 256>>>(xyz, pm);
    kB<<<NT2_, 256, DYN_SMEM>>>(xyz, W1, b1, g1, be1, b2, g2, be2);
    kC<<<BV_, 256>>>(W3, b3);
    kD<<<NT2_, 256, DYN_SMEM>>>(pm, g3, be3, W4);
    kE<<<B_*CP_, 256>>>(pf, out);
}

// round 9
// speedup vs baseline: 3.0656x; 1.5721x over previous
#include <cuda_runtime.h>
#include <cuda_fp16.h>
#include <math.h>
#include <float.h>
#include <stdint.h>

#define B_   8
#define V_   4
#define N_   16384
#define CP_  256
#define BV_  (B_*V_)            // 32
#define TM_  64                 // points per CTA tile
#define NT2_ (N_*BV_/TM_)       // 8192 tiles
#define A_STR 528               // A row stride bytes (256 fp16 + 16 pad)
#define B_STR 80                // B row stride bytes (32 fp16 + 16 pad)
#define A_IMG    33792          // 64*528
#define OFF_B    33792
#define B_BUF    20480          // one K32 chunk: 256 rows x 80B
#define B_GCH    16384          // packed gmem chunk bytes (256*64)
#define DYN_SMEM 95232          // A + 3*B_BUF

// ---------------- device scratch (static; no allocations) -------------------
__device__ float d_center[BV_*3];
__device__ float d_invdiam[BV_];
__device__ __align__(16) float d_gmax[BV_*CP_];
__device__ __align__(16) float d_gpart[BV_*CP_];
__device__ float d_mw[BV_*N_];
__device__ float d_denom[BV_];
__device__ __align__(16) unsigned char d_localA[(size_t)NT2_*A_IMG];  // 277MB
__device__ __align__(16) unsigned char d_W2f[CP_*CP_*2];
__device__ __align__(16) unsigned char d_W3f[CP_*CP_*2];

// ---------------- helpers ---------------------------------------------------
__device__ __forceinline__ uint32_t sm2u(const void* p) {
    uint32_t a;
    asm("{ .reg .u64 t; cvta.to.shared.u64 t, %1; cvt.u32.u64 %0, t; }"
        : "=r"(a) : "l"(p));
    return a;
}
#define LDSM4(r, addr) \
    asm volatile("ldmatrix.sync.aligned.m8n8.x4.shared.b16 {%0,%1,%2,%3}, [%4];" \
        : "=r"((r)[0]), "=r"((r)[1]), "=r"((r)[2]), "=r"((r)[3]) : "r"(addr))
#define MMAOP(d, a, b0, b1) \
    asm volatile("mma.sync.aligned.m16n8k16.row.col.f32.f16.f16.f32 " \
        "{%0,%1,%2,%3}, {%4,%5,%6,%7}, {%8,%9}, {%0,%1,%2,%3};" \
        : "+f"((d)[0]), "+f"((d)[1]), "+f"((d)[2]), "+f"((d)[3]) \
        : "r"((a)[0]), "r"((a)[1]), "r"((a)[2]), "r"((a)[3]), "r"(b0), "r"(b1))
#define CPA16(dst, src) \
    asm volatile("cp.async.cg.shared.global [%0], [%1], 16;" :: "r"(dst), "l"(src))
#define CPCOMMIT() asm volatile("cp.async.commit_group;" ::: "memory")
#define CPWAIT1()  asm volatile("cp.async.wait_group 1;" ::: "memory")

static __device__ __forceinline__ uint32_t pack2h(float v0, float v1) {
    __half h0 = __float2half_rn(v0);
    __half h1 = __float2half_rn(v1);
    return (uint32_t)__half_as_ushort(h0) | ((uint32_t)__half_as_ushort(h1) << 16);
}
__device__ __forceinline__ void atomicMaxFloat(float* addr, float val) {
    if (__float_as_int(val) >= 0) atomicMax((int*)addr, __float_as_int(val));
    else atomicMin((unsigned int*)addr, __float_as_uint(val));
}

__device__ __forceinline__ void prefetchB(uint32_t su, int buf, int ch,
                                          const unsigned char* g, int tid) {
    uint32_t base = su + OFF_B + (uint32_t)buf*B_BUF;
    #pragma unroll
    for (int i = 0; i < 4; i++) {
        int w = tid + i*256;             // 0..1023
        int n = w >> 2, c16 = w & 3;
        uint32_t dst = base + (uint32_t)n*B_STR + c16*16;
        CPA16(dst, g + (size_t)ch*B_GCH + (size_t)w*16);
    }
}

// ---------------- kP: convert weights to fp16 packed chunk layout -----------
__global__ void __launch_bounds__(256) kP(const float* __restrict__ W2,
                                          const float* __restrict__ W3) {
    int k = blockIdx.x;
    int n = threadIdx.x;
    int ch = k >> 5, kk = k & 31;
    size_t pos = (size_t)ch*B_GCH + (size_t)n*64 + (size_t)kk*2;
    *(unsigned short*)(d_W2f + pos) = __half_as_ushort(__float2half_rn(W2[k*CP_ + n]));
    *(unsigned short*)(d_W3f + pos) = __half_as_ushort(__float2half_rn(W3[k*CP_ + n]));
}

// ---------------- kA: per-(b,v) stats + init --------------------------------
__global__ void __launch_bounds__(256) kA(const float* __restrict__ xyz,
                                          const float* __restrict__ masks) {
    int bv = blockIdx.x;
    int b  = bv >> 2;
    int tid = threadIdx.x;

    float s0=0.f, s1=0.f, s2=0.f, cnt=0.f;
    float mx0=-FLT_MAX, mx1=-FLT_MAX, mx2=-FLT_MAX;
    float mn0= FLT_MAX, mn1= FLT_MAX, mn2= FLT_MAX;

    const float* mrow = masks + (size_t)bv*N_;
    const float* x0r  = xyz + (size_t)(b*3+0)*N_;
    const float* x1r  = xyz + (size_t)(b*3+1)*N_;
    const float* x2r  = xyz + (size_t)(b*3+2)*N_;

    for (int n = tid; n < N_; n += 256) {
        float m = mrow[n];
        float a = x0r[n]*m, c = x1r[n]*m, e = x2r[n]*m;
        s0 += a; s1 += c; s2 += e; cnt += m;
        mx0 = fmaxf(mx0,a); mx1 = fmaxf(mx1,c); mx2 = fmaxf(mx2,e);
        mn0 = fminf(mn0,a); mn1 = fminf(mn1,c); mn2 = fminf(mn2,e);
    }
    __shared__ float rs[4][256];
    __shared__ float rx[3][256];
    __shared__ float rn[3][256];
    rs[0][tid]=s0; rs[1][tid]=s1; rs[2][tid]=s2; rs[3][tid]=cnt;
    rx[0][tid]=mx0; rx[1][tid]=mx1; rx[2][tid]=mx2;
    rn[0][tid]=mn0; rn[1][tid]=mn1; rn[2][tid]=mn2;
    __syncthreads();
    for (int s = 128; s > 0; s >>= 1) {
        if (tid < s) {
            #pragma unroll
            for (int q = 0; q < 4; q++) rs[q][tid] += rs[q][tid+s];
            #pragma unroll
            for (int q = 0; q < 3; q++) {
                rx[q][tid] = fmaxf(rx[q][tid], rx[q][tid+s]);
                rn[q][tid] = fminf(rn[q][tid], rn[q][tid+s]);
            }
        }
        __syncthreads();
    }
    if (tid == 0) {
        float valid = fmaxf(rs[3][0], 1.f);
        d_center[bv*3+0] = rs[0][0]/valid;
        d_center[bv*3+1] = rs[1][0]/valid;
        d_center[bv*3+2] = rs[2][0]/valid;
        float diam = fmaxf(fmaxf(rx[0][0]-rn[0][0], rx[1][0]-rn[1][0]),
                           rx[2][0]-rn[2][0]);
        if (diam == 0.f) diam = 1.f;
        d_invdiam[bv] = 1.f/diam;
        d_denom[bv]   = 0.f;
    }
    d_gmax[bv*CP_ + tid] = -FLT_MAX;
}

// ---------------- kB: stage1+LN1+ReLU -> HMMA(W2) -> reg-LN2 -> local + gmax
__global__ void __launch_bounds__(256, 2) kB(const float* __restrict__ xyz,
    const float* __restrict__ W1, const float* __restrict__ b1,
    const float* __restrict__ g1, const float* __restrict__ be1,
    const float* __restrict__ b2, const float* __restrict__ g2,
    const float* __restrict__ be2)
{
    extern __shared__ unsigned char ds[];
    __shared__ float w1s[3*CP_];
    __shared__ float b1s[CP_], g1s[CP_], e1s[CP_], b2s[CP_], g2s[CP_], e2s[CP_];
    __shared__ float srS[TM_][4], srQ[TM_][4];
    __shared__ float sMean[TM_], sRstd[TM_];
    __shared__ float scx[2][CP_];

    int tile = blockIdx.x;
    int bv = tile >> 8;
    int b  = bv >> 2;
    int tid = threadIdx.x, lane = tid & 31, wid = tid >> 5;
    uint32_t su = sm2u(ds);

    prefetchB(su, 0, 0, d_W2f, tid); CPCOMMIT();
    prefetchB(su, 1, 1, d_W2f, tid); CPCOMMIT();

    for (int i = tid; i < 3*CP_; i += 256) w1s[i] = W1[i];
    b1s[tid]=b1[tid]; g1s[tid]=g1[tid]; e1s[tid]=be1[tid];
    b2s[tid]=b2[tid]; g2s[tid]=g2[tid]; e2s[tid]=be2[tid];

    int p = tid >> 2, sub = tid & 3, c0 = sub*64;
    float idm = d_invdiam[bv];
    int n = (tile & 255) * TM_ + p;
    float x0 = (xyz[(size_t)(b*3+0)*N_ + n] - d_center[bv*3+0]) * idm;
    float x1 = (xyz[(size_t)(b*3+1)*N_ + n] - d_center[bv*3+1]) * idm;
    float x2 = (xyz[(size_t)(b*3+2)*N_ + n] - d_center[bv*3+2]) * idm;
    __syncthreads();

    // LN1 stats over this thread's 64 channels
    float sum = 0.f, sq = 0.f;
    #pragma unroll 4
    for (int c = c0; c < c0+64; c++) {
        float y = b1s[c] + x0*w1s[c] + x1*w1s[CP_+c] + x2*w1s[2*CP_+c];
        sum += y; sq += y*y;
    }
    srS[p][sub] = sum; srQ[p][sub] = sq;
    __syncthreads();
    float mean = (srS[p][0]+srS[p][1]+srS[p][2]+srS[p][3]) * (1.f/CP_);
    float var  = (srQ[p][0]+srQ[p][1]+srQ[p][2]+srQ[p][3]) * (1.f/CP_) - mean*mean;
    float rstd = rsqrtf(var + 1e-5f);

    // recompute, LN+ReLU, fp16, write A rows to smem
    #pragma unroll 8
    for (int i = 0; i < 32; i++) {
        int c = c0 + 2*i;
        float y0 = b1s[c]   + x0*w1s[c]   + x1*w1s[CP_+c]   + x2*w1s[2*CP_+c];
        float y1 = b1s[c+1] + x0*w1s[c+1] + x1*w1s[CP_+c+1] + x2*w1s[2*CP_+c+1];
        y0 = fmaxf((y0-mean)*rstd*g1s[c]   + e1s[c],   0.f);
        y1 = fmaxf((y1-mean)*rstd*g1s[c+1] + e1s[c+1], 0.f);
        *(uint32_t*)(ds + (size_t)p*A_STR + c*2) = pack2h(y0, y1);
    }

    // ---- HMMA mainloop: 8 K32 chunks, triple-buffered B, 1 sync/iter ----
    int mt0 = (wid >> 2) * 16;
    int nb  = (wid & 3) * 64;
    uint32_t aoff0 = (uint32_t)(mt0 + (lane&7) + ((lane>>3)&1)*8)*A_STR + (lane>>4)*16;
    uint32_t aoff1 = aoff0 + 32u*A_STR;
    uint32_t boff  = (uint32_t)(nb + (lane&7) + (lane>>4)*8)*B_STR + ((lane>>3)&1)*16;

    float dA[8][4] = {}, dB[8][4] = {};
    #pragma unroll 1
    for (int ch = 0; ch < 8; ch++) {
        CPWAIT1();
        __syncthreads();
        if (ch < 6) prefetchB(su, (ch+2)%3, ch+2, d_W2f, tid);
        CPCOMMIT();
        uint32_t bb = su + OFF_B + (uint32_t)(ch%3)*B_BUF;
        #pragma unroll
        for (int kb = 0; kb < 2; kb++) {
            uint32_t kA = (uint32_t)(ch*64 + kb*32);
            uint32_t ah[4], ah2[4];
            LDSM4(ah,  su + aoff0 + kA);
            LDSM4(ah2, su + aoff1 + kA);
            #pragma unroll
            for (int nt = 0; nt < 4; nt++) {
                uint32_t bh[4];
                LDSM4(bh, bb + boff + (uint32_t)(nt*16*B_STR) + kb*32);
                MMAOP(dA[2*nt],   ah,  bh[0], bh[1]);
                MMAOP(dA[2*nt+1], ah,  bh[2], bh[3]);
                MMAOP(dB[2*nt],   ah2, bh[0], bh[1]);
                MMAOP(dB[2*nt+1], ah2, bh[2], bh[3]);
            }
        }
    }

    // ---- register epilogue: LN2 stats from fragments ----
    int r = lane >> 2, q2 = (lane & 3)*2;
    int rw0 = mt0 + r, rw1 = mt0 + r + 8, rw2 = mt0 + 32 + r, rw3 = mt0 + 40 + r;
    float rs0=0.f,rq0=0.f,rs1=0.f,rq1=0.f,rs2=0.f,rq2=0.f,rs3=0.f,rq3=0.f;
    #pragma unroll
    for (int nt = 0; nt < 8; nt++) {
        int c = nb + nt*8 + q2;
        float bb0 = b2s[c], bb1 = b2s[c+1], v;
        v = dA[nt][0]+bb0; rs0+=v; rq0+=v*v;
        v = dA[nt][1]+bb1; rs0+=v; rq0+=v*v;
        v = dA[nt][2]+bb0; rs1+=v; rq1+=v*v;
        v = dA[nt][3]+bb1; rs1+=v; rq1+=v*v;
        v = dB[nt][0]+bb0; rs2+=v; rq2+=v*v;
        v = dB[nt][1]+bb1; rs2+=v; rq2+=v*v;
        v = dB[nt][2]+bb0; rs3+=v; rq3+=v*v;
        v = dB[nt][3]+bb1; rs3+=v; rq3+=v*v;
    }
    rs0 += __shfl_xor_sync(~0u, rs0, 1); rs0 += __shfl_xor_sync(~0u, rs0, 2);
    rq0 += __shfl_xor_sync(~0u, rq0, 1); rq0 += __shfl_xor_sync(~0u, rq0, 2);
    rs1 += __shfl_xor_sync(~0u, rs1, 1); rs1 += __shfl_xor_sync(~0u, rs1, 2);
    rq1 += __shfl_xor_sync(~0u, rq1, 1); rq1 += __shfl_xor_sync(~0u, rq1, 2);
    rs2 += __shfl_xor_sync(~0u, rs2, 1); rs2 += __shfl_xor_sync(~0u, rs2, 2);
    rq2 += __shfl_xor_sync(~0u, rq2, 1); rq2 += __shfl_xor_sync(~0u, rq2, 2);
    rs3 += __shfl_xor_sync(~0u, rs3, 1); rs3 += __shfl_xor_sync(~0u, rs3, 2);
    rq3 += __shfl_xor_sync(~0u, rq3, 1); rq3 += __shfl_xor_sync(~0u, rq3, 2);
    __syncthreads();   // srS reuse safe-guard
    if ((lane & 3) == 0) {
        int w4 = wid & 3;
        srS[rw0][w4]=rs0; srQ[rw0][w4]=rq0;
        srS[rw1][w4]=rs1; srQ[rw1][w4]=rq1;
        srS[rw2][w4]=rs2; srQ[rw2][w4]=rq2;
        srS[rw3][w4]=rs3; srQ[rw3][w4]=rq3;
    }
    __syncthreads();
    if (tid < TM_) {
        float S = srS[tid][0]+srS[tid][1]+srS[tid][2]+srS[tid][3];
        float Q = srQ[tid][0]+srQ[tid][1]+srQ[tid][2]+srQ[tid][3];
        float mn = S * (1.f/CP_);
        sMean[tid] = mn;
        sRstd[tid] = rsqrtf(Q*(1.f/CP_) - mn*mn + 1e-5f);
    }
    __syncthreads();

    // normalize in registers, pack to local, column max
    float m0 = sMean[rw0], r0 = sRstd[rw0];
    float m1 = sMean[rw1], r1 = sRstd[rw1];
    float m2 = sMean[rw2], r2 = sRstd[rw2];
    float m3 = sMean[rw3], r3 = sRstd[rw3];
    unsigned char* lw = d_localA + (size_t)tile*A_IMG;
    float cm[16];
    #pragma unroll
    for (int nt = 0; nt < 8; nt++) {
        int c = nb + nt*8 + q2;
        float bb0=b2s[c], bb1=b2s[c+1], g0=g2s[c], g1=g2s[c+1], e0=e2s[c], e1=e2s[c+1];
        float v00 = (dA[nt][0]+bb0-m0)*r0*g0+e0, v01 = (dA[nt][1]+bb1-m0)*r0*g1+e1;
        float v10 = (dA[nt][2]+bb0-m1)*r1*g0+e0, v11 = (dA[nt][3]+bb1-m1)*r1*g1+e1;
        float v20 = (dB[nt][0]+bb0-m2)*r2*g0+e0, v21 = (dB[nt][1]+bb1-m2)*r2*g1+e1;
        float v30 = (dB[nt][2]+bb0-m3)*r3*g0+e0, v31 = (dB[nt][3]+bb1-m3)*r3*g1+e1;
        *(uint32_t*)(lw + (size_t)rw0*A_STR + c*2) = pack2h(v00, v01);
        *(uint32_t*)(lw + (size_t)rw1*A_STR + c*2) = pack2h(v10, v11);
        *(uint32_t*)(lw + (size_t)rw2*A_STR + c*2) = pack2h(v20, v21);
        *(uint32_t*)(lw + (size_t)rw3*A_STR + c*2) = pack2h(v30, v31);
        cm[2*nt]   = fmaxf(fmaxf(v00, v10), fmaxf(v20, v30));
        cm[2*nt+1] = fmaxf(fmaxf(v01, v11), fmaxf(v21, v31));
    }
    #pragma unroll
    for (int i = 0; i < 16; i++) {
        cm[i] = fmaxf(cm[i], __shfl_xor_sync(~0u, cm[i], 4));
        cm[i] = fmaxf(cm[i], __shfl_xor_sync(~0u, cm[i], 8));
        cm[i] = fmaxf(cm[i], __shfl_xor_sync(~0u, cm[i], 16));
    }
    if ((lane >> 2) == 0) {
        int grp = wid >> 2;
        #pragma unroll
        for (int nt = 0; nt < 8; nt++) {
            int c = nb + nt*8 + q2;
            scx[grp][c]   = cm[2*nt];
            scx[grp][c+1] = cm[2*nt+1];
        }
    }
    __syncthreads();
    atomicMaxFloat(&d_gmax[bv*CP_ + tid], fmaxf(scx[0][tid], scx[1][tid]));
}

// ---------------- kC: gpart = global_xyz @ W3[256:512] + b3 -----------------
__global__ void __launch_bounds__(256) kC(const float* __restrict__ W3,
                                          const float* __restrict__ b3) {
    int bv = blockIdx.x;
    int c  = threadIdx.x;
    __shared__ float sg[CP_];
    __shared__ float ws[32*CP_];
    sg[c] = d_gmax[bv*CP_ + c];
    float acc = b3[c];
    for (int ko = 0; ko < 8; ko++) {
        __syncthreads();
        const float4* src = (const float4*)(W3 + (size_t)(256 + ko*32)*CP_);
        for (int i = c; i < 32*CP_/4; i += 256) ((float4*)ws)[i] = src[i];
        __syncthreads();
        #pragma unroll 8
        for (int kk = 0; kk < 32; kk++)
            acc += sg[ko*32+kk] * ws[kk*CP_ + c];
    }
    d_gpart[bv*CP_ + c] = acc;
}

// ---------------- kD: HMMA(W3-top) + reg-LN3 + ReLU + W4 -> weights ---------
__global__ void __launch_bounds__(256, 2) kD(const float* __restrict__ masks,
    const float* __restrict__ g3, const float* __restrict__ be3,
    const float* __restrict__ W4)
{
    extern __shared__ unsigned char ds[];
    __shared__ float sG3[CP_], sE3[CP_], sW4[CP_], sGp[CP_];
    __shared__ float srS[TM_][4], srQ[TM_][4];
    __shared__ float sMean[TM_], sRstd[TM_];
    __shared__ float sw[TM_];

    int tile = blockIdx.x;
    int bv = tile >> 8;
    int n0g = (tile & 255) * TM_;
    int tid = threadIdx.x, lane = tid & 31, wid = tid >> 5;
    uint32_t su = sm2u(ds);

    {
        const unsigned char* src = d_localA + (size_t)tile*A_IMG;
        for (int i = tid; i < A_IMG/16; i += 256)
            CPA16(su + (uint32_t)i*16, src + (size_t)i*16);
    }
    prefetchB(su, 0, 0, d_W3f, tid); CPCOMMIT();
    prefetchB(su, 1, 1, d_W3f, tid); CPCOMMIT();

    sG3[tid] = g3[tid]; sE3[tid] = be3[tid]; sW4[tid] = W4[tid];
    sGp[tid] = d_gpart[bv*CP_ + tid];

    int mt0 = (wid >> 2) * 16;
    int nb  = (wid & 3) * 64;
    uint32_t aoff0 = (uint32_t)(mt0 + (lane&7) + ((lane>>3)&1)*8)*A_STR + (lane>>4)*16;
    uint32_t aoff1 = aoff0 + 32u*A_STR;
    uint32_t boff  = (uint32_t)(nb + (lane&7) + (lane>>4)*8)*B_STR + ((lane>>3)&1)*16;

    float dA[8][4] = {}, dB[8][4] = {};
    #pragma unroll 1
    for (int ch = 0; ch < 8; ch++) {
        CPWAIT1();
        __syncthreads();
        if (ch < 6) prefetchB(su, (ch+2)%3, ch+2, d_W3f, tid);
        CPCOMMIT();
        uint32_t bb = su + OFF_B + (uint32_t)(ch%3)*B_BUF;
        #pragma unroll
        for (int kb = 0; kb < 2; kb++) {
            uint32_t kA = (uint32_t)(ch*64 + kb*32);
            uint32_t ah[4], ah2[4];
            LDSM4(ah,  su + aoff0 + kA);
            LDSM4(ah2, su + aoff1 + kA);
            #pragma unroll
            for (int nt = 0; nt < 4; nt++) {
                uint32_t bh[4];
                LDSM4(bh, bb + boff + (uint32_t)(nt*16*B_STR) + kb*32);
                MMAOP(dA[2*nt],   ah,  bh[0], bh[1]);
                MMAOP(dA[2*nt+1], ah,  bh[2], bh[3]);
                MMAOP(dB[2*nt],   ah2, bh[0], bh[1]);
                MMAOP(dB[2*nt+1], ah2, bh[2], bh[3]);
            }
        }
    }

    // ---- register epilogue: LN3 stats ----
    int r = lane >> 2, q2 = (lane & 3)*2;
    int rw0 = mt0 + r, rw1 = mt0 + r + 8, rw2 = mt0 + 32 + r, rw3 = mt0 + 40 + r;
    float rs0=0.f,rq0=0.f,rs1=0.f,rq1=0.f,rs2=0.f,rq2=0.f,rs3=0.f,rq3=0.f;
    #pragma unroll
    for (int nt = 0; nt < 8; nt++) {
        int c = nb + nt*8 + q2;
        float gp0 = sGp[c], gp1 = sGp[c+1], v;
        v = dA[nt][0]+gp0; rs0+=v; rq0+=v*v;
        v = dA[nt][1]+gp1; rs0+=v; rq0+=v*v;
        v = dA[nt][2]+gp0; rs1+=v; rq1+=v*v;
        v = dA[nt][3]+gp1; rs1+=v; rq1+=v*v;
        v = dB[nt][0]+gp0; rs2+=v; rq2+=v*v;
        v = dB[nt][1]+gp1; rs2+=v; rq2+=v*v;
        v = dB[nt][2]+gp0; rs3+=v; rq3+=v*v;
        v = dB[nt][3]+gp1; rs3+=v; rq3+=v*v;
    }
    rs0 += __shfl_xor_sync(~0u, rs0, 1); rs0 += __shfl_xor_sync(~0u, rs0, 2);
    rq0 += __shfl_xor_sync(~0u, rq0, 1); rq0 += __shfl_xor_sync(~0u, rq0, 2);
    rs1 += __shfl_xor_sync(~0u, rs1, 1); rs1 += __shfl_xor_sync(~0u, rs1, 2);
    rq1 += __shfl_xor_sync(~0u, rq1, 1); rq1 += __shfl_xor_sync(~0u, rq1, 2);
    rs2 += __shfl_xor_sync(~0u, rs2, 1); rs2 += __shfl_xor_sync(~0u, rs2, 2);
    rq2 += __shfl_xor_sync(~0u, rq2, 1); rq2 += __shfl_xor_sync(~0u, rq2, 2);
    rs3 += __shfl_xor_sync(~0u, rs3, 1); rs3 += __shfl_xor_sync(~0u, rs3, 2);
    rq3 += __shfl_xor_sync(~0u, rq3, 1); rq3 += __shfl_xor_sync(~0u, rq3, 2);
    if ((lane & 3) == 0) {
        int w4 = wid & 3;
        srS[rw0][w4]=rs0; srQ[rw0][w4]=rq0;
        srS[rw1][w4]=rs1; srQ[rw1][w4]=rq1;
        srS[rw2][w4]=rs2; srQ[rw2][w4]=rq2;
        srS[rw3][w4]=rs3; srQ[rw3][w4]=rq3;
    }
    __syncthreads();
    if (tid < TM_) {
        float S = srS[tid][0]+srS[tid][1]+srS[tid][2]+srS[tid][3];
        float Q = srQ[tid][0]+srQ[tid][1]+srQ[tid][2]+srQ[tid][3];
        float mn = S * (1.f/CP_);
        sMean[tid] = mn;
        sRstd[tid] = rsqrtf(Q*(1.f/CP_) - mn*mn + 1e-5f);
    }
    __syncthreads();

    // normalize + ReLU + W4 dot in registers
    float m0 = sMean[rw0], r0 = sRstd[rw0];
    float m1 = sMean[rw1], r1 = sRstd[rw1];
    float m2 = sMean[rw2], r2 = sRstd[rw2];
    float m3 = sMean[rw3], r3 = sRstd[rw3];
    float d0=0.f, d1=0.f, d2=0.f, d3=0.f;
    #pragma unroll
    for (int nt = 0; nt < 8; nt++) {
        int c = nb + nt*8 + q2;
        float gp0=sGp[c], gp1=sGp[c+1], g0=sG3[c], g1=sG3[c+1];
        float e0=sE3[c], e1=sE3[c+1], w0=sW4[c], w1=sW4[c+1];
        d0 += fmaxf((dA[nt][0]+gp0-m0)*r0*g0+e0, 0.f)*w0
            + fmaxf((dA[nt][1]+gp1-m0)*r0*g1+e1, 0.f)*w1;
        d1 += fmaxf((dA[nt][2]+gp0-m1)*r1*g0+e0, 0.f)*w0
            + fmaxf((dA[nt][3]+gp1-m1)*r1*g1+e1, 0.f)*w1;
        d2 += fmaxf((dB[nt][0]+gp0-m2)*r2*g0+e0, 0.f)*w0
            + fmaxf((dB[nt][1]+gp1-m2)*r2*g1+e1, 0.f)*w1;
        d3 += fmaxf((dB[nt][2]+gp0-m3)*r3*g0+e0, 0.f)*w0
            + fmaxf((dB[nt][3]+gp1-m3)*r3*g1+e1, 0.f)*w1;
    }
    d0 += __shfl_xor_sync(~0u, d0, 1); d0 += __shfl_xor_sync(~0u, d0, 2);
    d1 += __shfl_xor_sync(~0u, d1, 1); d1 += __shfl_xor_sync(~0u, d1, 2);
    d2 += __shfl_xor_sync(~0u, d2, 1); d2 += __shfl_xor_sync(~0u, d2, 2);
    d3 += __shfl_xor_sync(~0u, d3, 1); d3 += __shfl_xor_sync(~0u, d3, 2);
    __syncthreads();   // srS reuse
    if ((lane & 3) == 0) {
        int w4 = wid & 3;
        srS[rw0][w4]=d0; srS[rw1][w4]=d1; srS[rw2][w4]=d2; srS[rw3][w4]=d3;
    }
    __syncthreads();
    if (tid < TM_) {
        float dt = srS[tid][0]+srS[tid][1]+srS[tid][2]+srS[tid][3];
        int n = n0g + tid;
        float m = masks[(size_t)bv*N_ + n];
        float w = 2.f * m / (1.f + expf(-dt));
        d_mw[(size_t)bv*N_ + n] = w;
        sw[tid] = w;
    }
    __syncthreads();
    if (tid == 0) {
        float s = 0.f;
        #pragma unroll 8
        for (int i = 0; i < TM_; i++) s += sw[i];
        atomicAdd(&d_denom[bv], s);
    }
}

// ---------------- kE: weighted pooling + epilogue ---------------------------
__global__ void __launch_bounds__(256) kE(const float* __restrict__ feats,
                                          float* __restrict__ out) {
    int blk = blockIdx.x;        // b*CP_ + c
    int b = blk >> 8;
    int c = blk & 255;
    int tid = threadIdx.x;

    const float* f   = feats + (size_t)(b*CP_ + c)*N_;
    const float* mw0 = d_mw + (size_t)(b*4+0)*N_;
    const float* mw1 = d_mw + (size_t)(b*4+1)*N_;
    const float* mw2 = d_mw + (size_t)(b*4+2)*N_;
    const float* mw3 = d_mw + (size_t)(b*4+3)*N_;

    float a0=0.f, a1=0.f, a2=0.f, a3=0.f;
    for (int n = tid; n < N_; n += 256) {
        float fv = f[n];
        a0 += fv*mw0[n]; a1 += fv*mw1[n]; a2 += fv*mw2[n]; a3 += fv*mw3[n];
    }
    #pragma unroll
    for (int o = 16; o > 0; o >>= 1) {
        a0 += __shfl_xor_sync(0xffffffffu, a0, o);
        a1 += __shfl_xor_sync(0xffffffffu, a1, o);
        a2 += __shfl_xor_sync(0xffffffffu, a2, o);
        a3 += __shfl_xor_sync(0xffffffffu, a3, o);
    }
    __shared__ float sr[4][8];
    int lane = tid & 31, warp = tid >> 5;
    if (lane == 0) { sr[0][warp]=a0; sr[1][warp]=a1; sr[2][warp]=a2; sr[3][warp]=a3; }
    __syncthreads();
    if (tid < 4) {
        float ps = 0.f;
        #pragma unroll
        for (int w = 0; w < 8; w++) ps += sr[tid][w];
        int bvv = b*4 + tid;
        float den = fmaxf(d_denom[bvv], 1e-8f);
        out[(size_t)bvv*CP_ + c] = ps/den + d_gmax[bvv*CP_ + c];
    }
}

// ---------------- launch ----------------------------------------------------
extern "C" void kernel_launch(void* const* d_in, const int* in_sizes, int n_in,
                              void* d_out, int out_size) {
    const float* xyz = (const float*)d_in[0];
    const float* pf  = (const float*)d_in[1];
    const float* pm  = (const float*)d_in[2];
    const float* W1  = (const float*)d_in[3];
    const float* b1  = (const float*)d_in[4];
    const float* g1  = (const float*)d_in[5];
    const float* be1 = (const float*)d_in[6];
    const float* W2  = (const float*)d_in[7];
    const float* b2  = (const float*)d_in[8];
    const float* g2  = (const float*)d_in[9];
    const float* be2 = (const float*)d_in[10];
    const float* W3  = (const float*)d_in[11];
    const float* b3  = (const float*)d_in[12];
    const float* g3  = (const float*)d_in[13];
    const float* be3 = (const float*)d_in[14];
    const float* W4  = (const float*)d_in[15];
    float* out = (float*)d_out;

    static int configured = 0;
    if (!configured) {
        cudaFuncSetAttribute(kB, cudaFuncAttributeMaxDynamicSharedMemorySize, DYN_SMEM);
        cudaFuncSetAttribute(kD, cudaFuncAttributeMaxDynamicSharedMemorySize, DYN_SMEM);
        configured = 1;
    }

    kP<<<CP_, 256>>>(W2, W3);
    kA<<<BV_, 256>>>(xyz, pm);
    kB<<<NT2_, 256, DYN_SMEM>>>(xyz, W1, b1, g1, be1, b2, g2, be2);
    kC<<<BV_, 256>>>(W3, b3);
    kD<<<NT2_, 256, DYN_SMEM>>>(pm, g3, be3, W4);
    kE<<<B_*CP_, 256>>>(pf, out);
}

// round 10
// speedup vs baseline: 3.2654x; 1.0651x over previous
#include <cuda_runtime.h>
#include <cuda_fp16.h>
#include <math.h>
#include <float.h>
#include <stdint.h>

#define B_   8
#define V_   4
#define N_   16384
#define CP_  256
#define BV_  (B_*V_)            // 32
#define TM_  64                 // points per CTA tile
#define NT2_ (N_*BV_/TM_)       // 8192 tiles
#define A_STR 528               // A row stride bytes (256 fp16 + 16 pad)
#define B_STR 80                // B row stride bytes (32 fp16 + 16 pad)
#define A_IMG    33792          // 64*528
#define OFF_B    33792
#define B_BUF    20480          // one K32 chunk: 256 rows x 80B
#define B_GCH    16384          // packed gmem chunk bytes (256*64)
#define DYN_SMEM 95232          // A + 3*B_BUF

// ---------------- device scratch (static; no allocations) -------------------
__device__ float d_center[BV_*3];
__device__ float d_invdiam[BV_];
__device__ float d_stat1[14];
__device__ __align__(16) float d_gmax[BV_*CP_];
__device__ __align__(16) float d_gpart[BV_*CP_];
__device__ float d_mw[BV_*N_];
__device__ float d_denom[BV_];
// z = local @ W3top, fp16 packed words [point][128]
__device__ __align__(16) uint32_t d_z[(size_t)BV_*N_*128];           // 268MB
__device__ __align__(16) unsigned char d_W2f[CP_*CP_*2];
__device__ __align__(16) unsigned char d_W3f[CP_*CP_*2];

// ---------------- helpers ---------------------------------------------------
__device__ __forceinline__ uint32_t sm2u(const void* p) {
    uint32_t a;
    asm("{ .reg .u64 t; cvta.to.shared.u64 t, %1; cvt.u32.u64 %0, t; }"
        : "=r"(a) : "l"(p));
    return a;
}
#define LDSM4(r, addr) \
    asm volatile("ldmatrix.sync.aligned.m8n8.x4.shared.b16 {%0,%1,%2,%3}, [%4];" \
        : "=r"((r)[0]), "=r"((r)[1]), "=r"((r)[2]), "=r"((r)[3]) : "r"(addr))
#define MMAOP(d, a, b0, b1) \
    asm volatile("mma.sync.aligned.m16n8k16.row.col.f32.f16.f16.f32 " \
        "{%0,%1,%2,%3}, {%4,%5,%6,%7}, {%8,%9}, {%0,%1,%2,%3};" \
        : "+f"((d)[0]), "+f"((d)[1]), "+f"((d)[2]), "+f"((d)[3]) \
        : "r"((a)[0]), "r"((a)[1]), "r"((a)[2]), "r"((a)[3]), "r"(b0), "r"(b1))
#define CPA16(dst, src) \
    asm volatile("cp.async.cg.shared.global [%0], [%1], 16;" :: "r"(dst), "l"(src))
#define CPCOMMIT() asm volatile("cp.async.commit_group;" ::: "memory")
#define CPWAIT1()  asm volatile("cp.async.wait_group 1;" ::: "memory")

static __device__ __forceinline__ uint32_t pack2h(float v0, float v1) {
    __half h0 = __float2half_rn(v0);
    __half h1 = __float2half_rn(v1);
    return (uint32_t)__half_as_ushort(h0) | ((uint32_t)__half_as_ushort(h1) << 16);
}
__device__ __forceinline__ void atomicMaxFloat(float* addr, float val) {
    if (__float_as_int(val) >= 0) atomicMax((int*)addr, __float_as_int(val));
    else atomicMin((unsigned int*)addr, __float_as_uint(val));
}

__device__ __forceinline__ void prefetchB(uint32_t su, int buf, int ch,
                                          const unsigned char* g, int tid) {
    uint32_t base = su + OFF_B + (uint32_t)buf*B_BUF;
    #pragma unroll
    for (int i = 0; i < 4; i++) {
        int w = tid + i*256;             // 0..1023
        int n = w >> 2, c16 = w & 3;
        uint32_t dst = base + (uint32_t)n*B_STR + c16*16;
        CPA16(dst, g + (size_t)ch*B_GCH + (size_t)w*16);
    }
}

// one 8-chunk HMMA mainloop over weights g; accumulators dA/dB
#define MAINLOOP(g) \
    _Pragma("unroll 1") \
    for (int ch = 0; ch < 8; ch++) { \
        CPWAIT1(); \
        __syncthreads(); \
        if (ch < 6) prefetchB(su, (ch+2)%3, ch+2, g, tid); \
        CPCOMMIT(); \
        uint32_t bb = su + OFF_B + (uint32_t)(ch%3)*B_BUF; \
        _Pragma("unroll") \
        for (int kb = 0; kb < 2; kb++) { \
            uint32_t kA = (uint32_t)(ch*64 + kb*32); \
            uint32_t ah[4], ah2[4]; \
            LDSM4(ah,  su + aoff0 + kA); \
            LDSM4(ah2, su + aoff1 + kA); \
            _Pragma("unroll") \
            for (int nt = 0; nt < 4; nt++) { \
                uint32_t bh[4]; \
                LDSM4(bh, bb + boff + (uint32_t)(nt*16*B_STR) + kb*32); \
                MMAOP(dA[2*nt],   ah,  bh[0], bh[1]); \
                MMAOP(dA[2*nt+1], ah,  bh[2], bh[3]); \
                MMAOP(dB[2*nt],   ah2, bh[0], bh[1]); \
                MMAOP(dB[2*nt+1], ah2, bh[2], bh[3]); \
            } \
        } \
    }

// ---------------- kP: convert weights to fp16 packed chunk layout -----------
__global__ void __launch_bounds__(256) kP(const float* __restrict__ W2,
                                          const float* __restrict__ W3) {
    int k = blockIdx.x;
    int n = threadIdx.x;
    int ch = k >> 5, kk = k & 31;
    size_t pos = (size_t)ch*B_GCH + (size_t)n*64 + (size_t)kk*2;
    *(unsigned short*)(d_W2f + pos) = __half_as_ushort(__float2half_rn(W2[k*CP_ + n]));
    *(unsigned short*)(d_W3f + pos) = __half_as_ushort(__float2half_rn(W3[k*CP_ + n]));
}

// ---------------- kS: analytic LN1 stats aggregates -------------------------
__global__ void __launch_bounds__(256) kS(const float* __restrict__ W1,
                                          const float* __restrict__ b1) {
    __shared__ float sm[14][256];
    int c = threadIdx.x;
    float b = b1[c], w0 = W1[c], w1 = W1[CP_+c], w2 = W1[2*CP_+c];
    sm[0][c]=b;      sm[1][c]=b*b;
    sm[2][c]=w0;     sm[3][c]=w1;     sm[4][c]=w2;
    sm[5][c]=b*w0;   sm[6][c]=b*w1;   sm[7][c]=b*w2;
    sm[8][c]=w0*w0;  sm[9][c]=w0*w1;  sm[10][c]=w0*w2;
    sm[11][c]=w1*w1; sm[12][c]=w1*w2; sm[13][c]=w2*w2;
    __syncthreads();
    for (int s = 128; s > 0; s >>= 1) {
        if (c < s) {
            #pragma unroll
            for (int q = 0; q < 14; q++) sm[q][c] += sm[q][c+s];
        }
        __syncthreads();
    }
    if (c < 14) d_stat1[c] = sm[c][0];
}

// ---------------- kA: per-(b,v) stats + init --------------------------------
__global__ void __launch_bounds__(256) kA(const float* __restrict__ xyz,
                                          const float* __restrict__ masks) {
    int bv = blockIdx.x;
    int b  = bv >> 2;
    int tid = threadIdx.x;

    float s0=0.f, s1=0.f, s2=0.f, cnt=0.f;
    float mx0=-FLT_MAX, mx1=-FLT_MAX, mx2=-FLT_MAX;
    float mn0= FLT_MAX, mn1= FLT_MAX, mn2= FLT_MAX;

    const float* mrow = masks + (size_t)bv*N_;
    const float* x0r  = xyz + (size_t)(b*3+0)*N_;
    const float* x1r  = xyz + (size_t)(b*3+1)*N_;
    const float* x2r  = xyz + (size_t)(b*3+2)*N_;

    for (int n = tid; n < N_; n += 256) {
        float m = mrow[n];
        float a = x0r[n]*m, c = x1r[n]*m, e = x2r[n]*m;
        s0 += a; s1 += c; s2 += e; cnt += m;
        mx0 = fmaxf(mx0,a); mx1 = fmaxf(mx1,c); mx2 = fmaxf(mx2,e);
        mn0 = fminf(mn0,a); mn1 = fminf(mn1,c); mn2 = fminf(mn2,e);
    }
    __shared__ float rs[4][256];
    __shared__ float rx[3][256];
    __shared__ float rn[3][256];
    rs[0][tid]=s0; rs[1][tid]=s1; rs[2][tid]=s2; rs[3][tid]=cnt;
    rx[0][tid]=mx0; rx[1][tid]=mx1; rx[2][tid]=mx2;
    rn[0][tid]=mn0; rn[1][tid]=mn1; rn[2][tid]=mn2;
    __syncthreads();
    for (int s = 128; s > 0; s >>= 1) {
        if (tid < s) {
            #pragma unroll
            for (int q = 0; q < 4; q++) rs[q][tid] += rs[q][tid+s];
            #pragma unroll
            for (int q = 0; q < 3; q++) {
                rx[q][tid] = fmaxf(rx[q][tid], rx[q][tid+s]);
                rn[q][tid] = fminf(rn[q][tid], rn[q][tid+s]);
            }
        }
        __syncthreads();
    }
    if (tid == 0) {
        float valid = fmaxf(rs[3][0], 1.f);
        d_center[bv*3+0] = rs[0][0]/valid;
        d_center[bv*3+1] = rs[1][0]/valid;
        d_center[bv*3+2] = rs[2][0]/valid;
        float diam = fmaxf(fmaxf(rx[0][0]-rn[0][0], rx[1][0]-rn[1][0]),
                           rx[2][0]-rn[2][0]);
        if (diam == 0.f) diam = 1.f;
        d_invdiam[bv] = 1.f/diam;
        d_denom[bv]   = 0.f;
    }
    d_gmax[bv*CP_ + tid] = -FLT_MAX;
}

// ----- kB: stage1 -> GEMM(W2) -> reg-LN2 -> gmax -> GEMM(W3top) -> z --------
__global__ void __launch_bounds__(256, 2) kB(const float* __restrict__ xyz,
    const float* __restrict__ W1, const float* __restrict__ b1,
    const float* __restrict__ g1, const float* __restrict__ be1,
    const float* __restrict__ b2, const float* __restrict__ g2,
    const float* __restrict__ be2)
{
    extern __shared__ unsigned char ds[];
    __shared__ float w1s[3*CP_];
    __shared__ float b1s[CP_], g1s[CP_], e1s[CP_], b2s[CP_], g2s[CP_], e2s[CP_];
    __shared__ float srS[TM_][4], srQ[TM_][4];
    __shared__ float sMean[TM_], sRstd[TM_];
    __shared__ float scx[2][CP_];

    int tile = blockIdx.x;
    int bv = tile >> 8;
    int b  = bv >> 2;
    int tid = threadIdx.x, lane = tid & 31, wid = tid >> 5;
    uint32_t su = sm2u(ds);

    prefetchB(su, 0, 0, d_W2f, tid); CPCOMMIT();
    prefetchB(su, 1, 1, d_W2f, tid); CPCOMMIT();

    for (int i = tid; i < 3*CP_; i += 256) w1s[i] = W1[i];
    b1s[tid]=b1[tid]; g1s[tid]=g1[tid]; e1s[tid]=be1[tid];
    b2s[tid]=b2[tid]; g2s[tid]=g2[tid]; e2s[tid]=be2[tid];

    int p = tid >> 2, sub = tid & 3, c0 = sub*64;
    float idm = d_invdiam[bv];
    int n = (tile & 255) * TM_ + p;
    float x0 = (xyz[(size_t)(b*3+0)*N_ + n] - d_center[bv*3+0]) * idm;
    float x1 = (xyz[(size_t)(b*3+1)*N_ + n] - d_center[bv*3+1]) * idm;
    float x2 = (xyz[(size_t)(b*3+2)*N_ + n] - d_center[bv*3+2]) * idm;

    // analytic LN1 stats (quadratic form in x)
    float mean, rstd;
    {
        const float* st = d_stat1;
        float S  = st[0] + x0*st[2] + x1*st[3] + x2*st[4];
        float E2 = st[1] + 2.f*(x0*st[5] + x1*st[6] + x2*st[7])
                 + x0*x0*st[8]  + 2.f*x0*x1*st[9] + 2.f*x0*x2*st[10]
                 + x1*x1*st[11] + 2.f*x1*x2*st[12] + x2*x2*st[13];
        mean = S * (1.f/CP_);
        rstd = rsqrtf(E2*(1.f/CP_) - mean*mean + 1e-5f);
    }
    __syncthreads();

    // single pass: y -> LN1 -> ReLU -> fp16 -> A smem
    #pragma unroll 8
    for (int i = 0; i < 32; i++) {
        int c = c0 + 2*i;
        float y0 = b1s[c]   + x0*w1s[c]   + x1*w1s[CP_+c]   + x2*w1s[2*CP_+c];
        float y1 = b1s[c+1] + x0*w1s[c+1] + x1*w1s[CP_+c+1] + x2*w1s[2*CP_+c+1];
        y0 = fmaxf((y0-mean)*rstd*g1s[c]   + e1s[c],   0.f);
        y1 = fmaxf((y1-mean)*rstd*g1s[c+1] + e1s[c+1], 0.f);
        *(uint32_t*)(ds + (size_t)p*A_STR + c*2) = pack2h(y0, y1);
    }

    int mt0 = (wid >> 2) * 16;
    int nb  = (wid & 3) * 64;
    uint32_t aoff0 = (uint32_t)(mt0 + (lane&7) + ((lane>>3)&1)*8)*A_STR + (lane>>4)*16;
    uint32_t aoff1 = aoff0 + 32u*A_STR;
    uint32_t boff  = (uint32_t)(nb + (lane&7) + (lane>>4)*8)*B_STR + ((lane>>3)&1)*16;

    float dA[8][4] = {}, dB[8][4] = {};
    MAINLOOP(d_W2f)

    __syncthreads();   // all reads of A(h) and B buffers done
    prefetchB(su, 0, 0, d_W3f, tid); CPCOMMIT();
    prefetchB(su, 1, 1, d_W3f, tid); CPCOMMIT();

    // ---- register epilogue: LN2 stats from fragments ----
    int r = lane >> 2, q2 = (lane & 3)*2;
    int rw0 = mt0 + r, rw1 = mt0 + r + 8, rw2 = mt0 + 32 + r, rw3 = mt0 + 40 + r;
    float rs0=0.f,rq0=0.f,rs1=0.f,rq1=0.f,rs2=0.f,rq2=0.f,rs3=0.f,rq3=0.f;
    #pragma unroll
    for (int nt = 0; nt < 8; nt++) {
        int c = nb + nt*8 + q2;
        float bb0 = b2s[c], bb1 = b2s[c+1], v;
        v = dA[nt][0]+bb0; rs0+=v; rq0+=v*v;
        v = dA[nt][1]+bb1; rs0+=v; rq0+=v*v;
        v = dA[nt][2]+bb0; rs1+=v; rq1+=v*v;
        v = dA[nt][3]+bb1; rs1+=v; rq1+=v*v;
        v = dB[nt][0]+bb0; rs2+=v; rq2+=v*v;
        v = dB[nt][1]+bb1; rs2+=v; rq2+=v*v;
        v = dB[nt][2]+bb0; rs3+=v; rq3+=v*v;
        v = dB[nt][3]+bb1; rs3+=v; rq3+=v*v;
    }
    rs0 += __shfl_xor_sync(~0u, rs0, 1); rs0 += __shfl_xor_sync(~0u, rs0, 2);
    rq0 += __shfl_xor_sync(~0u, rq0, 1); rq0 += __shfl_xor_sync(~0u, rq0, 2);
    rs1 += __shfl_xor_sync(~0u, rs1, 1); rs1 += __shfl_xor_sync(~0u, rs1, 2);
    rq1 += __shfl_xor_sync(~0u, rq1, 1); rq1 += __shfl_xor_sync(~0u, rq1, 2);
    rs2 += __shfl_xor_sync(~0u, rs2, 1); rs2 += __shfl_xor_sync(~0u, rs2, 2);
    rq2 += __shfl_xor_sync(~0u, rq2, 1); rq2 += __shfl_xor_sync(~0u, rq2, 2);
    rs3 += __shfl_xor_sync(~0u, rs3, 1); rs3 += __shfl_xor_sync(~0u, rs3, 2);
    rq3 += __shfl_xor_sync(~0u, rq3, 1); rq3 += __shfl_xor_sync(~0u, rq3, 2);
    if ((lane & 3) == 0) {
        int w4 = wid & 3;
        srS[rw0][w4]=rs0; srQ[rw0][w4]=rq0;
        srS[rw1][w4]=rs1; srQ[rw1][w4]=rq1;
        srS[rw2][w4]=rs2; srQ[rw2][w4]=rq2;
        srS[rw3][w4]=rs3; srQ[rw3][w4]=rq3;
    }
    __syncthreads();
    if (tid < TM_) {
        float S = srS[tid][0]+srS[tid][1]+srS[tid][2]+srS[tid][3];
        float Q = srQ[tid][0]+srQ[tid][1]+srQ[tid][2]+srQ[tid][3];
        float mn = S * (1.f/CP_);
        sMean[tid] = mn;
        sRstd[tid] = rsqrtf(Q*(1.f/CP_) - mn*mn + 1e-5f);
    }
    __syncthreads();

    // normalize in regs, pack local back into A smem, column max
    {
        float m0 = sMean[rw0], rr0 = sRstd[rw0];
        float m1 = sMean[rw1], rr1 = sRstd[rw1];
        float m2 = sMean[rw2], rr2 = sRstd[rw2];
        float m3 = sMean[rw3], rr3 = sRstd[rw3];
        float cm[16];
        #pragma unroll
        for (int nt = 0; nt < 8; nt++) {
            int c = nb + nt*8 + q2;
            float bb0=b2s[c], bb1=b2s[c+1], g0=g2s[c], g1=g2s[c+1], e0=e2s[c], e1=e2s[c+1];
            float v00 = (dA[nt][0]+bb0-m0)*rr0*g0+e0, v01 = (dA[nt][1]+bb1-m0)*rr0*g1+e1;
            float v10 = (dA[nt][2]+bb0-m1)*rr1*g0+e0, v11 = (dA[nt][3]+bb1-m1)*rr1*g1+e1;
            float v20 = (dB[nt][0]+bb0-m2)*rr2*g0+e0, v21 = (dB[nt][1]+bb1-m2)*rr2*g1+e1;
            float v30 = (dB[nt][2]+bb0-m3)*rr3*g0+e0, v31 = (dB[nt][3]+bb1-m3)*rr3*g1+e1;
            *(uint32_t*)(ds + (size_t)rw0*A_STR + c*2) = pack2h(v00, v01);
            *(uint32_t*)(ds + (size_t)rw1*A_STR + c*2) = pack2h(v10, v11);
            *(uint32_t*)(ds + (size_t)rw2*A_STR + c*2) = pack2h(v20, v21);
            *(uint32_t*)(ds + (size_t)rw3*A_STR + c*2) = pack2h(v30, v31);
            cm[2*nt]   = fmaxf(fmaxf(v00, v10), fmaxf(v20, v30));
            cm[2*nt+1] = fmaxf(fmaxf(v01, v11), fmaxf(v21, v31));
        }
        #pragma unroll
        for (int i = 0; i < 16; i++) {
            cm[i] = fmaxf(cm[i], __shfl_xor_sync(~0u, cm[i], 4));
            cm[i] = fmaxf(cm[i], __shfl_xor_sync(~0u, cm[i], 8));
            cm[i] = fmaxf(cm[i], __shfl_xor_sync(~0u, cm[i], 16));
        }
        if ((lane >> 2) == 0) {
            int grp = wid >> 2;
            #pragma unroll
            for (int nt = 0; nt < 8; nt++) {
                int c = nb + nt*8 + q2;
                scx[grp][c]   = cm[2*nt];
                scx[grp][c+1] = cm[2*nt+1];
            }
        }
    }
    __syncthreads();
    atomicMaxFloat(&d_gmax[bv*CP_ + tid], fmaxf(scx[0][tid], scx[1][tid]));

    // ---- GEMM 2: z = local @ W3top ----
    #pragma unroll
    for (int nt = 0; nt < 8; nt++) {
        #pragma unroll
        for (int i = 0; i < 4; i++) { dA[nt][i] = 0.f; dB[nt][i] = 0.f; }
    }
    MAINLOOP(d_W3f)

    // z epilogue: raw fp16 store
    uint32_t* zb = d_z + (size_t)tile*TM_*128;
    #pragma unroll
    for (int nt = 0; nt < 8; nt++) {
        int cw = (nb + nt*8 + q2) >> 1;
        zb[(size_t)rw0*128 + cw] = pack2h(dA[nt][0], dA[nt][1]);
        zb[(size_t)rw1*128 + cw] = pack2h(dA[nt][2], dA[nt][3]);
        zb[(size_t)rw2*128 + cw] = pack2h(dB[nt][0], dB[nt][1]);
        zb[(size_t)rw3*128 + cw] = pack2h(dB[nt][2], dB[nt][3]);
    }
}

// ---------------- kC: gpart = global_xyz @ W3[256:512] + b3 -----------------
__global__ void __launch_bounds__(256) kC(const float* __restrict__ W3,
                                          const float* __restrict__ b3) {
    int bv = blockIdx.x;
    int c  = threadIdx.x;
    __shared__ float sg[CP_];
    __shared__ float ws[32*CP_];
    sg[c] = d_gmax[bv*CP_ + c];
    float acc = b3[c];
    for (int ko = 0; ko < 8; ko++) {
        __syncthreads();
        const float4* src = (const float4*)(W3 + (size_t)(256 + ko*32)*CP_);
        for (int i = c; i < 32*CP_/4; i += 256) ((float4*)ws)[i] = src[i];
        __syncthreads();
        #pragma unroll 8
        for (int kk = 0; kk < 32; kk++)
            acc += sg[ko*32+kk] * ws[kk*CP_ + c];
    }
    d_gpart[bv*CP_ + c] = acc;
}

// ---------------- kD: streaming LN3 + ReLU + W4 -> weights ------------------
__global__ void __launch_bounds__(256) kD(const float* __restrict__ masks,
    const float* __restrict__ g3, const float* __restrict__ be3,
    const float* __restrict__ W4)
{
    __shared__ float sGp[CP_], sG3[CP_], sE3[CP_], sW4[CP_];
    int blk = blockIdx.x;              // 1024 blocks: 32 per bv
    int bv = blk >> 5;
    int pbase = (blk & 31) * 512;      // 512 points per CTA
    int tid = threadIdx.x, lane = tid & 31, wid = tid >> 5;

    sGp[tid] = d_gpart[bv*CP_ + tid];
    sG3[tid] = g3[tid]; sE3[tid] = be3[tid]; sW4[tid] = W4[tid];
    __syncthreads();

    int cbase = lane*8;
    float gp[8], gg[8], ee[8], ww[8];
    #pragma unroll
    for (int j = 0; j < 8; j++) {
        gp[j]=sGp[cbase+j]; gg[j]=sG3[cbase+j]; ee[j]=sE3[cbase+j]; ww[j]=sW4[cbase+j];
    }

    float dacc = 0.f;
    for (int pp = wid; pp < 512; pp += 8) {
        int n = pbase + pp;
        size_t pt = (size_t)bv*N_ + n;
        uint4 w = *(const uint4*)(d_z + pt*128 + lane*4);
        uint32_t ws4[4] = {w.x, w.y, w.z, w.w};
        float v[8];
        #pragma unroll
        for (int j = 0; j < 4; j++) {
            __half2 h2 = *reinterpret_cast<__half2*>(&ws4[j]);
            float2 f = __half22float2(h2);
            v[2*j]   = f.x + gp[2*j];
            v[2*j+1] = f.y + gp[2*j+1];
        }
        float s = 0.f, q = 0.f;
        #pragma unroll
        for (int j = 0; j < 8; j++) { s += v[j]; q += v[j]*v[j]; }
        #pragma unroll
        for (int o = 16; o > 0; o >>= 1) {
            s += __shfl_xor_sync(~0u, s, o);
            q += __shfl_xor_sync(~0u, q, o);
        }
        float mean = s * (1.f/CP_);
        float rstd = rsqrtf(q*(1.f/CP_) - mean*mean + 1e-5f);
        float dot = 0.f;
        #pragma unroll
        for (int j = 0; j < 8; j++)
            dot += fmaxf((v[j]-mean)*rstd*gg[j] + ee[j], 0.f) * ww[j];
        #pragma unroll
        for (int o = 16; o > 0; o >>= 1) dot += __shfl_xor_sync(~0u, dot, o);
        if (lane == 0) {
            float m = masks[pt];
            float wgt = 2.f * m / (1.f + expf(-dot));
            d_mw[pt] = wgt;
            dacc += wgt;
        }
    }
    if (lane == 0) atomicAdd(&d_denom[bv], dacc);
}

// ---------------- kE: weighted pooling + epilogue ---------------------------
__global__ void __launch_bounds__(256) kE(const float* __restrict__ feats,
                                          float* __restrict__ out) {
    int blk = blockIdx.x;        // b*CP_ + c
    int b = blk >> 8;
    int c = blk & 255;
    int tid = threadIdx.x;

    const float* f   = feats + (size_t)(b*CP_ + c)*N_;
    const float* mw0 = d_mw + (size_t)(b*4+0)*N_;
    const float* mw1 = d_mw + (size_t)(b*4+1)*N_;
    const float* mw2 = d_mw + (size_t)(b*4+2)*N_;
    const float* mw3 = d_mw + (size_t)(b*4+3)*N_;

    float a0=0.f, a1=0.f, a2=0.f, a3=0.f;
    for (int n = tid; n < N_; n += 256) {
        float fv = f[n];
        a0 += fv*mw0[n]; a1 += fv*mw1[n]; a2 += fv*mw2[n]; a3 += fv*mw3[n];
    }
    #pragma unroll
    for (int o = 16; o > 0; o >>= 1) {
        a0 += __shfl_xor_sync(0xffffffffu, a0, o);
        a1 += __shfl_xor_sync(0xffffffffu, a1, o);
        a2 += __shfl_xor_sync(0xffffffffu, a2, o);
        a3 += __shfl_xor_sync(0xffffffffu, a3, o);
    }
    __shared__ float sr[4][8];
    int lane = tid & 31, warp = tid >> 5;
    if (lane == 0) { sr[0][warp]=a0; sr[1][warp]=a1; sr[2][warp]=a2; sr[3][warp]=a3; }
    __syncthreads();
    if (tid < 4) {
        float ps = 0.f;
        #pragma unroll
        for (int w = 0; w < 8; w++) ps += sr[tid][w];
        int bvv = b*4 + tid;
        float den = fmaxf(d_denom[bvv], 1e-8f);
        out[(size_t)bvv*CP_ + c] = ps/den + d_gmax[bvv*CP_ + c];
    }
}

// ---------------- launch ----------------------------------------------------
extern "C" void kernel_launch(void* const* d_in, const int* in_sizes, int n_in,
                              void* d_out, int out_size) {
    const float* xyz = (const float*)d_in[0];
    const float* pf  = (const float*)d_in[1];
    const float* pm  = (const float*)d_in[2];
    const float* W1  = (const float*)d_in[3];
    const float* b1  = (const float*)d_in[4];
    const float* g1  = (const float*)d_in[5];
    const float* be1 = (const float*)d_in[6];
    const float* W2  = (const float*)d_in[7];
    const float* b2  = (const float*)d_in[8];
    const float* g2  = (const float*)d_in[9];
    const float* be2 = (const float*)d_in[10];
    const float* W3  = (const float*)d_in[11];
    const float* b3  = (const float*)d_in[12];
    const float* g3  = (const float*)d_in[13];
    const float* be3 = (const float*)d_in[14];
    const float* W4  = (const float*)d_in[15];
    float* out = (float*)d_out;

    static int configured = 0;
    if (!configured) {
        cudaFuncSetAttribute(kB, cudaFuncAttributeMaxDynamicSharedMemorySize, DYN_SMEM);
        configured = 1;
    }

    kP<<<CP_, 256>>>(W2, W3);
    kS<<<1, 256>>>(W1, b1);
    kA<<<BV_, 256>>>(xyz, pm);
    kB<<<NT2_, 256, DYN_SMEM>>>(xyz, W1, b1, g1, be1, b2, g2, be2);
    kC<<<BV_, 256>>>(W3, b3);
    kD<<<1024, 256>>>(pm, g3, be3, W4);
    kE<<<B_*CP_, 256>>>(pf, out);
}

// round 11
// speedup vs baseline: 3.3403x; 1.0229x over previous
#include <cuda_runtime.h>
#include <cuda_fp16.h>
#include <math.h>
#include <float.h>
#include <stdint.h>

#define B_   8
#define V_   4
#define N_   16384
#define CP_  256
#define BV_  (B_*V_)            // 32
#define TM_  64                 // points per tile
#define NT2_ (N_*BV_/TM_)       // 8192 tiles
#define GRIDP 148               // persistent grid
#define A_STR 528               // padded row stride bytes (256 fp16 + 16 pad)
#define A_IMG    33792          // 64*528
#define OFF_RB   67584          // resident B offset (after 2 A buffers)
#define RB_BYTES 135168         // 256*528
#define DYN_SMEM (OFF_RB + RB_BYTES)   // 202752

// ---------------- device scratch (static; no allocations) -------------------
__device__ float d_center[BV_*3];
__device__ float d_invdiam[BV_];
__device__ float d_stat1[14];
__device__ __align__(16) float d_gmax[BV_*CP_];
__device__ __align__(16) float d_gpart[BV_*CP_];
__device__ float d_mw[BV_*N_];
__device__ float d_denom[BV_];
__device__ __align__(16) unsigned char d_localA[(size_t)NT2_*A_IMG];  // 277MB
__device__ __align__(16) uint32_t d_z[(size_t)BV_*N_*128];            // 268MB
// weights fp16, plain [n][k] row-major (512B rows)
__device__ __align__(16) unsigned char d_W2f[CP_*CP_*2];
__device__ __align__(16) unsigned char d_W3f[CP_*CP_*2];

// ---------------- helpers ---------------------------------------------------
__device__ __forceinline__ uint32_t sm2u(const void* p) {
    uint32_t a;
    asm("{ .reg .u64 t; cvta.to.shared.u64 t, %1; cvt.u32.u64 %0, t; }"
        : "=r"(a) : "l"(p));
    return a;
}
#define LDSM4(r, addr) \
    asm volatile("ldmatrix.sync.aligned.m8n8.x4.shared.b16 {%0,%1,%2,%3}, [%4];" \
        : "=r"((r)[0]), "=r"((r)[1]), "=r"((r)[2]), "=r"((r)[3]) : "r"(addr))
#define MMAOP(d, a, b0, b1) \
    asm volatile("mma.sync.aligned.m16n8k16.row.col.f32.f16.f16.f32 " \
        "{%0,%1,%2,%3}, {%4,%5,%6,%7}, {%8,%9}, {%0,%1,%2,%3};" \
        : "+f"((d)[0]), "+f"((d)[1]), "+f"((d)[2]), "+f"((d)[3]) \
        : "r"((a)[0]), "r"((a)[1]), "r"((a)[2]), "r"((a)[3]), "r"(b0), "r"(b1))
#define CPA16(dst, src) \
    asm volatile("cp.async.cg.shared.global [%0], [%1], 16;" :: "r"(dst), "l"(src))
#define CPCOMMIT() asm volatile("cp.async.commit_group;" ::: "memory")
#define CPWAIT1()  asm volatile("cp.async.wait_group 1;" ::: "memory")
#define CPWAIT0()  asm volatile("cp.async.wait_group 0;" ::: "memory")

static __device__ __forceinline__ uint32_t pack2h(float v0, float v1) {
    __half h0 = __float2half_rn(v0);
    __half h1 = __float2half_rn(v1);
    return (uint32_t)__half_as_ushort(h0) | ((uint32_t)__half_as_ushort(h1) << 16);
}
__device__ __forceinline__ void atomicMaxFloat(float* addr, float val) {
    if (__float_as_int(val) >= 0) atomicMax((int*)addr, __float_as_int(val));
    else atomicMin((unsigned int*)addr, __float_as_uint(val));
}

// copy 128KB weight matrix into resident padded smem rows (cp.async)
__device__ __forceinline__ void loadResidentB(uint32_t su, const unsigned char* g, int tid) {
    for (int i = tid; i < 8192; i += 256) {
        int row = i >> 5, q = i & 31;
        CPA16(su + OFF_RB + (uint32_t)row*A_STR + q*16, g + (size_t)i*16);
    }
}

// K=256 mainloop, B resident, zero syncs. ab = A buffer smem addr.
#define MAINLOOP_R(ab) \
    _Pragma("unroll 1") \
    for (int ch = 0; ch < 8; ch++) { \
        _Pragma("unroll") \
        for (int kb = 0; kb < 2; kb++) { \
            uint32_t kA = (uint32_t)(ch*64 + kb*32); \
            uint32_t ah[4], ah2[4]; \
            LDSM4(ah,  (ab) + aoff0 + kA); \
            LDSM4(ah2, (ab) + aoff1 + kA); \
            _Pragma("unroll") \
            for (int nt = 0; nt < 4; nt++) { \
                uint32_t bh[4]; \
                LDSM4(bh, su + OFF_RB + boff + (uint32_t)(nt*16*A_STR) + kA); \
                MMAOP(dA[2*nt],   ah,  bh[0], bh[1]); \
                MMAOP(dA[2*nt+1], ah,  bh[2], bh[3]); \
                MMAOP(dB[2*nt],   ah2, bh[0], bh[1]); \
                MMAOP(dB[2*nt+1], ah2, bh[2], bh[3]); \
            } \
        } \
    }

// ---------------- kP: weights -> fp16 [n][k] --------------------------------
__global__ void __launch_bounds__(256) kP(const float* __restrict__ W2,
                                          const float* __restrict__ W3) {
    int k = blockIdx.x;
    int n = threadIdx.x;
    size_t pos = ((size_t)n*CP_ + k)*2;
    *(unsigned short*)(d_W2f + pos) = __half_as_ushort(__float2half_rn(W2[k*CP_ + n]));
    *(unsigned short*)(d_W3f + pos) = __half_as_ushort(__float2half_rn(W3[k*CP_ + n]));
}

// ---------------- kS: analytic LN1 stats aggregates -------------------------
__global__ void __launch_bounds__(256) kS(const float* __restrict__ W1,
                                          const float* __restrict__ b1) {
    __shared__ float sm[14][256];
    int c = threadIdx.x;
    float b = b1[c], w0 = W1[c], w1 = W1[CP_+c], w2 = W1[2*CP_+c];
    sm[0][c]=b;      sm[1][c]=b*b;
    sm[2][c]=w0;     sm[3][c]=w1;     sm[4][c]=w2;
    sm[5][c]=b*w0;   sm[6][c]=b*w1;   sm[7][c]=b*w2;
    sm[8][c]=w0*w0;  sm[9][c]=w0*w1;  sm[10][c]=w0*w2;
    sm[11][c]=w1*w1; sm[12][c]=w1*w2; sm[13][c]=w2*w2;
    __syncthreads();
    for (int s = 128; s > 0; s >>= 1) {
        if (c < s) {
            #pragma unroll
            for (int q = 0; q < 14; q++) sm[q][c] += sm[q][c+s];
        }
        __syncthreads();
    }
    if (c < 14) d_stat1[c] = sm[c][0];
}

// ---------------- kA: per-(b,v) stats + init --------------------------------
__global__ void __launch_bounds__(256) kA(const float* __restrict__ xyz,
                                          const float* __restrict__ masks) {
    int bv = blockIdx.x;
    int b  = bv >> 2;
    int tid = threadIdx.x;

    float s0=0.f, s1=0.f, s2=0.f, cnt=0.f;
    float mx0=-FLT_MAX, mx1=-FLT_MAX, mx2=-FLT_MAX;
    float mn0= FLT_MAX, mn1= FLT_MAX, mn2= FLT_MAX;

    const float* mrow = masks + (size_t)bv*N_;
    const float* x0r  = xyz + (size_t)(b*3+0)*N_;
    const float* x1r  = xyz + (size_t)(b*3+1)*N_;
    const float* x2r  = xyz + (size_t)(b*3+2)*N_;

    for (int n = tid; n < N_; n += 256) {
        float m = mrow[n];
        float a = x0r[n]*m, c = x1r[n]*m, e = x2r[n]*m;
        s0 += a; s1 += c; s2 += e; cnt += m;
        mx0 = fmaxf(mx0,a); mx1 = fmaxf(mx1,c); mx2 = fmaxf(mx2,e);
        mn0 = fminf(mn0,a); mn1 = fminf(mn1,c); mn2 = fminf(mn2,e);
    }
    __shared__ float rs[4][256];
    __shared__ float rx[3][256];
    __shared__ float rn[3][256];
    rs[0][tid]=s0; rs[1][tid]=s1; rs[2][tid]=s2; rs[3][tid]=cnt;
    rx[0][tid]=mx0; rx[1][tid]=mx1; rx[2][tid]=mx2;
    rn[0][tid]=mn0; rn[1][tid]=mn1; rn[2][tid]=mn2;
    __syncthreads();
    for (int s = 128; s > 0; s >>= 1) {
        if (tid < s) {
            #pragma unroll
            for (int q = 0; q < 4; q++) rs[q][tid] += rs[q][tid+s];
            #pragma unroll
            for (int q = 0; q < 3; q++) {
                rx[q][tid] = fmaxf(rx[q][tid], rx[q][tid+s]);
                rn[q][tid] = fminf(rn[q][tid], rn[q][tid+s]);
            }
        }
        __syncthreads();
    }
    if (tid == 0) {
        float valid = fmaxf(rs[3][0], 1.f);
        d_center[bv*3+0] = rs[0][0]/valid;
        d_center[bv*3+1] = rs[1][0]/valid;
        d_center[bv*3+2] = rs[2][0]/valid;
        float diam = fmaxf(fmaxf(rx[0][0]-rn[0][0], rx[1][0]-rn[1][0]),
                           rx[2][0]-rn[2][0]);
        if (diam == 0.f) diam = 1.f;
        d_invdiam[bv] = 1.f/diam;
        d_denom[bv]   = 0.f;
    }
    d_gmax[bv*CP_ + tid] = -FLT_MAX;
}

// ---- kG1 (persistent): stage1 -> GEMM(W2 resident) -> reg-LN2 -> local+gmax
__global__ void __launch_bounds__(256) kG1(const float* __restrict__ xyz,
    const float* __restrict__ W1, const float* __restrict__ b1,
    const float* __restrict__ g1, const float* __restrict__ be1,
    const float* __restrict__ b2, const float* __restrict__ g2,
    const float* __restrict__ be2)
{
    extern __shared__ unsigned char ds[];
    __shared__ float w1s[3*CP_];
    __shared__ float b1s[CP_], g1s[CP_], e1s[CP_], b2s[CP_], g2s[CP_], e2s[CP_];
    __shared__ float srS[TM_][4], srQ[TM_][4];
    __shared__ float sMean[TM_], sRstd[TM_];
    __shared__ float scx[2][CP_];
    __shared__ float sCen[3*BV_], sInv[BV_], sSt[14];

    int tid = threadIdx.x, lane = tid & 31, wid = tid >> 5;
    uint32_t su = sm2u(ds);

    loadResidentB(su, d_W2f, tid); CPCOMMIT();

    for (int i = tid; i < 3*CP_; i += 256) w1s[i] = W1[i];
    b1s[tid]=b1[tid]; g1s[tid]=g1[tid]; e1s[tid]=be1[tid];
    b2s[tid]=b2[tid]; g2s[tid]=g2[tid]; e2s[tid]=be2[tid];
    if (tid < 3*BV_) sCen[tid] = d_center[tid];
    if (tid < BV_)   sInv[tid] = d_invdiam[tid];
    if (tid < 14)    sSt[tid]  = d_stat1[tid];
    CPWAIT0();
    __syncthreads();

    int p = tid >> 2, sub = tid & 3, c0 = sub*64;
    int mt0 = (wid >> 2) * 16;
    int nb  = (wid & 3) * 64;
    uint32_t aoff0 = (uint32_t)(mt0 + (lane&7) + ((lane>>3)&1)*8)*A_STR + (lane>>4)*16;
    uint32_t aoff1 = aoff0 + 32u*A_STR;
    uint32_t boff  = (uint32_t)(nb + (lane&7) + (lane>>4)*8)*A_STR + ((lane>>3)&1)*16;
    int r = lane >> 2, q2 = (lane & 3)*2;
    int rw0 = mt0 + r, rw1 = mt0 + r + 8, rw2 = mt0 + 32 + r, rw3 = mt0 + 40 + r;

    int it = 0;
    for (int tile = blockIdx.x; tile < NT2_; tile += GRIDP, it++) {
        int bv = tile >> 8;
        int b  = bv >> 2;
        uint32_t ab = su + (uint32_t)(it & 1)*A_IMG;

        // stage 1: analytic LN1 + single value pass into A buffer
        int n = (tile & 255) * TM_ + p;
        float idm = sInv[bv];
        float x0 = (xyz[(size_t)(b*3+0)*N_ + n] - sCen[bv*3+0]) * idm;
        float x1 = (xyz[(size_t)(b*3+1)*N_ + n] - sCen[bv*3+1]) * idm;
        float x2 = (xyz[(size_t)(b*3+2)*N_ + n] - sCen[bv*3+2]) * idm;
        float S  = sSt[0] + x0*sSt[2] + x1*sSt[3] + x2*sSt[4];
        float E2 = sSt[1] + 2.f*(x0*sSt[5] + x1*sSt[6] + x2*sSt[7])
                 + x0*x0*sSt[8]  + 2.f*x0*x1*sSt[9] + 2.f*x0*x2*sSt[10]
                 + x1*x1*sSt[11] + 2.f*x1*x2*sSt[12] + x2*x2*sSt[13];
        float mean = S * (1.f/CP_);
        float rstd = rsqrtf(E2*(1.f/CP_) - mean*mean + 1e-5f);
        #pragma unroll 8
        for (int i = 0; i < 32; i++) {
            int c = c0 + 2*i;
            float y0 = b1s[c]   + x0*w1s[c]   + x1*w1s[CP_+c]   + x2*w1s[2*CP_+c];
            float y1 = b1s[c+1] + x0*w1s[c+1] + x1*w1s[CP_+c+1] + x2*w1s[2*CP_+c+1];
            y0 = fmaxf((y0-mean)*rstd*g1s[c]   + e1s[c],   0.f);
            y1 = fmaxf((y1-mean)*rstd*g1s[c+1] + e1s[c+1], 0.f);
            *(uint32_t*)((unsigned char*)ds + ((size_t)(it&1)*A_IMG) + (size_t)p*A_STR + c*2) = pack2h(y0, y1);
        }
        __syncthreads();

        float dA[8][4] = {}, dB[8][4] = {};
        MAINLOOP_R(ab)

        // reg epilogue: LN2 stats
        float rs0=0.f,rq0=0.f,rs1=0.f,rq1=0.f,rs2=0.f,rq2=0.f,rs3=0.f,rq3=0.f;
        #pragma unroll
        for (int nt = 0; nt < 8; nt++) {
            int c = nb + nt*8 + q2;
            float bb0 = b2s[c], bb1 = b2s[c+1], v;
            v = dA[nt][0]+bb0; rs0+=v; rq0+=v*v;
            v = dA[nt][1]+bb1; rs0+=v; rq0+=v*v;
            v = dA[nt][2]+bb0; rs1+=v; rq1+=v*v;
            v = dA[nt][3]+bb1; rs1+=v; rq1+=v*v;
            v = dB[nt][0]+bb0; rs2+=v; rq2+=v*v;
            v = dB[nt][1]+bb1; rs2+=v; rq2+=v*v;
            v = dB[nt][2]+bb0; rs3+=v; rq3+=v*v;
            v = dB[nt][3]+bb1; rs3+=v; rq3+=v*v;
        }
        rs0 += __shfl_xor_sync(~0u, rs0, 1); rs0 += __shfl_xor_sync(~0u, rs0, 2);
        rq0 += __shfl_xor_sync(~0u, rq0, 1); rq0 += __shfl_xor_sync(~0u, rq0, 2);
        rs1 += __shfl_xor_sync(~0u, rs1, 1); rs1 += __shfl_xor_sync(~0u, rs1, 2);
        rq1 += __shfl_xor_sync(~0u, rq1, 1); rq1 += __shfl_xor_sync(~0u, rq1, 2);
        rs2 += __shfl_xor_sync(~0u, rs2, 1); rs2 += __shfl_xor_sync(~0u, rs2, 2);
        rq2 += __shfl_xor_sync(~0u, rq2, 1); rq2 += __shfl_xor_sync(~0u, rq2, 2);
        rs3 += __shfl_xor_sync(~0u, rs3, 1); rs3 += __shfl_xor_sync(~0u, rs3, 2);
        rq3 += __shfl_xor_sync(~0u, rq3, 1); rq3 += __shfl_xor_sync(~0u, rq3, 2);
        if ((lane & 3) == 0) {
            int w4 = wid & 3;
            srS[rw0][w4]=rs0; srQ[rw0][w4]=rq0;
            srS[rw1][w4]=rs1; srQ[rw1][w4]=rq1;
            srS[rw2][w4]=rs2; srQ[rw2][w4]=rq2;
            srS[rw3][w4]=rs3; srQ[rw3][w4]=rq3;
        }
        __syncthreads();
        if (tid < TM_) {
            float Ss = srS[tid][0]+srS[tid][1]+srS[tid][2]+srS[tid][3];
            float Qs = srQ[tid][0]+srQ[tid][1]+srQ[tid][2]+srQ[tid][3];
            float mn = Ss * (1.f/CP_);
            sMean[tid] = mn;
            sRstd[tid] = rsqrtf(Qs*(1.f/CP_) - mn*mn + 1e-5f);
        }
        __syncthreads();

        {
            float m0 = sMean[rw0], rr0 = sRstd[rw0];
            float m1 = sMean[rw1], rr1 = sRstd[rw1];
            float m2 = sMean[rw2], rr2 = sRstd[rw2];
            float m3 = sMean[rw3], rr3 = sRstd[rw3];
            unsigned char* lw = d_localA + (size_t)tile*A_IMG;
            float cm[16];
            #pragma unroll
            for (int nt = 0; nt < 8; nt++) {
                int c = nb + nt*8 + q2;
                float bb0=b2s[c], bb1=b2s[c+1], g0=g2s[c], g1=g2s[c+1], e0=e2s[c], e1=e2s[c+1];
                float v00 = (dA[nt][0]+bb0-m0)*rr0*g0+e0, v01 = (dA[nt][1]+bb1-m0)*rr0*g1+e1;
                float v10 = (dA[nt][2]+bb0-m1)*rr1*g0+e0, v11 = (dA[nt][3]+bb1-m1)*rr1*g1+e1;
                float v20 = (dB[nt][0]+bb0-m2)*rr2*g0+e0, v21 = (dB[nt][1]+bb1-m2)*rr2*g1+e1;
                float v30 = (dB[nt][2]+bb0-m3)*rr3*g0+e0, v31 = (dB[nt][3]+bb1-m3)*rr3*g1+e1;
                *(uint32_t*)(lw + (size_t)rw0*A_STR + c*2) = pack2h(v00, v01);
                *(uint32_t*)(lw + (size_t)rw1*A_STR + c*2) = pack2h(v10, v11);
                *(uint32_t*)(lw + (size_t)rw2*A_STR + c*2) = pack2h(v20, v21);
                *(uint32_t*)(lw + (size_t)rw3*A_STR + c*2) = pack2h(v30, v31);
                cm[2*nt]   = fmaxf(fmaxf(v00, v10), fmaxf(v20, v30));
                cm[2*nt+1] = fmaxf(fmaxf(v01, v11), fmaxf(v21, v31));
            }
            #pragma unroll
            for (int i = 0; i < 16; i++) {
                cm[i] = fmaxf(cm[i], __shfl_xor_sync(~0u, cm[i], 4));
                cm[i] = fmaxf(cm[i], __shfl_xor_sync(~0u, cm[i], 8));
                cm[i] = fmaxf(cm[i], __shfl_xor_sync(~0u, cm[i], 16));
            }
            if ((lane >> 2) == 0) {
                int grp = wid >> 2;
                #pragma unroll
                for (int nt = 0; nt < 8; nt++) {
                    int c = nb + nt*8 + q2;
                    scx[grp][c]   = cm[2*nt];
                    scx[grp][c+1] = cm[2*nt+1];
                }
            }
        }
        __syncthreads();
        atomicMaxFloat(&d_gmax[bv*CP_ + tid], fmaxf(scx[0][tid], scx[1][tid]));
    }
}

// ---- kG2 (persistent): local -> GEMM(W3top resident) -> z ------------------
__global__ void __launch_bounds__(256) kG2() {
    extern __shared__ unsigned char ds[];
    int tid = threadIdx.x, lane = tid & 31, wid = tid >> 5;
    uint32_t su = sm2u(ds);

    // group 0: resident W3 + A(tile0); group 1: A(tile1)
    loadResidentB(su, d_W3f, tid);
    {
        int t0 = blockIdx.x;
        if (t0 < NT2_) {
            const unsigned char* src = d_localA + (size_t)t0*A_IMG;
            for (int i = tid; i < A_IMG/16; i += 256)
                CPA16(su + (uint32_t)i*16, src + (size_t)i*16);
        }
    }
    CPCOMMIT();
    {
        int t1 = blockIdx.x + GRIDP;
        if (t1 < NT2_) {
            const unsigned char* src = d_localA + (size_t)t1*A_IMG;
            for (int i = tid; i < A_IMG/16; i += 256)
                CPA16(su + A_IMG + (uint32_t)i*16, src + (size_t)i*16);
        }
    }
    CPCOMMIT();

    int mt0 = (wid >> 2) * 16;
    int nb  = (wid & 3) * 64;
    uint32_t aoff0 = (uint32_t)(mt0 + (lane&7) + ((lane>>3)&1)*8)*A_STR + (lane>>4)*16;
    uint32_t aoff1 = aoff0 + 32u*A_STR;
    uint32_t boff  = (uint32_t)(nb + (lane&7) + (lane>>4)*8)*A_STR + ((lane>>3)&1)*16;
    int r = lane >> 2, q2 = (lane & 3)*2;
    int rw0 = mt0 + r, rw1 = mt0 + r + 8, rw2 = mt0 + 32 + r, rw3 = mt0 + 40 + r;

    int it = 0;
    for (int tile = blockIdx.x; tile < NT2_; tile += GRIDP, it++) {
        CPWAIT1();
        __syncthreads();
        uint32_t ab = su + (uint32_t)(it & 1)*A_IMG;

        float dA[8][4] = {}, dB[8][4] = {};
        MAINLOOP_R(ab)

        __syncthreads();   // all reads of ab done before refill
        {
            int nxt = tile + 2*GRIDP;
            if (nxt < NT2_) {
                const unsigned char* src = d_localA + (size_t)nxt*A_IMG;
                for (int i = tid; i < A_IMG/16; i += 256)
                    CPA16(ab - su + su + (uint32_t)i*16, src + (size_t)i*16);
            }
        }
        CPCOMMIT();

        // z epilogue: raw fp16 store (overlaps prefetch)
        uint32_t* zb = d_z + (size_t)tile*TM_*128;
        #pragma unroll
        for (int nt = 0; nt < 8; nt++) {
            int cw = (nb + nt*8 + q2) >> 1;
            zb[(size_t)rw0*128 + cw] = pack2h(dA[nt][0], dA[nt][1]);
            zb[(size_t)rw1*128 + cw] = pack2h(dA[nt][2], dA[nt][3]);
            zb[(size_t)rw2*128 + cw] = pack2h(dB[nt][0], dB[nt][1]);
            zb[(size_t)rw3*128 + cw] = pack2h(dB[nt][2], dB[nt][3]);
        }
    }
}

// ---------------- kC: gpart = global_xyz @ W3[256:512] + b3 -----------------
__global__ void __launch_bounds__(256) kC(const float* __restrict__ W3,
                                          const float* __restrict__ b3) {
    int bv = blockIdx.x;
    int c  = threadIdx.x;
    __shared__ float sg[CP_];
    __shared__ float ws[32*CP_];
    sg[c] = d_gmax[bv*CP_ + c];
    float acc = b3[c];
    for (int ko = 0; ko < 8; ko++) {
        __syncthreads();
        const float4* src = (const float4*)(W3 + (size_t)(256 + ko*32)*CP_);
        for (int i = c; i < 32*CP_/4; i += 256) ((float4*)ws)[i] = src[i];
        __syncthreads();
        #pragma unroll 8
        for (int kk = 0; kk < 32; kk++)
            acc += sg[ko*32+kk] * ws[kk*CP_ + c];
    }
    d_gpart[bv*CP_ + c] = acc;
}

// ---------------- kD: streaming LN3 + ReLU + W4 -> weights ------------------
__global__ void __launch_bounds__(256) kD(const float* __restrict__ masks,
    const float* __restrict__ g3, const float* __restrict__ be3,
    const float* __restrict__ W4)
{
    __shared__ float sGp[CP_], sG3[CP_], sE3[CP_], sW4[CP_];
    int blk = blockIdx.x;              // 1024 blocks: 32 per bv
    int bv = blk >> 5;
    int pbase = (blk & 31) * 512;
    int tid = threadIdx.x, lane = tid & 31, wid = tid >> 5;

    sGp[tid] = d_gpart[bv*CP_ + tid];
    sG3[tid] = g3[tid]; sE3[tid] = be3[tid]; sW4[tid] = W4[tid];
    __syncthreads();

    int cbase = lane*8;
    float gp[8], gg[8], ee[8], ww[8];
    #pragma unroll
    for (int j = 0; j < 8; j++) {
        gp[j]=sGp[cbase+j]; gg[j]=sG3[cbase+j]; ee[j]=sE3[cbase+j]; ww[j]=sW4[cbase+j];
    }

    float dacc = 0.f;
    for (int pp = wid; pp < 512; pp += 8) {
        int n = pbase + pp;
        size_t pt = (size_t)bv*N_ + n;
        uint4 w = *(const uint4*)(d_z + pt*128 + lane*4);
        uint32_t ws4[4] = {w.x, w.y, w.z, w.w};
        float v[8];
        #pragma unroll
        for (int j = 0; j < 4; j++) {
            __half2 h2 = *reinterpret_cast<__half2*>(&ws4[j]);
            float2 f = __half22float2(h2);
            v[2*j]   = f.x + gp[2*j];
            v[2*j+1] = f.y + gp[2*j+1];
        }
        float s = 0.f, q = 0.f;
        #pragma unroll
        for (int j = 0; j < 8; j++) { s += v[j]; q += v[j]*v[j]; }
        #pragma unroll
        for (int o = 16; o > 0; o >>= 1) {
            s += __shfl_xor_sync(~0u, s, o);
            q += __shfl_xor_sync(~0u, q, o);
        }
        float mean = s * (1.f/CP_);
        float rstd = rsqrtf(q*(1.f/CP_) - mean*mean + 1e-5f);
        float dot = 0.f;
        #pragma unroll
        for (int j = 0; j < 8; j++)
            dot += fmaxf((v[j]-mean)*rstd*gg[j] + ee[j], 0.f) * ww[j];
        #pragma unroll
        for (int o = 16; o > 0; o >>= 1) dot += __shfl_xor_sync(~0u, dot, o);
        if (lane == 0) {
            float m = masks[pt];
            float wgt = 2.f * m / (1.f + expf(-dot));
            d_mw[pt] = wgt;
            dacc += wgt;
        }
    }
    if (lane == 0) atomicAdd(&d_denom[bv], dacc);
}

// ---------------- kE: weighted pooling + epilogue ---------------------------
__global__ void __launch_bounds__(256) kE(const float* __restrict__ feats,
                                          float* __restrict__ out) {
    int blk = blockIdx.x;        // b*CP_ + c
    int b = blk >> 8;
    int c = blk & 255;
    int tid = threadIdx.x;

    const float* f   = feats + (size_t)(b*CP_ + c)*N_;
    const float* mw0 = d_mw + (size_t)(b*4+0)*N_;
    const float* mw1 = d_mw + (size_t)(b*4+1)*N_;
    const float* mw2 = d_mw + (size_t)(b*4+2)*N_;
    const float* mw3 = d_mw + (size_t)(b*4+3)*N_;

    float a0=0.f, a1=0.f, a2=0.f, a3=0.f;
    for (int n = tid; n < N_; n += 256) {
        float fv = f[n];
        a0 += fv*mw0[n]; a1 += fv*mw1[n]; a2 += fv*mw2[n]; a3 += fv*mw3[n];
    }
    #pragma unroll
    for (int o = 16; o > 0; o >>= 1) {
        a0 += __shfl_xor_sync(0xffffffffu, a0, o);
        a1 += __shfl_xor_sync(0xffffffffu, a1, o);
        a2 += __shfl_xor_sync(0xffffffffu, a2, o);
        a3 += __shfl_xor_sync(0xffffffffu, a3, o);
    }
    __shared__ float sr[4][8];
    int lane = tid & 31, warp = tid >> 5;
    if (lane == 0) { sr[0][warp]=a0; sr[1][warp]=a1; sr[2][warp]=a2; sr[3][warp]=a3; }
    __syncthreads();
    if (tid < 4) {
        float ps = 0.f;
        #pragma unroll
        for (int w = 0; w < 8; w++) ps += sr[tid][w];
        int bvv = b*4 + tid;
        float den = fmaxf(d_denom[bvv], 1e-8f);
        out[(size_t)bvv*CP_ + c] = ps/den + d_gmax[bvv*CP_ + c];
    }
}

// ---------------- launch ----------------------------------------------------
extern "C" void kernel_launch(void* const* d_in, const int* in_sizes, int n_in,
                              void* d_out, int out_size) {
    const float* xyz = (const float*)d_in[0];
    const float* pf  = (const float*)d_in[1];
    const float* pm  = (const float*)d_in[2];
    const float* W1  = (const float*)d_in[3];
    const float* b1  = (const float*)d_in[4];
    const float* g1  = (const float*)d_in[5];
    const float* be1 = (const float*)d_in[6];
    const float* W2  = (const float*)d_in[7];
    const float* b2  = (const float*)d_in[8];
    const float* g2  = (const float*)d_in[9];
    const float* be2 = (const float*)d_in[10];
    const float* W3  = (const float*)d_in[11];
    const float* b3  = (const float*)d_in[12];
    const float* g3  = (const float*)d_in[13];
    const float* be3 = (const float*)d_in[14];
    const float* W4  = (const float*)d_in[15];
    float* out = (float*)d_out;

    static int configured = 0;
    if (!configured) {
        cudaFuncSetAttribute(kG1, cudaFuncAttributeMaxDynamicSharedMemorySize, DYN_SMEM);
        cudaFuncSetAttribute(kG2, cudaFuncAttributeMaxDynamicSharedMemorySize, DYN_SMEM);
        configured = 1;
    }

    kP<<<CP_, 256>>>(W2, W3);
    kS<<<1, 256>>>(W1, b1);
    kA<<<BV_, 256>>>(xyz, pm);
    kG1<<<GRIDP, 256, DYN_SMEM>>>(xyz, W1, b1, g1, be1, b2, g2, be2);
    kC<<<BV_, 256>>>(W3, b3);
    kG2<<<GRIDP, 256, DYN_SMEM>>>();
    kD<<<1024, 256>>>(pm, g3, be3, W4);
    kE<<<B_*CP_, 256>>>(pf, out);
}

// round 12
// speedup vs baseline: 4.5369x; 1.3582x over previous
#include <cuda_runtime.h>
#include <cuda_fp16.h>
#include <math.h>
#include <float.h>
#include <stdint.h>

#define B_   8
#define V_   4
#define N_   16384
#define CP_  256
#define BV_  (B_*V_)            // 32
#define TM_  128                // points per tile
#define NT_  (N_*BV_/TM_)       // 4096 tiles
#define GRIDP 148               // persistent grid
#define A_STR 528               // padded row stride bytes (256 fp16 + 16 pad)
#define A_IMG    67584          // 128*528
#define OFF_RB   67584          // resident B after single A buffer
#define RB_BYTES 135168         // 256*528
#define DYN_SMEM (OFF_RB + RB_BYTES)   // 202752

// ---------------- device scratch (static; no allocations) -------------------
__device__ float d_center[BV_*3];
__device__ float d_invdiam[BV_];
__device__ float d_stat1[14];
__device__ __align__(16) float d_gmax[BV_*CP_];
__device__ __align__(16) float d_gpart[BV_*CP_];
__device__ float d_mw[BV_*N_];
__device__ float d_denom[BV_];
__device__ __align__(16) unsigned char d_localA[(size_t)NT_*A_IMG];   // 277MB
__device__ __align__(16) uint32_t d_z[(size_t)BV_*N_*128];            // 268MB
__device__ __align__(16) unsigned char d_W2f[CP_*CP_*2];  // fp16 [n][k]
__device__ __align__(16) unsigned char d_W3f[CP_*CP_*2];

// ---------------- helpers ---------------------------------------------------
__device__ __forceinline__ uint32_t sm2u(const void* p) {
    uint32_t a;
    asm("{ .reg .u64 t; cvta.to.shared.u64 t, %1; cvt.u32.u64 %0, t; }"
        : "=r"(a) : "l"(p));
    return a;
}
#define LDSM4(r, addr) \
    asm volatile("ldmatrix.sync.aligned.m8n8.x4.shared.b16 {%0,%1,%2,%3}, [%4];" \
        : "=r"((r)[0]), "=r"((r)[1]), "=r"((r)[2]), "=r"((r)[3]) : "r"(addr))
#define MMAOP(d, a, b0, b1) \
    asm volatile("mma.sync.aligned.m16n8k16.row.col.f32.f16.f16.f32 " \
        "{%0,%1,%2,%3}, {%4,%5,%6,%7}, {%8,%9}, {%0,%1,%2,%3};" \
        : "+f"((d)[0]), "+f"((d)[1]), "+f"((d)[2]), "+f"((d)[3]) \
        : "r"((a)[0]), "r"((a)[1]), "r"((a)[2]), "r"((a)[3]), "r"(b0), "r"(b1))
#define CPA16(dst, src) \
    asm volatile("cp.async.cg.shared.global [%0], [%1], 16;" :: "r"(dst), "l"(src))
#define CPCOMMIT() asm volatile("cp.async.commit_group;" ::: "memory")
#define CPWAIT0()  asm volatile("cp.async.wait_group 0;" ::: "memory")

static __device__ __forceinline__ uint32_t pack2h(float v0, float v1) {
    __half h0 = __float2half_rn(v0);
    __half h1 = __float2half_rn(v1);
    return (uint32_t)__half_as_ushort(h0) | ((uint32_t)__half_as_ushort(h1) << 16);
}
__device__ __forceinline__ void atomicMaxFloat(float* addr, float val) {
    if (__float_as_int(val) >= 0) atomicMax((int*)addr, __float_as_int(val));
    else atomicMin((unsigned int*)addr, __float_as_uint(val));
}

// copy 128KB weight matrix into resident padded smem rows
__device__ __forceinline__ void loadResidentB(uint32_t su, const unsigned char* g, int tid) {
    for (int i = tid; i < 8192; i += 256) {
        int row = i >> 5, q = i & 31;
        CPA16(su + OFF_RB + (uint32_t)row*A_STR + q*16, g + (size_t)i*16);
    }
}

// K=256 mainloop, M=128: 4 m-strips per warp, B resident, zero syncs
#define MAINLOOP_R(ab) \
    _Pragma("unroll 1") \
    for (int ch = 0; ch < 8; ch++) { \
        _Pragma("unroll") \
        for (int kb = 0; kb < 2; kb++) { \
            uint32_t kA = (uint32_t)(ch*64 + kb*32); \
            uint32_t a0[4], a1[4], a2[4], a3[4]; \
            LDSM4(a0, (ab) + aoff0 + kA); \
            LDSM4(a1, (ab) + aoff0 + 16896u + kA); \
            LDSM4(a2, (ab) + aoff0 + 33792u + kA); \
            LDSM4(a3, (ab) + aoff0 + 50688u + kA); \
            _Pragma("unroll") \
            for (int nt = 0; nt < 4; nt++) { \
                uint32_t bh[4]; \
                LDSM4(bh, su + OFF_RB + boff + (uint32_t)(nt*16*A_STR) + kA); \
                MMAOP(dS[0][2*nt],   a0, bh[0], bh[1]); \
                MMAOP(dS[0][2*nt+1], a0, bh[2], bh[3]); \
                MMAOP(dS[1][2*nt],   a1, bh[0], bh[1]); \
                MMAOP(dS[1][2*nt+1], a1, bh[2], bh[3]); \
                MMAOP(dS[2][2*nt],   a2, bh[0], bh[1]); \
                MMAOP(dS[2][2*nt+1], a2, bh[2], bh[3]); \
                MMAOP(dS[3][2*nt],   a3, bh[0], bh[1]); \
                MMAOP(dS[3][2*nt+1], a3, bh[2], bh[3]); \
            } \
        } \
    }

// ---------------- kP: weights -> fp16 [n][k] --------------------------------
__global__ void __launch_bounds__(256) kP(const float* __restrict__ W2,
                                          const float* __restrict__ W3) {
    int k = blockIdx.x;
    int n = threadIdx.x;
    size_t pos = ((size_t)n*CP_ + k)*2;
    *(unsigned short*)(d_W2f + pos) = __half_as_ushort(__float2half_rn(W2[k*CP_ + n]));
    *(unsigned short*)(d_W3f + pos) = __half_as_ushort(__float2half_rn(W3[k*CP_ + n]));
}

// ---------------- kS: analytic LN1 stats aggregates -------------------------
__global__ void __launch_bounds__(256) kS(const float* __restrict__ W1,
                                          const float* __restrict__ b1) {
    __shared__ float sm[14][256];
    int c = threadIdx.x;
    float b = b1[c], w0 = W1[c], w1 = W1[CP_+c], w2 = W1[2*CP_+c];
    sm[0][c]=b;      sm[1][c]=b*b;
    sm[2][c]=w0;     sm[3][c]=w1;     sm[4][c]=w2;
    sm[5][c]=b*w0;   sm[6][c]=b*w1;   sm[7][c]=b*w2;
    sm[8][c]=w0*w0;  sm[9][c]=w0*w1;  sm[10][c]=w0*w2;
    sm[11][c]=w1*w1; sm[12][c]=w1*w2; sm[13][c]=w2*w2;
    __syncthreads();
    for (int s = 128; s > 0; s >>= 1) {
        if (c < s) {
            #pragma unroll
            for (int q = 0; q < 14; q++) sm[q][c] += sm[q][c+s];
        }
        __syncthreads();
    }
    if (c < 14) d_stat1[c] = sm[c][0];
}

// ---------------- kA: per-(b,v) stats + init --------------------------------
__global__ void __launch_bounds__(256) kA(const float* __restrict__ xyz,
                                          const float* __restrict__ masks) {
    int bv = blockIdx.x;
    int b  = bv >> 2;
    int tid = threadIdx.x;

    float s0=0.f, s1=0.f, s2=0.f, cnt=0.f;
    float mx0=-FLT_MAX, mx1=-FLT_MAX, mx2=-FLT_MAX;
    float mn0= FLT_MAX, mn1= FLT_MAX, mn2= FLT_MAX;

    const float* mrow = masks + (size_t)bv*N_;
    const float* x0r  = xyz + (size_t)(b*3+0)*N_;
    const float* x1r  = xyz + (size_t)(b*3+1)*N_;
    const float* x2r  = xyz + (size_t)(b*3+2)*N_;

    for (int n = tid; n < N_; n += 256) {
        float m = mrow[n];
        float a = x0r[n]*m, c = x1r[n]*m, e = x2r[n]*m;
        s0 += a; s1 += c; s2 += e; cnt += m;
        mx0 = fmaxf(mx0,a); mx1 = fmaxf(mx1,c); mx2 = fmaxf(mx2,e);
        mn0 = fminf(mn0,a); mn1 = fminf(mn1,c); mn2 = fminf(mn2,e);
    }
    __shared__ float rs[4][256];
    __shared__ float rx[3][256];
    __shared__ float rn[3][256];
    rs[0][tid]=s0; rs[1][tid]=s1; rs[2][tid]=s2; rs[3][tid]=cnt;
    rx[0][tid]=mx0; rx[1][tid]=mx1; rx[2][tid]=mx2;
    rn[0][tid]=mn0; rn[1][tid]=mn1; rn[2][tid]=mn2;
    __syncthreads();
    for (int s = 128; s > 0; s >>= 1) {
        if (tid < s) {
            #pragma unroll
            for (int q = 0; q < 4; q++) rs[q][tid] += rs[q][tid+s];
            #pragma unroll
            for (int q = 0; q < 3; q++) {
                rx[q][tid] = fmaxf(rx[q][tid], rx[q][tid+s]);
                rn[q][tid] = fminf(rn[q][tid], rn[q][tid+s]);
            }
        }
        __syncthreads();
    }
    if (tid == 0) {
        float valid = fmaxf(rs[3][0], 1.f);
        d_center[bv*3+0] = rs[0][0]/valid;
        d_center[bv*3+1] = rs[1][0]/valid;
        d_center[bv*3+2] = rs[2][0]/valid;
        float diam = fmaxf(fmaxf(rx[0][0]-rn[0][0], rx[1][0]-rn[1][0]),
                           rx[2][0]-rn[2][0]);
        if (diam == 0.f) diam = 1.f;
        d_invdiam[bv] = 1.f/diam;
        d_denom[bv]   = 0.f;
    }
    d_gmax[bv*CP_ + tid] = -FLT_MAX;
}

// ---- kG1 (persistent, M=128): stage1 -> GEMM(W2) -> reg-LN2 -> local+gmax --
__global__ void __launch_bounds__(256) kG1(const float* __restrict__ xyz,
    const float* __restrict__ W1, const float* __restrict__ b1,
    const float* __restrict__ g1, const float* __restrict__ be1,
    const float* __restrict__ b2, const float* __restrict__ g2,
    const float* __restrict__ be2)
{
    extern __shared__ unsigned char ds[];
    __shared__ float w1s[3*CP_];
    __shared__ float b1s[CP_], g1s[CP_], e1s[CP_], b2s[CP_], g2s[CP_], e2s[CP_];
    __shared__ float srS[TM_][4], srQ[TM_][4];
    __shared__ float sMean[TM_], sRstd[TM_];
    __shared__ float scx[2][CP_];
    __shared__ float sCen[3*BV_], sInv[BV_], sSt[14];

    int tid = threadIdx.x, lane = tid & 31, wid = tid >> 5;
    uint32_t su = sm2u(ds);

    loadResidentB(su, d_W2f, tid); CPCOMMIT();

    for (int i = tid; i < 3*CP_; i += 256) w1s[i] = W1[i];
    b1s[tid]=b1[tid]; g1s[tid]=g1[tid]; e1s[tid]=be1[tid];
    b2s[tid]=b2[tid]; g2s[tid]=g2[tid]; e2s[tid]=be2[tid];
    if (tid < 3*BV_) sCen[tid] = d_center[tid];
    if (tid < BV_)   sInv[tid] = d_invdiam[tid];
    if (tid < 14)    sSt[tid]  = d_stat1[tid];
    CPWAIT0();
    __syncthreads();

    int p = tid >> 1, half = tid & 1, c0 = half*128;
    int mt0 = (wid >> 2) * 16;
    int nb  = (wid & 3) * 64;
    uint32_t aoff0 = (uint32_t)(mt0 + (lane&7) + ((lane>>3)&1)*8)*A_STR + (lane>>4)*16;
    uint32_t boff  = (uint32_t)(nb + (lane&7) + (lane>>4)*8)*A_STR + ((lane>>3)&1)*16;
    int r = lane >> 2, q2 = (lane & 3)*2;

    for (int tile = blockIdx.x; tile < NT_; tile += GRIDP) {
        int bv = tile >> 7;
        int b  = bv >> 2;

        // stage 1: analytic LN1, single value pass into A smem
        int n = (tile & 127) * TM_ + p;
        float idm = sInv[bv];
        float x0 = (xyz[(size_t)(b*3+0)*N_ + n] - sCen[bv*3+0]) * idm;
        float x1 = (xyz[(size_t)(b*3+1)*N_ + n] - sCen[bv*3+1]) * idm;
        float x2 = (xyz[(size_t)(b*3+2)*N_ + n] - sCen[bv*3+2]) * idm;
        float S  = sSt[0] + x0*sSt[2] + x1*sSt[3] + x2*sSt[4];
        float E2 = sSt[1] + 2.f*(x0*sSt[5] + x1*sSt[6] + x2*sSt[7])
                 + x0*x0*sSt[8]  + 2.f*x0*x1*sSt[9] + 2.f*x0*x2*sSt[10]
                 + x1*x1*sSt[11] + 2.f*x1*x2*sSt[12] + x2*x2*sSt[13];
        float mean = S * (1.f/CP_);
        float rstd = rsqrtf(E2*(1.f/CP_) - mean*mean + 1e-5f);
        #pragma unroll 8
        for (int i = 0; i < 64; i++) {
            int c = c0 + 2*i;
            float y0 = b1s[c]   + x0*w1s[c]   + x1*w1s[CP_+c]   + x2*w1s[2*CP_+c];
            float y1 = b1s[c+1] + x0*w1s[c+1] + x1*w1s[CP_+c+1] + x2*w1s[2*CP_+c+1];
            y0 = fmaxf((y0-mean)*rstd*g1s[c]   + e1s[c],   0.f);
            y1 = fmaxf((y1-mean)*rstd*g1s[c+1] + e1s[c+1], 0.f);
            *(uint32_t*)(ds + (size_t)p*A_STR + c*2) = pack2h(y0, y1);
        }
        __syncthreads();

        float dS[4][8][4] = {};
        MAINLOOP_R(su)

        // reg epilogue: LN2 stats
        float rsm[4][2] = {}, rqm[4][2] = {};
        #pragma unroll
        for (int s = 0; s < 4; s++) {
            #pragma unroll
            for (int f = 0; f < 8; f++) {
                int c = nb + f*8 + q2;
                float bb0 = b2s[c], bb1 = b2s[c+1], v;
                v = dS[s][f][0]+bb0; rsm[s][0]+=v; rqm[s][0]+=v*v;
                v = dS[s][f][1]+bb1; rsm[s][0]+=v; rqm[s][0]+=v*v;
                v = dS[s][f][2]+bb0; rsm[s][1]+=v; rqm[s][1]+=v*v;
                v = dS[s][f][3]+bb1; rsm[s][1]+=v; rqm[s][1]+=v*v;
            }
        }
        #pragma unroll
        for (int s = 0; s < 4; s++) {
            #pragma unroll
            for (int h = 0; h < 2; h++) {
                rsm[s][h] += __shfl_xor_sync(~0u, rsm[s][h], 1);
                rsm[s][h] += __shfl_xor_sync(~0u, rsm[s][h], 2);
                rqm[s][h] += __shfl_xor_sync(~0u, rqm[s][h], 1);
                rqm[s][h] += __shfl_xor_sync(~0u, rqm[s][h], 2);
            }
        }
        if ((lane & 3) == 0) {
            int w4 = wid & 3;
            #pragma unroll
            for (int s = 0; s < 4; s++) {
                #pragma unroll
                for (int h = 0; h < 2; h++) {
                    int row = mt0 + s*32 + h*8 + r;
                    srS[row][w4] = rsm[s][h];
                    srQ[row][w4] = rqm[s][h];
                }
            }
        }
        __syncthreads();
        if (tid < TM_) {
            float Ss = srS[tid][0]+srS[tid][1]+srS[tid][2]+srS[tid][3];
            float Qs = srQ[tid][0]+srQ[tid][1]+srQ[tid][2]+srQ[tid][3];
            float mn = Ss * (1.f/CP_);
            sMean[tid] = mn;
            sRstd[tid] = rsqrtf(Qs*(1.f/CP_) - mn*mn + 1e-5f);
        }
        __syncthreads();

        {
            unsigned char* lw = d_localA + (size_t)tile*A_IMG;
            float cm[16];
            #pragma unroll
            for (int i = 0; i < 16; i++) cm[i] = -FLT_MAX;
            #pragma unroll
            for (int s = 0; s < 4; s++) {
                int row0 = mt0 + s*32 + r, row1 = row0 + 8;
                float m0 = sMean[row0], rr0 = sRstd[row0];
                float m1 = sMean[row1], rr1 = sRstd[row1];
                #pragma unroll
                for (int f = 0; f < 8; f++) {
                    int c = nb + f*8 + q2;
                    float bb0=b2s[c], bb1=b2s[c+1], g0=g2s[c], g1=g2s[c+1];
                    float e0=e2s[c], e1=e2s[c+1];
                    float v00 = (dS[s][f][0]+bb0-m0)*rr0*g0+e0;
                    float v01 = (dS[s][f][1]+bb1-m0)*rr0*g1+e1;
                    float v10 = (dS[s][f][2]+bb0-m1)*rr1*g0+e0;
                    float v11 = (dS[s][f][3]+bb1-m1)*rr1*g1+e1;
                    *(uint32_t*)(lw + (size_t)row0*A_STR + c*2) = pack2h(v00, v01);
                    *(uint32_t*)(lw + (size_t)row1*A_STR + c*2) = pack2h(v10, v11);
                    cm[2*f]   = fmaxf(cm[2*f],   fmaxf(v00, v10));
                    cm[2*f+1] = fmaxf(cm[2*f+1], fmaxf(v01, v11));
                }
            }
            #pragma unroll
            for (int i = 0; i < 16; i++) {
                cm[i] = fmaxf(cm[i], __shfl_xor_sync(~0u, cm[i], 4));
                cm[i] = fmaxf(cm[i], __shfl_xor_sync(~0u, cm[i], 8));
                cm[i] = fmaxf(cm[i], __shfl_xor_sync(~0u, cm[i], 16));
            }
            if ((lane >> 2) == 0) {
                int grp = wid >> 2;
                #pragma unroll
                for (int f = 0; f < 8; f++) {
                    int c = nb + f*8 + q2;
                    scx[grp][c]   = cm[2*f];
                    scx[grp][c+1] = cm[2*f+1];
                }
            }
        }
        __syncthreads();
        atomicMaxFloat(&d_gmax[bv*CP_ + tid], fmaxf(scx[0][tid], scx[1][tid]));
        __syncthreads();   // A smem free for next tile's stage-1
    }
}

// ---- kG2 (persistent, M=128): local -> GEMM(W3top) -> z --------------------
__global__ void __launch_bounds__(256) kG2() {
    extern __shared__ unsigned char ds[];
    int tid = threadIdx.x, lane = tid & 31, wid = tid >> 5;
    uint32_t su = sm2u(ds);

    loadResidentB(su, d_W3f, tid); CPCOMMIT();
    CPWAIT0();
    __syncthreads();

    int mt0 = (wid >> 2) * 16;
    int nb  = (wid & 3) * 64;
    uint32_t aoff0 = (uint32_t)(mt0 + (lane&7) + ((lane>>3)&1)*8)*A_STR + (lane>>4)*16;
    uint32_t boff  = (uint32_t)(nb + (lane&7) + (lane>>4)*8)*A_STR + ((lane>>3)&1)*16;
    int r = lane >> 2, q2 = (lane & 3)*2;

    for (int tile = blockIdx.x; tile < NT_; tile += GRIDP) {
        // load A tile (67.5KB)
        {
            const unsigned char* src = d_localA + (size_t)tile*A_IMG;
            for (int i = tid; i < A_IMG/16; i += 256)
                CPA16(su + (uint32_t)i*16, src + (size_t)i*16);
        }
        CPCOMMIT();
        CPWAIT0();
        __syncthreads();

        float dS[4][8][4] = {};
        MAINLOOP_R(su)
        __syncthreads();   // all reads done before next iteration's cp.async

        uint32_t* zb = d_z + (size_t)tile*TM_*128;
        #pragma unroll
        for (int s = 0; s < 4; s++) {
            int row0 = mt0 + s*32 + r, row1 = row0 + 8;
            #pragma unroll
            for (int f = 0; f < 8; f++) {
                int cw = (nb + f*8 + q2) >> 1;
                zb[(size_t)row0*128 + cw] = pack2h(dS[s][f][0], dS[s][f][1]);
                zb[(size_t)row1*128 + cw] = pack2h(dS[s][f][2], dS[s][f][3]);
            }
        }
    }
}

// ---------------- kC: gpart = global_xyz @ W3[256:512] + b3 -----------------
__global__ void __launch_bounds__(256) kC(const float* __restrict__ W3,
                                          const float* __restrict__ b3) {
    int bv = blockIdx.x;
    int c  = threadIdx.x;
    __shared__ float sg[CP_];
    __shared__ float ws[32*CP_];
    sg[c] = d_gmax[bv*CP_ + c];
    float acc = b3[c];
    for (int ko = 0; ko < 8; ko++) {
        __syncthreads();
        const float4* src = (const float4*)(W3 + (size_t)(256 + ko*32)*CP_);
        for (int i = c; i < 32*CP_/4; i += 256) ((float4*)ws)[i] = src[i];
        __syncthreads();
        #pragma unroll 8
        for (int kk = 0; kk < 32; kk++)
            acc += sg[ko*32+kk] * ws[kk*CP_ + c];
    }
    d_gpart[bv*CP_ + c] = acc;
}

// ---------------- kD: streaming LN3 + ReLU + W4 -> weights ------------------
__global__ void __launch_bounds__(256) kD(const float* __restrict__ masks,
    const float* __restrict__ g3, const float* __restrict__ be3,
    const float* __restrict__ W4)
{
    __shared__ float sGp[CP_], sG3[CP_], sE3[CP_], sW4[CP_];
    int blk = blockIdx.x;              // 1024 blocks: 32 per bv
    int bv = blk >> 5;
    int pbase = (blk & 31) * 512;
    int tid = threadIdx.x, lane = tid & 31, wid = tid >> 5;

    sGp[tid] = d_gpart[bv*CP_ + tid];
    sG3[tid] = g3[tid]; sE3[tid] = be3[tid]; sW4[tid] = W4[tid];
    __syncthreads();

    int cbase = lane*8;
    float gp[8], gg[8], ee[8], ww[8];
    #pragma unroll
    for (int j = 0; j < 8; j++) {
        gp[j]=sGp[cbase+j]; gg[j]=sG3[cbase+j]; ee[j]=sE3[cbase+j]; ww[j]=sW4[cbase+j];
    }

    float dacc = 0.f;
    for (int pp = wid; pp < 512; pp += 8) {
        int n = pbase + pp;
        size_t pt = (size_t)bv*N_ + n;
        uint4 w = *(const uint4*)(d_z + pt*128 + lane*4);
        uint32_t ws4[4] = {w.x, w.y, w.z, w.w};
        float v[8];
        #pragma unroll
        for (int j = 0; j < 4; j++) {
            __half2 h2 = *reinterpret_cast<__half2*>(&ws4[j]);
            float2 f = __half22float2(h2);
            v[2*j]   = f.x + gp[2*j];
            v[2*j+1] = f.y + gp[2*j+1];
        }
        float s = 0.f, q = 0.f;
        #pragma unroll
        for (int j = 0; j < 8; j++) { s += v[j]; q += v[j]*v[j]; }
        #pragma unroll
        for (int o = 16; o > 0; o >>= 1) {
            s += __shfl_xor_sync(~0u, s, o);
            q += __shfl_xor_sync(~0u, q, o);
        }
        float mean = s * (1.f/CP_);
        float rstd = rsqrtf(q*(1.f/CP_) - mean*mean + 1e-5f);
        float dot = 0.f;
        #pragma unroll
        for (int j = 0; j < 8; j++)
            dot += fmaxf((v[j]-mean)*rstd*gg[j] + ee[j], 0.f) * ww[j];
        #pragma unroll
        for (int o = 16; o > 0; o >>= 1) dot += __shfl_xor_sync(~0u, dot, o);
        if (lane == 0) {
            float m = masks[pt];
            float wgt = 2.f * m / (1.f + expf(-dot));
            d_mw[pt] = wgt;
            dacc += wgt;
        }
    }
    if (lane == 0) atomicAdd(&d_denom[bv], dacc);
}

// ---------------- kE: weighted pooling + epilogue ---------------------------
__global__ void __launch_bounds__(256) kE(const float* __restrict__ feats,
                                          float* __restrict__ out) {
    int blk = blockIdx.x;        // b*CP_ + c
    int b = blk >> 8;
    int c = blk & 255;
    int tid = threadIdx.x;

    const float* f   = feats + (size_t)(b*CP_ + c)*N_;
    const float* mw0 = d_mw + (size_t)(b*4+0)*N_;
    const float* mw1 = d_mw + (size_t)(b*4+1)*N_;
    const float* mw2 = d_mw + (size_t)(b*4+2)*N_;
    const float* mw3 = d_mw + (size_t)(b*4+3)*N_;

    float a0=0.f, a1=0.f, a2=0.f, a3=0.f;
    for (int n = tid; n < N_; n += 256) {
        float fv = f[n];
        a0 += fv*mw0[n]; a1 += fv*mw1[n]; a2 += fv*mw2[n]; a3 += fv*mw3[n];
    }
    #pragma unroll
    for (int o = 16; o > 0; o >>= 1) {
        a0 += __shfl_xor_sync(0xffffffffu, a0, o);
        a1 += __shfl_xor_sync(0xffffffffu, a1, o);
        a2 += __shfl_xor_sync(0xffffffffu, a2, o);
        a3 += __shfl_xor_sync(0xffffffffu, a3, o);
    }
    __shared__ float sr[4][8];
    int lane = tid & 31, warp = tid >> 5;
    if (lane == 0) { sr[0][warp]=a0; sr[1][warp]=a1; sr[2][warp]=a2; sr[3][warp]=a3; }
    __syncthreads();
    if (tid < 4) {
        float ps = 0.f;
        #pragma unroll
        for (int w = 0; w < 8; w++) ps += sr[tid][w];
        int bvv = b*4 + tid;
        float den = fmaxf(d_denom[bvv], 1e-8f);
        out[(size_t)bvv*CP_ + c] = ps/den + d_gmax[bvv*CP_ + c];
    }
}

// ---------------- launch ----------------------------------------------------
extern "C" void kernel_launch(void* const* d_in, const int* in_sizes, int n_in,
                              void* d_out, int out_size) {
    const float* xyz = (const float*)d_in[0];
    const float* pf  = (const float*)d_in[1];
    const float* pm  = (const float*)d_in[2];
    const float* W1  = (const float*)d_in[3];
    const float* b1  = (const float*)d_in[4];
    const float* g1  = (const float*)d_in[5];
    const float* be1 = (const float*)d_in[6];
    const float* W2  = (const float*)d_in[7];
    const float* b2  = (const float*)d_in[8];
    const float* g2  = (const float*)d_in[9];
    const float* be2 = (const float*)d_in[10];
    const float* W3  = (const float*)d_in[11];
    const float* b3  = (const float*)d_in[12];
    const float* g3  = (const float*)d_in[13];
    const float* be3 = (const float*)d_in[14];
    const float* W4  = (const float*)d_in[15];
    float* out = (float*)d_out;

    static int configured = 0;
    if (!configured) {
        cudaFuncSetAttribute(kG1, cudaFuncAttributeMaxDynamicSharedMemorySize, DYN_SMEM);
        cudaFuncSetAttribute(kG2, cudaFuncAttributeMaxDynamicSharedMemorySize, DYN_SMEM);
        configured = 1;
    }

    kP<<<CP_, 256>>>(W2, W3);
    kS<<<1, 256>>>(W1, b1);
    kA<<<BV_, 256>>>(xyz, pm);
    kG1<<<GRIDP, 256, DYN_SMEM>>>(xyz, W1, b1, g1, be1, b2, g2, be2);
    kC<<<BV_, 256>>>(W3, b3);
    kG2<<<GRIDP, 256, DYN_SMEM>>>();
    kD<<<1024, 256>>>(pm, g3, be3, W4);
    kE<<<B_*CP_, 256>>>(pf, out);
}